// round 1
// baseline (speedup 1.0000x reference)
#include <cuda_runtime.h>
#include <math.h>

#define NA 20000
#define NP 800000
#define NSP 119
#define NRAD 5
#define NB 7
#define NFEAT 360
#define U1 512
#define U2 512
#define RMAXV 6.0f
#define PI_F 3.14159265358979323846f

typedef unsigned long long u64;

// Scratch (static device globals — no runtime allocation).
__device__ float g_M[100 * NA];        // unique symmetric moments, comp-major [c][atom]
__device__ float g_featsT[NFEAT * NA]; // features transposed [feat][atom]
__device__ float g_h1T[U1 * NA];       // hidden1 transposed [n][atom]
__device__ float g_h2[(size_t)NA * U2];// hidden2 row-major [atom][n]

// ---------------------------------------------------------------------------
// packed fp32x2 helpers (Blackwell full-rate fp32 path)
// ---------------------------------------------------------------------------
__device__ __forceinline__ void fma2(u64& d, u64 a, u64 b) {
    asm("fma.rn.f32x2 %0, %1, %2, %0;" : "+l"(d) : "l"(a), "l"(b));
}
__device__ __forceinline__ u64 pack2(float x, float y) {
    u64 r; asm("mov.b64 %0, {%1, %2};" : "=l"(r) : "f"(x), "f"(y)); return r;
}
__device__ __forceinline__ void unpack2(float& x, float& y, u64 v) {
    asm("mov.b64 {%0, %1}, %2;" : "=f"(x), "=f"(y) : "l"(v));
}

// symmetric index maps (fold at compile time under full unroll)
__device__ __forceinline__ int imap2(int a, int b) {
    int i = a < b ? a : b, j = a < b ? b : a;
    return (i == 0) ? j : ((i == 1) ? (2 + j) : 5);
}
__device__ __forceinline__ int imap3(int a, int b, int c) {
    int i = a, j = b, k = c, t;
    if (i > j) { t = i; i = j; j = t; }
    if (j > k) { t = j; j = k; k = t; }
    if (i > j) { t = i; i = j; j = t; }
    if (i == 0) return imap2(j, k);
    if (i == 1) return (j == 1) ? (5 + k) : 8;
    return 9;
}

// ---------------------------------------------------------------------------
__global__ void zero_kernel() {
    int i = blockIdx.x * blockDim.x + threadIdx.x;
    int n = (100 * NA) / 4;
    if (i < n) reinterpret_cast<float4*>(g_M)[i] = make_float4(0.f, 0.f, 0.f, 0.f);
}

// ---------------------------------------------------------------------------
// Pair phase: per pair compute 5 radial channels + direction products,
// atomically accumulate unique symmetric moment components per atom i.
// ---------------------------------------------------------------------------
__global__ void pair_kernel(const float* __restrict__ R, const int* __restrict__ Z,
                            const int* __restrict__ nbr, const float* __restrict__ off,
                            const float* __restrict__ emb) {
    int p = blockIdx.x * blockDim.x + threadIdx.x;
    if (p >= NP) return;
    int ia = nbr[p];
    int ja = nbr[NP + p];

    float dx = R[ja * 3 + 0] - R[ia * 3 + 0] + off[p * 3 + 0];
    float dy = R[ja * 3 + 1] - R[ia * 3 + 1] + off[p * 3 + 1];
    float dz = R[ja * 3 + 2] - R[ia * 3 + 2] + off[p * 3 + 2];
    float dr = sqrtf(dx * dx + dy * dy + dz * dz);
    if (!(dr < RMAXV)) return;  // cutoff == 0 -> contributes nothing

    float inv = 1.0f / (dr + 1e-5f);
    float dn0 = dx * inv, dn1 = dy * inv, dn2 = dz * inv;

    const float betta = 49.0f / 36.0f;
    const float rad_norm = powf(2.0f * betta / PI_F, 0.75f);
    float cut = 0.5f * (cosf(PI_F * dr * (1.0f / RMAXV)) + 1.0f);

    float basis[NB];
#pragma unroll
    for (int b = 0; b < NB; b++) {
        float t = dr - (0.5f + 0.91666666666666667f * (float)b);
        basis[b] = rad_norm * expf(-betta * t * t);
    }

    int zi = Z[ia], zj = Z[ja];
    const float* e = emb + (size_t)(zj * NSP + zi) * (NRAD * NB);
    float pref = 0.37796447300922720f * cut;  // EMB_NORM * cutoff
    float rad[NRAD];
#pragma unroll
    for (int r = 0; r < NRAD; r++) {
        float s = 0.f;
#pragma unroll
        for (int b = 0; b < NB; b++) s += e[r * NB + b] * basis[b];
        rad[r] = pref * s;
    }

    float dnv[3] = {dn0, dn1, dn2};
    float d2[6] = {dn0 * dn0, dn0 * dn1, dn0 * dn2, dn1 * dn1, dn1 * dn2, dn2 * dn2};
    float d3[10] = {d2[0] * dn0, d2[0] * dn1, d2[0] * dn2, d2[3] * dn0, d2[1] * dn2,
                    d2[5] * dn0, d2[3] * dn1, d2[3] * dn2, d2[5] * dn1, d2[5] * dn2};

#pragma unroll
    for (int r = 0; r < NRAD; r++) {
        float v = rad[r];
        atomicAdd(&g_M[r * NA + ia], v);
#pragma unroll
        for (int i = 0; i < 3; i++) atomicAdd(&g_M[(5 + r * 3 + i) * NA + ia], v * dnv[i]);
#pragma unroll
        for (int q = 0; q < 6; q++) atomicAdd(&g_M[(20 + r * 6 + q) * NA + ia], v * d2[q]);
#pragma unroll
        for (int q = 0; q < 10; q++) atomicAdd(&g_M[(50 + r * 10 + q) * NA + ia], v * d3[q]);
    }
}

// ---------------------------------------------------------------------------
// Per-atom contractions -> 360 features (transposed layout)
// ---------------------------------------------------------------------------
#define M2F(r, x, y) m2[r][imap2((x), (y))]
#define M3F(r, x, y, z) m3[r][imap3((x), (y), (z))]

__global__ void __launch_bounds__(128) feat_kernel() {
    int a = blockIdx.x * blockDim.x + threadIdx.x;
    if (a >= NA) return;

    float m0[5], m1[5][3], m2[5][6], m3[5][10];
#pragma unroll
    for (int r = 0; r < 5; r++) m0[r] = g_M[r * NA + a];
#pragma unroll
    for (int r = 0; r < 5; r++)
#pragma unroll
        for (int i = 0; i < 3; i++) m1[r][i] = g_M[(5 + r * 3 + i) * NA + a];
#pragma unroll
    for (int r = 0; r < 5; r++)
#pragma unroll
        for (int q = 0; q < 6; q++) m2[r][q] = g_M[(20 + r * 6 + q) * NA + a];
#pragma unroll
    for (int r = 0; r < 5; r++)
#pragma unroll
        for (int q = 0; q < 10; q++) m3[r][q] = g_M[(50 + r * 10 + q) * NA + a];

    const float w2[6] = {1.f, 2.f, 2.f, 1.f, 2.f, 1.f};
    const float w3[10] = {1.f, 3.f, 3.f, 3.f, 6.f, 3.f, 1.f, 3.f, 3.f, 1.f};

    float* F = g_featsT;
    int pos = 0;
#define PUT(v) do { F[(size_t)pos * NA + a] = (v); pos++; } while (0)

    // M0
#pragma unroll
    for (int r = 0; r < 5; r++) PUT(m0[r]);

    // c1: sum_i M1[r,i] M1[s,i] over tril (r>=s)
#pragma unroll
    for (int r = 0; r < 5; r++)
#pragma unroll
        for (int s = 0; s <= r; s++) {
            float acc = 0.f;
#pragma unroll
            for (int i = 0; i < 3; i++) acc += m1[r][i] * m1[s][i];
            PUT(acc);
        }

    // c2: sum_ij M2 M2 with symmetric weights
#pragma unroll
    for (int r = 0; r < 5; r++)
#pragma unroll
        for (int s = 0; s <= r; s++) {
            float acc = 0.f;
#pragma unroll
            for (int q = 0; q < 6; q++) acc += w2[q] * m2[r][q] * m2[s][q];
            PUT(acc);
        }

    // c3: sum_ijk M3 M3 with symmetric weights
#pragma unroll
    for (int r = 0; r < 5; r++)
#pragma unroll
        for (int s = 0; s <= r; s++) {
            float acc = 0.f;
#pragma unroll
            for (int q = 0; q < 10; q++) acc += w3[q] * m3[r][q] * m3[s][q];
            PUT(acc);
        }

    // c4: sum_{ijk} M2[r,ij] M2[s,ik] M2[t,jk] over (r>=s>=t)
#pragma unroll
    for (int r = 0; r < 5; r++)
#pragma unroll
        for (int s = 0; s <= r; s++)
#pragma unroll
            for (int t = 0; t <= s; t++) {
                float acc = 0.f;
#pragma unroll
                for (int x = 0; x < 3; x++)
#pragma unroll
                    for (int y = 0; y < 3; y++)
#pragma unroll
                        for (int z = 0; z < 3; z++)
                            acc += M2F(r, x, y) * M2F(s, x, z) * M2F(t, y, z);
                PUT(acc);
            }

    // c5: sum_ij M1[r,i] M1[s,j] M2[t,ij], pair(r>=s) outer, t inner
#pragma unroll
    for (int r = 0; r < 5; r++)
#pragma unroll
        for (int s = 0; s <= r; s++)
#pragma unroll
            for (int t = 0; t < 5; t++) {
                float acc = 0.f;
#pragma unroll
                for (int x = 0; x < 3; x++)
#pragma unroll
                    for (int y = 0; y < 3; y++)
                        acc += m1[r][x] * m1[s][y] * M2F(t, x, y);
                PUT(acc);
            }

    // c6: A[k][l] = sum_ij M3[r,ijk] M3[s,ijl]; c6 = sum_kl A[k][l] M2[t,kl]
#pragma unroll
    for (int r = 0; r < 5; r++)
#pragma unroll
        for (int s = 0; s <= r; s++) {
            float A[3][3];
#pragma unroll
            for (int k = 0; k < 3; k++)
#pragma unroll
                for (int l = 0; l < 3; l++) {
                    float acc = 0.f;
#pragma unroll
                    for (int x = 0; x < 3; x++)
#pragma unroll
                        for (int y = 0; y < 3; y++)
                            acc += M3F(r, x, y, k) * M3F(s, x, y, l);
                    A[k][l] = acc;
                }
#pragma unroll
            for (int t = 0; t < 5; t++) {
                float acc = 0.f;
#pragma unroll
                for (int k = 0; k < 3; k++)
#pragma unroll
                    for (int l = 0; l < 3; l++)
                        acc += A[k][l] * M2F(t, k, l);
                PUT(acc);
            }
        }

    // c7: B[k] = sum_ij M3[r,ijk] M2[s,ij]; c7 = sum_k B[k] M1[t,k], full (r,s,t)
#pragma unroll
    for (int r = 0; r < 5; r++)
#pragma unroll
        for (int s = 0; s < 5; s++) {
            float B[3];
#pragma unroll
            for (int k = 0; k < 3; k++) {
                float acc = 0.f;
#pragma unroll
                for (int x = 0; x < 3; x++)
#pragma unroll
                    for (int y = 0; y < 3; y++)
                        acc += M3F(r, x, y, k) * M2F(s, x, y);
                B[k] = acc;
            }
#pragma unroll
            for (int t = 0; t < 5; t++)
                PUT(B[0] * m1[t][0] + B[1] * m1[t][1] + B[2] * m1[t][2]);
        }
#undef PUT
}

// ---------------------------------------------------------------------------
// Tiled SGEMM, A stored K-major [K][M], B row-major [K][N].
// C[m][n] = swish?(scale * sum_k A[k][m]B[k][n] + 0.1*bias[n])
// transC: write C transposed [N][M]. Inner loop uses packed fma.rn.f32x2.
// ---------------------------------------------------------------------------
__global__ void __launch_bounds__(256) gemm_kernel(
    const float* __restrict__ A, const float* __restrict__ B,
    const float* __restrict__ bias, float* __restrict__ C,
    int M, int N, int K, float scale, int transC, int doSwish) {
    __shared__ float As[8][128];
    __shared__ float Bs[8][128];

    int bm = blockIdx.y * 128;
    int bn = blockIdx.x * 128;
    int tid = threadIdx.x;
    int lak = tid >> 5, lam = (tid & 31) * 4;
    int tm = (tid >> 4) * 8, tn = (tid & 15) * 8;

    u64 acc[8][4];
#pragma unroll
    for (int i = 0; i < 8; i++)
#pragma unroll
        for (int j = 0; j < 4; j++) acc[i][j] = 0ull;

    for (int k0 = 0; k0 < K; k0 += 8) {
        float4 av = make_float4(0.f, 0.f, 0.f, 0.f);
        if (bm + lam < M) av = *(const float4*)(A + (size_t)(k0 + lak) * M + bm + lam);
        *(float4*)&As[lak][lam] = av;
        float4 bv = *(const float4*)(B + (size_t)(k0 + lak) * N + bn + lam);
        *(float4*)&Bs[lak][lam] = bv;
        __syncthreads();
#pragma unroll
        for (int kk = 0; kk < 8; kk++) {
            float areg[8];
            u64 b2[4];
#pragma unroll
            for (int i = 0; i < 8; i++) areg[i] = As[kk][tm + i];
            const u64* bp = (const u64*)&Bs[kk][tn];
#pragma unroll
            for (int j = 0; j < 4; j++) b2[j] = bp[j];
#pragma unroll
            for (int i = 0; i < 8; i++) {
                u64 ad = pack2(areg[i], areg[i]);
#pragma unroll
                for (int j = 0; j < 4; j++) fma2(acc[i][j], ad, b2[j]);
            }
        }
        __syncthreads();
    }

#pragma unroll
    for (int i = 0; i < 8; i++) {
        int row = bm + tm + i;
        if (row >= M) continue;
#pragma unroll
        for (int j = 0; j < 4; j++) {
            float lo, hi;
            unpack2(lo, hi, acc[i][j]);
            int n0 = bn + tn + j * 2;
            float v0 = lo * scale + 0.1f * bias[n0];
            float v1 = hi * scale + 0.1f * bias[n0 + 1];
            if (doSwish) {
                v0 = v0 / (1.0f + expf(-v0));
                v1 = v1 / (1.0f + expf(-v1));
            }
            if (transC) {
                C[(size_t)n0 * M + row] = v0;
                C[(size_t)(n0 + 1) * M + row] = v1;
            } else {
                *(float2*)(C + (size_t)row * N + n0) = make_float2(v0, v1);
            }
        }
    }
}

// ---------------------------------------------------------------------------
// Final GEMV + species mask: one warp per atom.
// ---------------------------------------------------------------------------
__global__ void out_kernel(const float* __restrict__ W3, const float* __restrict__ b3,
                           const int* __restrict__ Z, float* __restrict__ out) {
    int warp = (blockIdx.x * blockDim.x + threadIdx.x) >> 5;
    int lane = threadIdx.x & 31;
    if (warp >= NA) return;
    const float* h = g_h2 + (size_t)warp * U2;
    float s = 0.f;
#pragma unroll
    for (int t = 0; t < U2 / 32; t++) s += h[lane + 32 * t] * W3[lane + 32 * t];
#pragma unroll
    for (int o = 16; o; o >>= 1) s += __shfl_xor_sync(0xffffffffu, s, o);
    if (lane == 0) {
        float v = s * 0.04419417382415922f + 0.1f * b3[0];
        out[warp] = (Z[warp] > 0) ? v : 0.0f;
    }
}

// ---------------------------------------------------------------------------
extern "C" void kernel_launch(void* const* d_in, const int* in_sizes, int n_in,
                              void* d_out, int out_size) {
    const float* R   = (const float*)d_in[0];
    const int*   Z   = (const int*)d_in[1];
    const int*   nbr = (const int*)d_in[2];
    // d_in[3] = box (unused)
    const float* off = (const float*)d_in[4];
    const float* emb = (const float*)d_in[5];
    const float* W1  = (const float*)d_in[6];
    const float* b1  = (const float*)d_in[7];
    const float* W2  = (const float*)d_in[8];
    const float* b2  = (const float*)d_in[9];
    const float* W3  = (const float*)d_in[10];
    const float* b3  = (const float*)d_in[11];
    float* out = (float*)d_out;

    float *pFeats, *pH1T, *pH2;
    cudaGetSymbolAddress((void**)&pFeats, g_featsT);
    cudaGetSymbolAddress((void**)&pH1T, g_h1T);
    cudaGetSymbolAddress((void**)&pH2, g_h2);

    zero_kernel<<<(100 * NA / 4 + 255) / 256, 256>>>();
    pair_kernel<<<(NP + 255) / 256, 256>>>(R, Z, nbr, off, emb);
    feat_kernel<<<(NA + 127) / 128, 128>>>();

    const float s1 = 0.05270462766947299f;  // 1/sqrt(360)
    const float s2 = 0.04419417382415922f;  // 1/sqrt(512)

    {   // h1T = swish(featsT^T @ W1 * s1 + 0.1 b1), stored transposed
        dim3 g(U1 / 128, (NA + 127) / 128);
        gemm_kernel<<<g, 256>>>(pFeats, W1, b1, pH1T, NA, U1, NFEAT, s1, 1, 1);
    }
    {   // h2 = swish(h1 @ W2 * s2 + 0.1 b2), row-major
        dim3 g(U2 / 128, (NA + 127) / 128);
        gemm_kernel<<<g, 256>>>(pH1T, W2, b2, pH2, NA, U2, U1, s2, 0, 1);
    }
    out_kernel<<<(NA * 32 + 255) / 256, 256>>>(W3, b3, Z, out);
}

// round 3
// speedup vs baseline: 1.8322x; 1.8322x over previous
#include <cuda_runtime.h>
#include <cuda_bf16.h>
#include <math.h>
#include <stdint.h>

#define NA 20000
#define NAP 20096           // padded rows (157*128)
#define NP 800000
#define NSP 119
#define NB 7
#define RMAXV 6.0f
#define PI_F 3.14159265358979323846f

#define KP1 1088            // 3*360 padded to 64
#define KP2 1536            // 3*512
#define U 512

// ---------------------------------------------------------------------------
// device scratch (zero-initialized at module load)
// ---------------------------------------------------------------------------
__device__ float g_M[(size_t)NA * 100];                    // [atom][100] moments
__device__ __nv_bfloat16 g_A1[(size_t)NAP * KP1];          // feats, bf16 triple
__device__ __nv_bfloat16 g_B1[(size_t)U * KP1];            // W1^T, bf16 triple
__device__ __nv_bfloat16 g_A2[(size_t)NAP * KP2];          // h1, bf16 triple
__device__ __nv_bfloat16 g_B2[(size_t)U * KP2];            // W2^T, bf16 triple
__device__ float g_h2[(size_t)NA * U];                     // h2 fp32 row-major

// ---------------------------------------------------------------------------
// helpers
// ---------------------------------------------------------------------------
__device__ __forceinline__ uint32_t smem_u32(const void* p) {
    uint32_t a;
    asm("{ .reg .u64 t; cvta.to.shared.u64 t, %1; cvt.u32.u64 %0, t; }" : "=r"(a) : "l"(p));
    return a;
}
#define CP16(dst, src)   asm volatile("cp.async.cg.shared.global [%0], [%1], 16;" :: "r"(dst), "l"(src))
#define CP_COMMIT()      asm volatile("cp.async.commit_group;" ::: "memory")
#define CP_WAIT(n)       asm volatile("cp.async.wait_group %0;" :: "n"(n) : "memory")

__device__ __forceinline__ void ldm_x4(uint32_t& r0, uint32_t& r1, uint32_t& r2, uint32_t& r3,
                                       uint32_t addr) {
    asm volatile("ldmatrix.sync.aligned.m8n8.x4.shared.b16 {%0,%1,%2,%3}, [%4];"
                 : "=r"(r0), "=r"(r1), "=r"(r2), "=r"(r3) : "r"(addr));
}
__device__ __forceinline__ void mma16816(float* d, const uint32_t* a, const uint32_t* b) {
    asm volatile("mma.sync.aligned.m16n8k16.row.col.f32.bf16.bf16.f32 "
                 "{%0,%1,%2,%3}, {%4,%5,%6,%7}, {%8,%9}, {%0,%1,%2,%3};"
                 : "+f"(d[0]), "+f"(d[1]), "+f"(d[2]), "+f"(d[3])
                 : "r"(a[0]), "r"(a[1]), "r"(a[2]), "r"(a[3]), "r"(b[0]), "r"(b[1]));
}

// bf16 hi/lo split
__device__ __forceinline__ void bsplit(float v, uint32_t& h, uint32_t& l) {
    __nv_bfloat16 hb = __float2bfloat16(v);
    float r = v - __bfloat162float(hb);
    __nv_bfloat16 lb = __float2bfloat16(r);
    h = (uint32_t)__bfloat16_as_ushort(hb);
    l = (uint32_t)__bfloat16_as_ushort(lb);
}

// vector f32 reduction (sm_90+)
__device__ __forceinline__ void red4(float* p, float a, float b, float c, float d) {
    asm volatile("red.global.add.v4.f32 [%0], {%1,%2,%3,%4};"
                 :: "l"(p), "f"(a), "f"(b), "f"(c), "f"(d) : "memory");
}

// symmetric index maps
__device__ __forceinline__ int imap2(int a, int b) {
    int i = a < b ? a : b, j = a < b ? b : a;
    return (i == 0) ? j : ((i == 1) ? (2 + j) : 5);
}
__device__ __forceinline__ int imap3(int a, int b, int c) {
    int i = a, j = b, k = c, t;
    if (i > j) { t = i; i = j; j = t; }
    if (j > k) { t = j; j = k; k = t; }
    if (i > j) { t = i; i = j; j = t; }
    if (i == 0) return imap2(j, k);
    if (i == 1) return (j == 1) ? (5 + k) : 8;
    return 9;
}

// ---------------------------------------------------------------------------
__global__ void zero_kernel() {
    size_t i = (size_t)blockIdx.x * blockDim.x + threadIdx.x;
    size_t n = ((size_t)NA * 100) / 4;
    if (i < n) reinterpret_cast<float4*>(g_M)[i] = make_float4(0.f, 0.f, 0.f, 0.f);
}

// ---------------------------------------------------------------------------
// pair phase -> 25 red.v4 per active pair into g_M[atom][r*20 + {0..19}]
// ---------------------------------------------------------------------------
__global__ void pair_kernel(const float* __restrict__ R, const int* __restrict__ Z,
                            const int* __restrict__ nbr, const float* __restrict__ off,
                            const float* __restrict__ emb) {
    int p = blockIdx.x * blockDim.x + threadIdx.x;
    if (p >= NP) return;
    int ia = nbr[p];
    int ja = nbr[NP + p];

    float dx = R[ja * 3 + 0] - R[ia * 3 + 0] + off[p * 3 + 0];
    float dy = R[ja * 3 + 1] - R[ia * 3 + 1] + off[p * 3 + 1];
    float dz = R[ja * 3 + 2] - R[ia * 3 + 2] + off[p * 3 + 2];
    float dr = sqrtf(dx * dx + dy * dy + dz * dz);
    if (!(dr < RMAXV)) return;

    float inv = 1.0f / (dr + 1e-5f);
    float dn0 = dx * inv, dn1 = dy * inv, dn2 = dz * inv;

    const float betta = 49.0f / 36.0f;
    const float rad_norm = powf(2.0f * betta / PI_F, 0.75f);
    float cut = 0.5f * (cosf(PI_F * dr * (1.0f / RMAXV)) + 1.0f);

    float basis[NB];
#pragma unroll
    for (int b = 0; b < NB; b++) {
        float t = dr - (0.5f + 0.91666666666666667f * (float)b);
        basis[b] = rad_norm * expf(-betta * t * t);
    }

    int zi = Z[ia], zj = Z[ja];
    const float* e = emb + (size_t)(zj * NSP + zi) * 35;
    float pref = 0.37796447300922720f * cut;
    float rad[5];
#pragma unroll
    for (int r = 0; r < 5; r++) {
        float s = 0.f;
#pragma unroll
        for (int b = 0; b < NB; b++) s += e[r * NB + b] * basis[b];
        rad[r] = pref * s;
    }

    float d2[6] = {dn0 * dn0, dn0 * dn1, dn0 * dn2, dn1 * dn1, dn1 * dn2, dn2 * dn2};
    float d3[10] = {d2[0] * dn0, d2[0] * dn1, d2[0] * dn2, d2[3] * dn0, d2[1] * dn2,
                    d2[5] * dn0, d2[3] * dn1, d2[3] * dn2, d2[5] * dn1, d2[5] * dn2};

    float* base = g_M + (size_t)ia * 100;
#pragma unroll
    for (int r = 0; r < 5; r++) {
        float v = rad[r];
        float* q = base + r * 20;
        red4(q + 0,  v,          v * dn0,    v * dn1,    v * dn2);
        red4(q + 4,  v * d2[0],  v * d2[1],  v * d2[2],  v * d2[3]);
        red4(q + 8,  v * d2[4],  v * d2[5],  v * d3[0],  v * d3[1]);
        red4(q + 12, v * d3[2],  v * d3[3],  v * d3[4],  v * d3[5]);
        red4(q + 16, v * d3[6],  v * d3[7],  v * d3[8],  v * d3[9]);
    }
}

// ---------------------------------------------------------------------------
// per-atom contractions -> 360 feats -> bf16 triple rows of g_A1
// ---------------------------------------------------------------------------
__device__ __forceinline__ void flush8(const float* fb, uint4* dst) {
    uint32_t pw[12];
#pragma unroll
    for (int e = 0; e < 4; e++) {
        uint32_t H0, L0, H1, L1;
        bsplit(fb[2 * e], H0, L0);
        bsplit(fb[2 * e + 1], H1, L1);
        pw[3 * e + 0] = H0 | (L0 << 16);
        pw[3 * e + 1] = H0 | (H1 << 16);
        pw[3 * e + 2] = L1 | (H1 << 16);
    }
    dst[0] = make_uint4(pw[0], pw[1], pw[2], pw[3]);
    dst[1] = make_uint4(pw[4], pw[5], pw[6], pw[7]);
    dst[2] = make_uint4(pw[8], pw[9], pw[10], pw[11]);
}

#define M2F(r, x, y) m2[r][imap2((x), (y))]
#define M3F(r, x, y, z) m3[r][imap3((x), (y), (z))]

__global__ void __launch_bounds__(128) feat_kernel() {
    int a = blockIdx.x * blockDim.x + threadIdx.x;
    if (a >= NA) return;

    const float* v = g_M + (size_t)a * 100;
    float m0[5], m1[5][3], m2[5][6], m3[5][10];
#pragma unroll
    for (int r = 0; r < 5; r++) {
        m0[r] = v[r * 20];
#pragma unroll
        for (int i = 0; i < 3; i++) m1[r][i] = v[r * 20 + 1 + i];
#pragma unroll
        for (int q = 0; q < 6; q++) m2[r][q] = v[r * 20 + 4 + q];
#pragma unroll
        for (int q = 0; q < 10; q++) m3[r][q] = v[r * 20 + 10 + q];
    }

    const float w2[6] = {1.f, 2.f, 2.f, 1.f, 2.f, 1.f};
    const float w3[10] = {1.f, 3.f, 3.f, 3.f, 6.f, 3.f, 1.f, 3.f, 3.f, 1.f};

    char* rowb = (char*)g_A1 + (size_t)a * (KP1 * 2);
    float fb[8];
    int cnt = 0, pos = 0;
#define PUT(x) do { fb[cnt] = (x); \
    if (cnt == 7) { flush8(fb, (uint4*)(rowb + (size_t)(pos - 7) * 6)); cnt = 0; } else cnt++; \
    pos++; } while (0)

#pragma unroll
    for (int r = 0; r < 5; r++) PUT(m0[r]);

#pragma unroll
    for (int r = 0; r < 5; r++)
#pragma unroll
        for (int s = 0; s <= r; s++) {
            float acc = 0.f;
#pragma unroll
            for (int i = 0; i < 3; i++) acc += m1[r][i] * m1[s][i];
            PUT(acc);
        }

#pragma unroll
    for (int r = 0; r < 5; r++)
#pragma unroll
        for (int s = 0; s <= r; s++) {
            float acc = 0.f;
#pragma unroll
            for (int q = 0; q < 6; q++) acc += w2[q] * m2[r][q] * m2[s][q];
            PUT(acc);
        }

#pragma unroll
    for (int r = 0; r < 5; r++)
#pragma unroll
        for (int s = 0; s <= r; s++) {
            float acc = 0.f;
#pragma unroll
            for (int q = 0; q < 10; q++) acc += w3[q] * m3[r][q] * m3[s][q];
            PUT(acc);
        }

#pragma unroll
    for (int r = 0; r < 5; r++)
#pragma unroll
        for (int s = 0; s <= r; s++)
#pragma unroll
            for (int t = 0; t <= s; t++) {
                float acc = 0.f;
#pragma unroll
                for (int x = 0; x < 3; x++)
#pragma unroll
                    for (int y = 0; y < 3; y++)
#pragma unroll
                        for (int z = 0; z < 3; z++)
                            acc += M2F(r, x, y) * M2F(s, x, z) * M2F(t, y, z);
                PUT(acc);
            }

#pragma unroll
    for (int r = 0; r < 5; r++)
#pragma unroll
        for (int s = 0; s <= r; s++)
#pragma unroll
            for (int t = 0; t < 5; t++) {
                float acc = 0.f;
#pragma unroll
                for (int x = 0; x < 3; x++)
#pragma unroll
                    for (int y = 0; y < 3; y++)
                        acc += m1[r][x] * m1[s][y] * M2F(t, x, y);
                PUT(acc);
            }

#pragma unroll
    for (int r = 0; r < 5; r++)
#pragma unroll
        for (int s = 0; s <= r; s++) {
            float A[3][3];
#pragma unroll
            for (int k = 0; k < 3; k++)
#pragma unroll
                for (int l = 0; l < 3; l++) {
                    float acc = 0.f;
#pragma unroll
                    for (int x = 0; x < 3; x++)
#pragma unroll
                        for (int y = 0; y < 3; y++)
                            acc += M3F(r, x, y, k) * M3F(s, x, y, l);
                    A[k][l] = acc;
                }
#pragma unroll
            for (int t = 0; t < 5; t++) {
                float acc = 0.f;
#pragma unroll
                for (int k = 0; k < 3; k++)
#pragma unroll
                    for (int l = 0; l < 3; l++)
                        acc += A[k][l] * M2F(t, k, l);
                PUT(acc);
            }
        }

#pragma unroll
    for (int r = 0; r < 5; r++)
#pragma unroll
        for (int s = 0; s < 5; s++) {
            float B[3];
#pragma unroll
            for (int k = 0; k < 3; k++) {
                float acc = 0.f;
#pragma unroll
                for (int x = 0; x < 3; x++)
#pragma unroll
                    for (int y = 0; y < 3; y++)
                        acc += M3F(r, x, y, k) * M2F(s, x, y);
                B[k] = acc;
            }
#pragma unroll
            for (int t = 0; t < 5; t++)
                PUT(B[0] * m1[t][0] + B[1] * m1[t][1] + B[2] * m1[t][2]);
        }
#undef PUT
}

// ---------------------------------------------------------------------------
// weight prep: W[K][512] fp32 -> B[n][Kp] bf16 triple (hi,hi,lo)
// ---------------------------------------------------------------------------
__global__ void wprep_kernel(const float* __restrict__ W, __nv_bfloat16* __restrict__ B,
                             int K, int Kp) {
    int idx = blockIdx.x * blockDim.x + threadIdx.x;
    if (idx >= K * 512) return;
    int k = idx >> 9, n = idx & 511;
    float w = W[(size_t)k * 512 + n];
    __nv_bfloat16 h = __float2bfloat16(w);
    __nv_bfloat16 l = __float2bfloat16(w - __bfloat162float(h));
    __nv_bfloat16* row = B + (size_t)n * Kp + 3 * k;
    row[0] = h; row[1] = h; row[2] = l;
}

// ---------------------------------------------------------------------------
// mma.sync bf16 GEMM: C[M,512] = act(A[M,Kp] @ B[512,Kp]^T * scale + 0.1*bias)
// block 128x128, warp 32x64 (8 warps), k-tile 32, 2-stage cp.async.
// Smem tiles padded to 80B rows (conflict-free ldmatrix).
// mode 1: swish -> bf16-triple rows (next layer A). mode 2: swish -> fp32.
// ---------------------------------------------------------------------------
#define STAGE 20480
#define BOFF  10240

__device__ __forceinline__ void load_stage(uint32_t sb, const char* Ab, const char* Bb,
                                           int m0, int bn, int ldab, int kt, int tid) {
    uint32_t st = (uint32_t)(kt & 1) * STAGE;
    int k0B = kt * 64;
#pragma unroll
    for (int i = 0; i < 2; i++) {
        int t = tid + i * 256;
        int row = t >> 2, ch = (t & 3) * 16;
        CP16(sb + st + (uint32_t)(row * 80 + ch),
             Ab + (size_t)(m0 + row) * ldab + k0B + ch);
    }
#pragma unroll
    for (int i = 0; i < 2; i++) {
        int t = tid + i * 256;
        int row = t >> 2, ch = (t & 3) * 16;
        CP16(sb + st + BOFF + (uint32_t)(row * 80 + ch),
             Bb + (size_t)(bn * 128 + row) * ldab + k0B + ch);
    }
    CP_COMMIT();
}

__global__ void __launch_bounds__(256) gemm_mma(
    const __nv_bfloat16* __restrict__ A, const __nv_bfloat16* __restrict__ B,
    const float* __restrict__ bias, char* __restrict__ Cout,
    int Kp, float scale, int mode) {
    __shared__ __align__(16) char smem[2 * STAGE];
    uint32_t sb = smem_u32(smem);

    const int tid = threadIdx.x, wid = tid >> 5, lane = tid & 31;
    const int wm = wid & 3, wn = wid >> 2;          // warp grid 4(m) x 2(n)
    const int bn = blockIdx.x, m0 = blockIdx.y * 128;
    const int ldab = Kp * 2;
    const int nk = Kp >> 5;

    const char* Ab = (const char*)A;
    const char* Bb = (const char*)B;

    float d[2][8][4];
#pragma unroll
    for (int i = 0; i < 2; i++)
#pragma unroll
        for (int j = 0; j < 8; j++)
#pragma unroll
            for (int q = 0; q < 4; q++) d[i][j][q] = 0.f;

    load_stage(sb, Ab, Bb, m0, bn, ldab, 0, tid);
    load_stage(sb, Ab, Bb, m0, bn, ldab, 1, tid);
    CP_WAIT(1);
    __syncthreads();

    const int lr = lane & 15, lc = lane >> 4;

    for (int kt = 0; kt < nk; kt++) {
        uint32_t sA = sb + (uint32_t)(kt & 1) * STAGE;
        uint32_t sBt = sA + BOFF;
#pragma unroll
        for (int h = 0; h < 2; h++) {
            uint32_t a[2][4];
#pragma unroll
            for (int mi = 0; mi < 2; mi++)
                ldm_x4(a[mi][0], a[mi][1], a[mi][2], a[mi][3],
                       sA + (uint32_t)((wm * 32 + mi * 16 + lr) * 80 + lc * 16 + h * 32));
            uint32_t b[8][2];
#pragma unroll
            for (int pi = 0; pi < 4; pi++) {
                uint32_t t0, t1, t2, t3;
                ldm_x4(t0, t1, t2, t3,
                       sBt + (uint32_t)((wn * 64 + pi * 16 + lr) * 80 + lc * 16 + h * 32));
                b[2 * pi][0] = t0; b[2 * pi][1] = t2;
                b[2 * pi + 1][0] = t1; b[2 * pi + 1][1] = t3;
            }
#pragma unroll
            for (int mi = 0; mi < 2; mi++)
#pragma unroll
                for (int ni = 0; ni < 8; ni++)
                    mma16816(d[mi][ni], a[mi], b[ni]);
        }
        __syncthreads();
        if (kt + 2 < nk) {
            load_stage(sb, Ab, Bb, m0, bn, ldab, kt + 2, tid);
            CP_WAIT(1);
        } else {
            CP_WAIT(0);
        }
        __syncthreads();
    }

    // epilogue
    const int g = lane >> 2, tg = lane & 3;
#pragma unroll
    for (int mi = 0; mi < 2; mi++) {
#pragma unroll
        for (int ni = 0; ni < 8; ni++) {
            int n = bn * 128 + wn * 64 + ni * 8 + 2 * tg;
            float bz0 = 0.1f * bias[n], bz1 = 0.1f * bias[n + 1];
#pragma unroll
            for (int half = 0; half < 2; half++) {
                int m = m0 + wm * 32 + mi * 16 + g + half * 8;
                if (m >= NA) continue;
                float v0 = d[mi][ni][2 * half + 0] * scale + bz0;
                float v1 = d[mi][ni][2 * half + 1] * scale + bz1;
                v0 = v0 / (1.0f + __expf(-v0));
                v1 = v1 / (1.0f + __expf(-v1));
                if (mode == 1) {
                    uint32_t H0, L0, H1, L1;
                    bsplit(v0, H0, L0);
                    bsplit(v1, H1, L1);
                    uint32_t* dst = (uint32_t*)(Cout + (size_t)m * (KP2 * 2) + (size_t)n * 6);
                    dst[0] = H0 | (L0 << 16);
                    dst[1] = H0 | (H1 << 16);
                    dst[2] = L1 | (H1 << 16);
                } else {
                    *(float2*)((float*)Cout + (size_t)m * U + n) = make_float2(v0, v1);
                }
            }
        }
    }
}

// ---------------------------------------------------------------------------
// final GEMV + species mask
// ---------------------------------------------------------------------------
__global__ void out_kernel(const float* __restrict__ W3, const float* __restrict__ b3,
                           const int* __restrict__ Z, float* __restrict__ out) {
    int warp = (blockIdx.x * blockDim.x + threadIdx.x) >> 5;
    int lane = threadIdx.x & 31;
    if (warp >= NA) return;
    const float* h = g_h2 + (size_t)warp * U;
    float s = 0.f;
#pragma unroll
    for (int t = 0; t < U / 32; t++) s += h[lane + 32 * t] * W3[lane + 32 * t];
#pragma unroll
    for (int o = 16; o; o >>= 1) s += __shfl_xor_sync(0xffffffffu, s, o);
    if (lane == 0) {
        float v = s * 0.04419417382415922f + 0.1f * b3[0];
        out[warp] = (Z[warp] > 0) ? v : 0.0f;
    }
}

// ---------------------------------------------------------------------------
extern "C" void kernel_launch(void* const* d_in, const int* in_sizes, int n_in,
                              void* d_out, int out_size) {
    const float* R   = (const float*)d_in[0];
    const int*   Z   = (const int*)d_in[1];
    const int*   nbr = (const int*)d_in[2];
    const float* off = (const float*)d_in[4];
    const float* emb = (const float*)d_in[5];
    const float* W1  = (const float*)d_in[6];
    const float* b1  = (const float*)d_in[7];
    const float* W2  = (const float*)d_in[8];
    const float* b2  = (const float*)d_in[9];
    const float* W3  = (const float*)d_in[10];
    const float* b3  = (const float*)d_in[11];
    float* out = (float*)d_out;

    __nv_bfloat16 *pA1, *pB1, *pA2, *pB2;
    float* pH2;
    cudaGetSymbolAddress((void**)&pA1, g_A1);
    cudaGetSymbolAddress((void**)&pB1, g_B1);
    cudaGetSymbolAddress((void**)&pA2, g_A2);
    cudaGetSymbolAddress((void**)&pB2, g_B2);
    cudaGetSymbolAddress((void**)&pH2, g_h2);

    zero_kernel<<<((NA * 100 / 4) + 255) / 256, 256>>>();
    pair_kernel<<<(NP + 255) / 256, 256>>>(R, Z, nbr, off, emb);
    feat_kernel<<<(NA + 127) / 128, 128>>>();
    wprep_kernel<<<(360 * 512 + 255) / 256, 256>>>(W1, pB1, 360, KP1);
    wprep_kernel<<<(512 * 512 + 255) / 256, 256>>>(W2, pB2, 512, KP2);

    const float s1 = 0.05270462766947299f;  // 1/sqrt(360)
    const float s2 = 0.04419417382415922f;  // 1/sqrt(512)

    dim3 g(4, NAP / 128);
    gemm_mma<<<g, 256>>>(pA1, pB1, b1, (char*)pA2, KP1, s1, 1);
    gemm_mma<<<g, 256>>>(pA2, pB2, b2, (char*)pH2, KP2, s2, 2);

    out_kernel<<<(NA * 32 + 255) / 256, 256>>>(W3, b3, Z, out);
}

// round 4
// speedup vs baseline: 2.1136x; 1.1536x over previous
#include <cuda_runtime.h>
#include <cuda_fp16.h>
#include <math.h>
#include <stdint.h>

#define NA 20000
#define NAP 20096           // padded rows (157*128)
#define NP 800000
#define NSP 119
#define NB 7
#define RMAXV 6.0f
#define PI_F 3.14159265358979323846f

#define KP1 736             // 2*360 padded to 32-element k-tiles
#define KP2 1024            // 2*512
#define U 512
#define IN_SCALE 0.00390625f   // 2^-8 applied to GEMM A inputs

// ---------------------------------------------------------------------------
// device scratch (static; zero at module load)
// ---------------------------------------------------------------------------
__device__ int   g_cnt[NA];
__device__ int   g_ofs[NA + 1];
__device__ int   g_cur[NA];
__device__ float g_prod[(size_t)NP * 32];        // per active pair: rad[5]+D[20]
__device__ float g_M[(size_t)NA * 100];          // [atom][100] moments
__device__ __half g_A1[(size_t)NAP * KP1];       // feats (scaled), fp16 hi/lo
__device__ __half g_B1[(size_t)U * KP1];         // W1^T fp16 (hi,hi)
__device__ __half g_A2[(size_t)NAP * KP2];       // h1 (scaled), fp16 hi/lo
__device__ __half g_B2[(size_t)U * KP2];         // W2^T fp16 (hi,hi)
__device__ float g_h2[(size_t)NA * U];           // h2 fp32 row-major

// ---------------------------------------------------------------------------
// helpers
// ---------------------------------------------------------------------------
__device__ __forceinline__ uint32_t smem_u32(const void* p) {
    uint32_t a;
    asm("{ .reg .u64 t; cvta.to.shared.u64 t, %1; cvt.u32.u64 %0, t; }" : "=r"(a) : "l"(p));
    return a;
}
#define CP16(dst, src)   asm volatile("cp.async.cg.shared.global [%0], [%1], 16;" :: "r"(dst), "l"(src))
#define CP_COMMIT()      asm volatile("cp.async.commit_group;" ::: "memory")
#define CP_WAIT(n)       asm volatile("cp.async.wait_group %0;" :: "n"(n) : "memory")

__device__ __forceinline__ void ldm_x4(uint32_t& r0, uint32_t& r1, uint32_t& r2, uint32_t& r3,
                                       uint32_t addr) {
    asm volatile("ldmatrix.sync.aligned.m8n8.x4.shared.b16 {%0,%1,%2,%3}, [%4];"
                 : "=r"(r0), "=r"(r1), "=r"(r2), "=r"(r3) : "r"(addr));
}
__device__ __forceinline__ void mma16816(float* d, const uint32_t* a, const uint32_t* b) {
    asm volatile("mma.sync.aligned.m16n8k16.row.col.f32.f16.f16.f32 "
                 "{%0,%1,%2,%3}, {%4,%5,%6,%7}, {%8,%9}, {%0,%1,%2,%3};"
                 : "+f"(d[0]), "+f"(d[1]), "+f"(d[2]), "+f"(d[3])
                 : "r"(a[0]), "r"(a[1]), "r"(a[2]), "r"(a[3]), "r"(b[0]), "r"(b[1]));
}

// fp16 hi/lo split (input assumed pre-scaled into fp16 range)
__device__ __forceinline__ void hsplit(float v, uint32_t& h, uint32_t& l) {
    __half hb = __float2half(v);
    float r = v - __half2float(hb);
    __half lb = __float2half(r);
    h = (uint32_t)__half_as_ushort(hb);
    l = (uint32_t)__half_as_ushort(lb);
}

// symmetric index maps (compile-time folded)
__device__ __forceinline__ int imap2(int a, int b) {
    int i = a < b ? a : b, j = a < b ? b : a;
    return (i == 0) ? j : ((i == 1) ? (2 + j) : 5);
}
__device__ __forceinline__ int imap3(int a, int b, int c) {
    int i = a, j = b, k = c, t;
    if (i > j) { t = i; i = j; j = t; }
    if (j > k) { t = j; j = k; k = t; }
    if (i > j) { t = i; i = j; j = t; }
    if (i == 0) return imap2(j, k);
    if (i == 1) return (j == 1) ? (5 + k) : 8;
    return 9;
}

// ---------------------------------------------------------------------------
// pair pipeline: zero counts -> histogram -> scan -> phase1 -> phase2
// ---------------------------------------------------------------------------
__global__ void zc_kernel() {
    int i = blockIdx.x * blockDim.x + threadIdx.x;
    if (i < NA) g_cnt[i] = 0;
}

__global__ void hist_kernel(const float* __restrict__ R, const int* __restrict__ nbr,
                            const float* __restrict__ off) {
    int p = blockIdx.x * blockDim.x + threadIdx.x;
    if (p >= NP) return;
    int ia = nbr[p], ja = nbr[NP + p];
    float dx = R[ja * 3 + 0] - R[ia * 3 + 0] + off[p * 3 + 0];
    float dy = R[ja * 3 + 1] - R[ia * 3 + 1] + off[p * 3 + 1];
    float dz = R[ja * 3 + 2] - R[ia * 3 + 2] + off[p * 3 + 2];
    float dr = sqrtf(dx * dx + dy * dy + dz * dz);
    if (dr < RMAXV) atomicAdd(&g_cnt[ia], 1);
}

__global__ void __launch_bounds__(1024) scan_kernel() {
    __shared__ int part[1024];
    int t = threadIdx.x;
    int b0 = t * 20;
    int b1 = b0 + 20 < NA ? b0 + 20 : NA;
    int s = 0;
    for (int b = b0; b < b1; b++) s += g_cnt[b];
    part[t] = s;
    __syncthreads();
    for (int o = 1; o < 1024; o <<= 1) {
        int v = (t >= o) ? part[t - o] : 0;
        __syncthreads();
        part[t] += v;
        __syncthreads();
    }
    int run = (t == 0) ? 0 : part[t - 1];
    for (int b = b0; b < b1; b++) {
        g_ofs[b] = run;
        g_cur[b] = run;
        run += g_cnt[b];
    }
    if (t == 1023) g_ofs[NA] = run;
}

__global__ void p1_kernel(const float* __restrict__ R, const int* __restrict__ Z,
                          const int* __restrict__ nbr, const float* __restrict__ off,
                          const float* __restrict__ emb) {
    int p = blockIdx.x * blockDim.x + threadIdx.x;
    if (p >= NP) return;
    int ia = nbr[p], ja = nbr[NP + p];

    float dx = R[ja * 3 + 0] - R[ia * 3 + 0] + off[p * 3 + 0];
    float dy = R[ja * 3 + 1] - R[ia * 3 + 1] + off[p * 3 + 1];
    float dz = R[ja * 3 + 2] - R[ia * 3 + 2] + off[p * 3 + 2];
    float dr = sqrtf(dx * dx + dy * dy + dz * dz);
    if (!(dr < RMAXV)) return;

    float inv = 1.0f / (dr + 1e-5f);
    float dn0 = dx * inv, dn1 = dy * inv, dn2 = dz * inv;

    const float betta = 49.0f / 36.0f;
    const float rad_norm = 0.898112f;   // (2*betta/pi)^0.75
    float cut = 0.5f * (cosf(PI_F * dr * (1.0f / RMAXV)) + 1.0f);

    float basis[NB];
#pragma unroll
    for (int b = 0; b < NB; b++) {
        float t = dr - (0.5f + 0.91666666666666667f * (float)b);
        basis[b] = rad_norm * expf(-betta * t * t);
    }

    int zi = Z[ia], zj = Z[ja];
    const float* e = emb + (size_t)(zj * NSP + zi) * 35;
    float pref = 0.37796447300922720f * cut;
    float rad[5];
#pragma unroll
    for (int r = 0; r < 5; r++) {
        float s = 0.f;
#pragma unroll
        for (int b = 0; b < NB; b++) s += e[r * NB + b] * basis[b];
        rad[r] = pref * s;
    }

    float d2[6] = {dn0 * dn0, dn0 * dn1, dn0 * dn2, dn1 * dn1, dn1 * dn2, dn2 * dn2};
    float d3[10] = {d2[0] * dn0, d2[0] * dn1, d2[0] * dn2, d2[3] * dn0, d2[1] * dn2,
                    d2[5] * dn0, d2[3] * dn1, d2[3] * dn2, d2[5] * dn1, d2[5] * dn2};

    int pos = atomicAdd(&g_cur[ia], 1);
    float* pb = g_prod + (size_t)pos * 32;
    float4* pb4 = (float4*)pb;
    pb4[0] = make_float4(rad[0], rad[1], rad[2], rad[3]);
    pb4[1] = make_float4(rad[4], 1.0f, dn0, dn1);
    pb4[2] = make_float4(dn2, d2[0], d2[1], d2[2]);
    pb4[3] = make_float4(d2[3], d2[4], d2[5], d3[0]);
    pb4[4] = make_float4(d3[1], d3[2], d3[3], d3[4]);
    pb4[5] = make_float4(d3[5], d3[6], d3[7], d3[8]);
    pb[24] = d3[9];
}

// one warp per atom; lane c<25 accumulates components 4c..4c+3
__global__ void p2_kernel() {
    int gw = (blockIdx.x * blockDim.x + threadIdx.x) >> 5;
    int lane = threadIdx.x & 31;
    if (gw >= NA || lane >= 25) return;
    int beg = g_ofs[gw], end = g_ofs[gw + 1];
    int r = lane / 5, d0 = (4 * lane) % 20;
    float a0 = 0.f, a1 = 0.f, a2 = 0.f, a3 = 0.f;
    for (int s = beg; s < end; s++) {
        const float* pb = g_prod + (size_t)s * 32;
        float rv = __ldg(pb + r);
        a0 += rv * __ldg(pb + 5 + d0 + 0);
        a1 += rv * __ldg(pb + 5 + d0 + 1);
        a2 += rv * __ldg(pb + 5 + d0 + 2);
        a3 += rv * __ldg(pb + 5 + d0 + 3);
    }
    *(float4*)(g_M + (size_t)gw * 100 + 4 * lane) = make_float4(a0, a1, a2, a3);
}

// ---------------------------------------------------------------------------
// per-atom contractions -> 360 feats -> fp16 (hi,lo) rows of g_A1, pre-scaled
// ---------------------------------------------------------------------------
__device__ __forceinline__ void flush8(const float* fb, uint4* dst) {
    uint32_t pw[8];
#pragma unroll
    for (int e = 0; e < 8; e++) {
        uint32_t H, L;
        hsplit(fb[e] * IN_SCALE, H, L);
        pw[e] = H | (L << 16);
    }
    dst[0] = make_uint4(pw[0], pw[1], pw[2], pw[3]);
    dst[1] = make_uint4(pw[4], pw[5], pw[6], pw[7]);
}

#define M2F(r, x, y) m2[r][imap2((x), (y))]
#define M3F(r, x, y, z) m3[r][imap3((x), (y), (z))]

__global__ void __launch_bounds__(128) feat_kernel() {
    int a = blockIdx.x * blockDim.x + threadIdx.x;
    if (a >= NA) return;

    const float* v = g_M + (size_t)a * 100;
    float m0[5], m1[5][3], m2[5][6], m3[5][10];
#pragma unroll
    for (int r = 0; r < 5; r++) {
        m0[r] = v[r * 20];
#pragma unroll
        for (int i = 0; i < 3; i++) m1[r][i] = v[r * 20 + 1 + i];
#pragma unroll
        for (int q = 0; q < 6; q++) m2[r][q] = v[r * 20 + 4 + q];
#pragma unroll
        for (int q = 0; q < 10; q++) m3[r][q] = v[r * 20 + 10 + q];
    }

    const float w2[6] = {1.f, 2.f, 2.f, 1.f, 2.f, 1.f};
    const float w3[10] = {1.f, 3.f, 3.f, 3.f, 6.f, 3.f, 1.f, 3.f, 3.f, 1.f};

    char* rowb = (char*)g_A1 + (size_t)a * (KP1 * 2);
    float fb[8];
    int cnt = 0, pos = 0;
#define PUT(x) do { fb[cnt] = (x); \
    if (cnt == 7) { flush8(fb, (uint4*)(rowb + (size_t)(pos - 7) * 4)); cnt = 0; } else cnt++; \
    pos++; } while (0)

#pragma unroll
    for (int r = 0; r < 5; r++) PUT(m0[r]);

#pragma unroll
    for (int r = 0; r < 5; r++)
#pragma unroll
        for (int s = 0; s <= r; s++) {
            float acc = 0.f;
#pragma unroll
            for (int i = 0; i < 3; i++) acc += m1[r][i] * m1[s][i];
            PUT(acc);
        }

#pragma unroll
    for (int r = 0; r < 5; r++)
#pragma unroll
        for (int s = 0; s <= r; s++) {
            float acc = 0.f;
#pragma unroll
            for (int q = 0; q < 6; q++) acc += w2[q] * m2[r][q] * m2[s][q];
            PUT(acc);
        }

#pragma unroll
    for (int r = 0; r < 5; r++)
#pragma unroll
        for (int s = 0; s <= r; s++) {
            float acc = 0.f;
#pragma unroll
            for (int q = 0; q < 10; q++) acc += w3[q] * m3[r][q] * m3[s][q];
            PUT(acc);
        }

#pragma unroll
    for (int r = 0; r < 5; r++)
#pragma unroll
        for (int s = 0; s <= r; s++)
#pragma unroll
            for (int t = 0; t <= s; t++) {
                float acc = 0.f;
#pragma unroll
                for (int x = 0; x < 3; x++)
#pragma unroll
                    for (int y = 0; y < 3; y++)
#pragma unroll
                        for (int z = 0; z < 3; z++)
                            acc += M2F(r, x, y) * M2F(s, x, z) * M2F(t, y, z);
                PUT(acc);
            }

#pragma unroll
    for (int r = 0; r < 5; r++)
#pragma unroll
        for (int s = 0; s <= r; s++)
#pragma unroll
            for (int t = 0; t < 5; t++) {
                float acc = 0.f;
#pragma unroll
                for (int x = 0; x < 3; x++)
#pragma unroll
                    for (int y = 0; y < 3; y++)
                        acc += m1[r][x] * m1[s][y] * M2F(t, x, y);
                PUT(acc);
            }

#pragma unroll
    for (int r = 0; r < 5; r++)
#pragma unroll
        for (int s = 0; s <= r; s++) {
            float A[3][3];
#pragma unroll
            for (int k = 0; k < 3; k++)
#pragma unroll
                for (int l = 0; l < 3; l++) {
                    float acc = 0.f;
#pragma unroll
                    for (int x = 0; x < 3; x++)
#pragma unroll
                        for (int y = 0; y < 3; y++)
                            acc += M3F(r, x, y, k) * M3F(s, x, y, l);
                    A[k][l] = acc;
                }
#pragma unroll
            for (int t = 0; t < 5; t++) {
                float acc = 0.f;
#pragma unroll
                for (int k = 0; k < 3; k++)
#pragma unroll
                    for (int l = 0; l < 3; l++)
                        acc += A[k][l] * M2F(t, k, l);
                PUT(acc);
            }
        }

#pragma unroll
    for (int r = 0; r < 5; r++)
#pragma unroll
        for (int s = 0; s < 5; s++) {
            float B[3];
#pragma unroll
            for (int k = 0; k < 3; k++) {
                float acc = 0.f;
#pragma unroll
                for (int x = 0; x < 3; x++)
#pragma unroll
                    for (int y = 0; y < 3; y++)
                        acc += M3F(r, x, y, k) * M2F(s, x, y);
                B[k] = acc;
            }
#pragma unroll
            for (int t = 0; t < 5; t++)
                PUT(B[0] * m1[t][0] + B[1] * m1[t][1] + B[2] * m1[t][2]);
        }
#undef PUT
}

// ---------------------------------------------------------------------------
// weight prep: W[K][512] fp32 -> B[n][Kp] fp16 (hi,hi) replicated
// ---------------------------------------------------------------------------
__global__ void wprep_kernel(const float* __restrict__ W, __half* __restrict__ B,
                             int K, int Kp) {
    int idx = blockIdx.x * blockDim.x + threadIdx.x;
    if (idx >= K * 512) return;
    int k = idx >> 9, n = idx & 511;
    float w = W[(size_t)k * 512 + n];
    uint32_t h = (uint32_t)__half_as_ushort(__float2half(w));
    *(uint32_t*)((char*)B + (size_t)n * (Kp * 2) + 4 * k) = h | (h << 16);
}

// ---------------------------------------------------------------------------
// mma.sync fp16 GEMM: C[M,512] = act(A[M,Kp] @ B[512,Kp]^T * scale + 0.1*bias)
// block 128x128, warp 32x64 (8 warps), k-tile 32, 2-stage cp.async.
// mode 1: swish -> fp16 (hi,lo) rows scaled by 2^-8 (next layer A). mode 2: fp32.
// ---------------------------------------------------------------------------
#define STAGE 20480
#define BOFF  10240

__device__ __forceinline__ void load_stage(uint32_t sb, const char* Ab, const char* Bb,
                                           int m0, int bn, int ldab, int kt, int tid) {
    uint32_t st = (uint32_t)(kt & 1) * STAGE;
    int k0B = kt * 64;
#pragma unroll
    for (int i = 0; i < 2; i++) {
        int t = tid + i * 256;
        int row = t >> 2, ch = (t & 3) * 16;
        CP16(sb + st + (uint32_t)(row * 80 + ch),
             Ab + (size_t)(m0 + row) * ldab + k0B + ch);
    }
#pragma unroll
    for (int i = 0; i < 2; i++) {
        int t = tid + i * 256;
        int row = t >> 2, ch = (t & 3) * 16;
        CP16(sb + st + BOFF + (uint32_t)(row * 80 + ch),
             Bb + (size_t)(bn * 128 + row) * ldab + k0B + ch);
    }
    CP_COMMIT();
}

__global__ void __launch_bounds__(256) gemm_mma(
    const __half* __restrict__ A, const __half* __restrict__ B,
    const float* __restrict__ bias, char* __restrict__ Cout,
    int Kp, float scale, int mode) {
    __shared__ __align__(16) char smem[2 * STAGE];
    uint32_t sb = smem_u32(smem);

    const int tid = threadIdx.x, wid = tid >> 5, lane = tid & 31;
    const int wm = wid & 3, wn = wid >> 2;          // warp grid 4(m) x 2(n)
    const int bn = blockIdx.x, m0 = blockIdx.y * 128;
    const int ldab = Kp * 2;
    const int nk = Kp >> 5;

    const char* Ab = (const char*)A;
    const char* Bb = (const char*)B;

    float d[2][8][4];
#pragma unroll
    for (int i = 0; i < 2; i++)
#pragma unroll
        for (int j = 0; j < 8; j++)
#pragma unroll
            for (int q = 0; q < 4; q++) d[i][j][q] = 0.f;

    load_stage(sb, Ab, Bb, m0, bn, ldab, 0, tid);
    load_stage(sb, Ab, Bb, m0, bn, ldab, 1, tid);
    CP_WAIT(1);
    __syncthreads();

    const int lr = lane & 15, lc = lane >> 4;

    for (int kt = 0; kt < nk; kt++) {
        uint32_t sA = sb + (uint32_t)(kt & 1) * STAGE;
        uint32_t sBt = sA + BOFF;
#pragma unroll
        for (int h = 0; h < 2; h++) {
            uint32_t a[2][4];
#pragma unroll
            for (int mi = 0; mi < 2; mi++)
                ldm_x4(a[mi][0], a[mi][1], a[mi][2], a[mi][3],
                       sA + (uint32_t)((wm * 32 + mi * 16 + lr) * 80 + lc * 16 + h * 32));
            uint32_t b[8][2];
#pragma unroll
            for (int pi = 0; pi < 4; pi++) {
                uint32_t t0, t1, t2, t3;
                ldm_x4(t0, t1, t2, t3,
                       sBt + (uint32_t)((wn * 64 + pi * 16 + lr) * 80 + lc * 16 + h * 32));
                b[2 * pi][0] = t0; b[2 * pi][1] = t2;
                b[2 * pi + 1][0] = t1; b[2 * pi + 1][1] = t3;
            }
#pragma unroll
            for (int mi = 0; mi < 2; mi++)
#pragma unroll
                for (int ni = 0; ni < 8; ni++)
                    mma16816(d[mi][ni], a[mi], b[ni]);
        }
        __syncthreads();
        if (kt + 2 < nk) {
            load_stage(sb, Ab, Bb, m0, bn, ldab, kt + 2, tid);
            CP_WAIT(1);
        } else {
            CP_WAIT(0);
        }
        __syncthreads();
    }

    // epilogue
    const int g = lane >> 2, tg = lane & 3;
#pragma unroll
    for (int mi = 0; mi < 2; mi++) {
#pragma unroll
        for (int ni = 0; ni < 8; ni++) {
            int n = bn * 128 + wn * 64 + ni * 8 + 2 * tg;
            float bz0 = 0.1f * bias[n], bz1 = 0.1f * bias[n + 1];
#pragma unroll
            for (int half = 0; half < 2; half++) {
                int m = m0 + wm * 32 + mi * 16 + g + half * 8;
                if (m >= NA) continue;
                float v0 = d[mi][ni][2 * half + 0] * scale + bz0;
                float v1 = d[mi][ni][2 * half + 1] * scale + bz1;
                v0 = v0 / (1.0f + __expf(-v0));
                v1 = v1 / (1.0f + __expf(-v1));
                if (mode == 1) {
                    uint32_t H0, L0, H1, L1;
                    hsplit(v0 * IN_SCALE, H0, L0);
                    hsplit(v1 * IN_SCALE, H1, L1);
                    *(uint2*)(Cout + (size_t)m * (KP2 * 2) + (size_t)n * 4) =
                        make_uint2(H0 | (L0 << 16), H1 | (L1 << 16));
                } else {
                    *(float2*)((float*)Cout + (size_t)m * U + n) = make_float2(v0, v1);
                }
            }
        }
    }
}

// ---------------------------------------------------------------------------
// final GEMV + species mask
// ---------------------------------------------------------------------------
__global__ void out_kernel(const float* __restrict__ W3, const float* __restrict__ b3,
                           const int* __restrict__ Z, float* __restrict__ out) {
    int warp = (blockIdx.x * blockDim.x + threadIdx.x) >> 5;
    int lane = threadIdx.x & 31;
    if (warp >= NA) return;
    const float* h = g_h2 + (size_t)warp * U;
    float s = 0.f;
#pragma unroll
    for (int t = 0; t < U / 32; t++) s += h[lane + 32 * t] * W3[lane + 32 * t];
#pragma unroll
    for (int o = 16; o; o >>= 1) s += __shfl_xor_sync(0xffffffffu, s, o);
    if (lane == 0) {
        float v = s * 0.04419417382415922f + 0.1f * b3[0];
        out[warp] = (Z[warp] > 0) ? v : 0.0f;
    }
}

// ---------------------------------------------------------------------------
extern "C" void kernel_launch(void* const* d_in, const int* in_sizes, int n_in,
                              void* d_out, int out_size) {
    const float* R   = (const float*)d_in[0];
    const int*   Z   = (const int*)d_in[1];
    const int*   nbr = (const int*)d_in[2];
    const float* off = (const float*)d_in[4];
    const float* emb = (const float*)d_in[5];
    const float* W1  = (const float*)d_in[6];
    const float* b1  = (const float*)d_in[7];
    const float* W2  = (const float*)d_in[8];
    const float* b2  = (const float*)d_in[9];
    const float* W3  = (const float*)d_in[10];
    const float* b3  = (const float*)d_in[11];
    float* out = (float*)d_out;

    __half *pA1, *pB1, *pA2, *pB2;
    float* pH2;
    cudaGetSymbolAddress((void**)&pA1, g_A1);
    cudaGetSymbolAddress((void**)&pB1, g_B1);
    cudaGetSymbolAddress((void**)&pA2, g_A2);
    cudaGetSymbolAddress((void**)&pB2, g_B2);
    cudaGetSymbolAddress((void**)&pH2, g_h2);

    zc_kernel<<<(NA + 255) / 256, 256>>>();
    hist_kernel<<<(NP + 255) / 256, 256>>>(R, nbr, off);
    scan_kernel<<<1, 1024>>>();
    p1_kernel<<<(NP + 255) / 256, 256>>>(R, Z, nbr, off, emb);
    p2_kernel<<<(NA * 32 + 255) / 256, 256>>>();
    feat_kernel<<<(NA + 127) / 128, 128>>>();
    wprep_kernel<<<(360 * 512 + 255) / 256, 256>>>(W1, pB1, 360, KP1);
    wprep_kernel<<<(512 * 512 + 255) / 256, 256>>>(W2, pB2, 512, KP2);

    const float s1 = 256.0f * 0.05270462766947299f;  // 2^8 / sqrt(360)
    const float s2 = 256.0f * 0.04419417382415922f;  // 2^8 / sqrt(512)

    dim3 g(4, NAP / 128);
    gemm_mma<<<g, 256>>>(pA1, pB1, b1, (char*)pA2, KP1, s1, 1);
    gemm_mma<<<g, 256>>>(pA2, pB2, b2, (char*)pH2, KP2, s2, 2);

    out_kernel<<<(NA * 32 + 255) / 256, 256>>>(W3, b3, Z, out);
}

// round 5
// speedup vs baseline: 2.1288x; 1.0072x over previous
#include <cuda_runtime.h>
#include <cuda_fp16.h>
#include <math.h>
#include <stdint.h>

#define NA 20000
#define NAP 20096           // padded rows (157*128)
#define NP 800000
#define NSP 119
#define NB 7
#define RMAXV 6.0f
#define PI_F 3.14159265358979323846f

#define KP1 736             // 2*360 padded to 32-element k-tiles
#define KP2 1024            // 2*512
#define U 512
#define IN_SCALE 0.00390625f   // 2^-8 applied to GEMM A inputs

// ---------------------------------------------------------------------------
// device scratch (static; zero at module load)
// ---------------------------------------------------------------------------
__device__ int   g_cnt[NA];
__device__ int   g_ofs[NA + 1];
__device__ int   g_cur[NA];
__device__ float g_outacc[NA];
__device__ float g_prod[(size_t)NP * 32];        // per active pair: rad[5]+D[20]
__device__ float g_M[(size_t)NA * 100];          // [atom][100] moments
__device__ __half g_A1[(size_t)NAP * KP1];       // feats (scaled), fp16 hi/lo
__device__ __half g_B1[(size_t)U * KP1];         // W1^T fp16 (hi,hi)
__device__ __half g_A2[(size_t)NAP * KP2];       // h1 (scaled), fp16 hi/lo
__device__ __half g_B2[(size_t)U * KP2];         // W2^T fp16 (hi,hi)

// ---------------------------------------------------------------------------
// helpers
// ---------------------------------------------------------------------------
__device__ __forceinline__ uint32_t smem_u32(const void* p) {
    uint32_t a;
    asm("{ .reg .u64 t; cvta.to.shared.u64 t, %1; cvt.u32.u64 %0, t; }" : "=r"(a) : "l"(p));
    return a;
}
#define CP16(dst, src)   asm volatile("cp.async.cg.shared.global [%0], [%1], 16;" :: "r"(dst), "l"(src))
#define CP_COMMIT()      asm volatile("cp.async.commit_group;" ::: "memory")
#define CP_WAIT(n)       asm volatile("cp.async.wait_group %0;" :: "n"(n) : "memory")

__device__ __forceinline__ void ldm_x4(uint32_t& r0, uint32_t& r1, uint32_t& r2, uint32_t& r3,
                                       uint32_t addr) {
    asm volatile("ldmatrix.sync.aligned.m8n8.x4.shared.b16 {%0,%1,%2,%3}, [%4];"
                 : "=r"(r0), "=r"(r1), "=r"(r2), "=r"(r3) : "r"(addr));
}
__device__ __forceinline__ void mma16816(float* d, const uint32_t* a, const uint32_t* b) {
    asm volatile("mma.sync.aligned.m16n8k16.row.col.f32.f16.f16.f32 "
                 "{%0,%1,%2,%3}, {%4,%5,%6,%7}, {%8,%9}, {%0,%1,%2,%3};"
                 : "+f"(d[0]), "+f"(d[1]), "+f"(d[2]), "+f"(d[3])
                 : "r"(a[0]), "r"(a[1]), "r"(a[2]), "r"(a[3]), "r"(b[0]), "r"(b[1]));
}
__device__ __forceinline__ void redf(float* p, float v) {
    asm volatile("red.global.add.f32 [%0], %1;" :: "l"(p), "f"(v) : "memory");
}

// fp16 hi/lo split (input assumed pre-scaled into fp16 range)
__device__ __forceinline__ void hsplit(float v, uint32_t& h, uint32_t& l) {
    __half hb = __float2half(v);
    float r = v - __half2float(hb);
    __half lb = __float2half(r);
    h = (uint32_t)__half_as_ushort(hb);
    l = (uint32_t)__half_as_ushort(lb);
}

// symmetric index maps (compile-time folded)
__device__ __forceinline__ int imap2(int a, int b) {
    int i = a < b ? a : b, j = a < b ? b : a;
    return (i == 0) ? j : ((i == 1) ? (2 + j) : 5);
}
__device__ __forceinline__ int imap3(int a, int b, int c) {
    int i = a, j = b, k = c, t;
    if (i > j) { t = i; i = j; j = t; }
    if (j > k) { t = j; j = k; k = t; }
    if (i > j) { t = i; i = j; j = t; }
    if (i == 0) return imap2(j, k);
    if (i == 1) return (j == 1) ? (5 + k) : 8;
    return 9;
}

// ---------------------------------------------------------------------------
// pair pipeline: zero -> histogram -> scan -> phase1 -> phase2
// ---------------------------------------------------------------------------
__global__ void zc_kernel() {
    int i = blockIdx.x * blockDim.x + threadIdx.x;
    if (i < NA) {
        g_cnt[i] = 0;
        g_outacc[i] = 0.f;
    }
}

__global__ void hist_kernel(const float* __restrict__ R, const int* __restrict__ nbr,
                            const float* __restrict__ off) {
    int p = blockIdx.x * blockDim.x + threadIdx.x;
    if (p >= NP) return;
    int ia = nbr[p], ja = nbr[NP + p];
    float dx = R[ja * 3 + 0] - R[ia * 3 + 0] + off[p * 3 + 0];
    float dy = R[ja * 3 + 1] - R[ia * 3 + 1] + off[p * 3 + 1];
    float dz = R[ja * 3 + 2] - R[ia * 3 + 2] + off[p * 3 + 2];
    float dr = sqrtf(dx * dx + dy * dy + dz * dz);
    if (dr < RMAXV) atomicAdd(&g_cnt[ia], 1);
}

__global__ void __launch_bounds__(1024) scan_kernel() {
    __shared__ int part[1024];
    int t = threadIdx.x;
    int b0 = t * 20;
    int b1 = b0 + 20 < NA ? b0 + 20 : NA;
    int s = 0;
    for (int b = b0; b < b1; b++) s += g_cnt[b];
    part[t] = s;
    __syncthreads();
    for (int o = 1; o < 1024; o <<= 1) {
        int v = (t >= o) ? part[t - o] : 0;
        __syncthreads();
        part[t] += v;
        __syncthreads();
    }
    int run = (t == 0) ? 0 : part[t - 1];
    for (int b = b0; b < b1; b++) {
        g_ofs[b] = run;
        g_cur[b] = run;
        run += g_cnt[b];
    }
    if (t == 1023) g_ofs[NA] = run;
}

__global__ void p1_kernel(const float* __restrict__ R, const int* __restrict__ Z,
                          const int* __restrict__ nbr, const float* __restrict__ off,
                          const float* __restrict__ emb) {
    int p = blockIdx.x * blockDim.x + threadIdx.x;
    if (p >= NP) return;
    int ia = nbr[p], ja = nbr[NP + p];

    float dx = R[ja * 3 + 0] - R[ia * 3 + 0] + off[p * 3 + 0];
    float dy = R[ja * 3 + 1] - R[ia * 3 + 1] + off[p * 3 + 1];
    float dz = R[ja * 3 + 2] - R[ia * 3 + 2] + off[p * 3 + 2];
    float dr = sqrtf(dx * dx + dy * dy + dz * dz);
    if (!(dr < RMAXV)) return;

    float inv = 1.0f / (dr + 1e-5f);
    float dn0 = dx * inv, dn1 = dy * inv, dn2 = dz * inv;

    const float betta = 49.0f / 36.0f;
    const float rad_norm = 0.898112f;   // (2*betta/pi)^0.75
    float cut = 0.5f * (cosf(PI_F * dr * (1.0f / RMAXV)) + 1.0f);

    float basis[NB];
#pragma unroll
    for (int b = 0; b < NB; b++) {
        float t = dr - (0.5f + 0.91666666666666667f * (float)b);
        basis[b] = rad_norm * expf(-betta * t * t);
    }

    int zi = Z[ia], zj = Z[ja];
    const float* e = emb + (size_t)(zj * NSP + zi) * 35;
    float pref = 0.37796447300922720f * cut;
    float rad[5];
#pragma unroll
    for (int r = 0; r < 5; r++) {
        float s = 0.f;
#pragma unroll
        for (int b = 0; b < NB; b++) s += e[r * NB + b] * basis[b];
        rad[r] = pref * s;
    }

    float d2[6] = {dn0 * dn0, dn0 * dn1, dn0 * dn2, dn1 * dn1, dn1 * dn2, dn2 * dn2};
    float d3[10] = {d2[0] * dn0, d2[0] * dn1, d2[0] * dn2, d2[3] * dn0, d2[1] * dn2,
                    d2[5] * dn0, d2[3] * dn1, d2[3] * dn2, d2[5] * dn1, d2[5] * dn2};

    int pos = atomicAdd(&g_cur[ia], 1);
    float* pb = g_prod + (size_t)pos * 32;
    float4* pb4 = (float4*)pb;
    pb4[0] = make_float4(rad[0], rad[1], rad[2], rad[3]);
    pb4[1] = make_float4(rad[4], 1.0f, dn0, dn1);
    pb4[2] = make_float4(dn2, d2[0], d2[1], d2[2]);
    pb4[3] = make_float4(d2[3], d2[4], d2[5], d3[0]);
    pb4[4] = make_float4(d3[1], d3[2], d3[3], d3[4]);
    pb4[5] = make_float4(d3[5], d3[6], d3[7], d3[8]);
    pb[24] = d3[9];
}

// one warp per atom; lane c<25 accumulates components 4c..4c+3
__global__ void p2_kernel() {
    int gw = (blockIdx.x * blockDim.x + threadIdx.x) >> 5;
    int lane = threadIdx.x & 31;
    if (gw >= NA || lane >= 25) return;
    int beg = g_ofs[gw], end = g_ofs[gw + 1];
    int r = lane / 5, d0 = (4 * lane) % 20;
    float a0 = 0.f, a1 = 0.f, a2 = 0.f, a3 = 0.f;
    for (int s = beg; s < end; s++) {
        const float* pb = g_prod + (size_t)s * 32;
        float rv = __ldg(pb + r);
        a0 += rv * __ldg(pb + 5 + d0 + 0);
        a1 += rv * __ldg(pb + 5 + d0 + 1);
        a2 += rv * __ldg(pb + 5 + d0 + 2);
        a3 += rv * __ldg(pb + 5 + d0 + 3);
    }
    *(float4*)(g_M + (size_t)gw * 100 + 4 * lane) = make_float4(a0, a1, a2, a3);
}

// ---------------------------------------------------------------------------
// per-atom contractions -> 360 feats -> fp16 (hi,lo) rows of g_A1, pre-scaled
// ---------------------------------------------------------------------------
__device__ __forceinline__ void flush8(const float* fb, uint4* dst) {
    uint32_t pw[8];
#pragma unroll
    for (int e = 0; e < 8; e++) {
        uint32_t H, L;
        hsplit(fb[e] * IN_SCALE, H, L);
        pw[e] = H | (L << 16);
    }
    dst[0] = make_uint4(pw[0], pw[1], pw[2], pw[3]);
    dst[1] = make_uint4(pw[4], pw[5], pw[6], pw[7]);
}

#define M2F(r, x, y) m2[r][imap2((x), (y))]
#define M3F(r, x, y, z) m3[r][imap3((x), (y), (z))]

__global__ void __launch_bounds__(128) feat_kernel() {
    int a = blockIdx.x * blockDim.x + threadIdx.x;
    if (a >= NA) return;

    const float* v = g_M + (size_t)a * 100;
    float m0[5], m1[5][3], m2[5][6], m3[5][10];
#pragma unroll
    for (int r = 0; r < 5; r++) {
        m0[r] = v[r * 20];
#pragma unroll
        for (int i = 0; i < 3; i++) m1[r][i] = v[r * 20 + 1 + i];
#pragma unroll
        for (int q = 0; q < 6; q++) m2[r][q] = v[r * 20 + 4 + q];
#pragma unroll
        for (int q = 0; q < 10; q++) m3[r][q] = v[r * 20 + 10 + q];
    }

    const float w2[6] = {1.f, 2.f, 2.f, 1.f, 2.f, 1.f};
    const float w3[10] = {1.f, 3.f, 3.f, 3.f, 6.f, 3.f, 1.f, 3.f, 3.f, 1.f};

    char* rowb = (char*)g_A1 + (size_t)a * (KP1 * 2);
    float fb[8];
    int cnt = 0, pos = 0;
#define PUT(x) do { fb[cnt] = (x); \
    if (cnt == 7) { flush8(fb, (uint4*)(rowb + (size_t)(pos - 7) * 4)); cnt = 0; } else cnt++; \
    pos++; } while (0)

#pragma unroll
    for (int r = 0; r < 5; r++) PUT(m0[r]);

#pragma unroll
    for (int r = 0; r < 5; r++)
#pragma unroll
        for (int s = 0; s <= r; s++) {
            float acc = 0.f;
#pragma unroll
            for (int i = 0; i < 3; i++) acc += m1[r][i] * m1[s][i];
            PUT(acc);
        }

#pragma unroll
    for (int r = 0; r < 5; r++)
#pragma unroll
        for (int s = 0; s <= r; s++) {
            float acc = 0.f;
#pragma unroll
            for (int q = 0; q < 6; q++) acc += w2[q] * m2[r][q] * m2[s][q];
            PUT(acc);
        }

#pragma unroll
    for (int r = 0; r < 5; r++)
#pragma unroll
        for (int s = 0; s <= r; s++) {
            float acc = 0.f;
#pragma unroll
            for (int q = 0; q < 10; q++) acc += w3[q] * m3[r][q] * m3[s][q];
            PUT(acc);
        }

#pragma unroll
    for (int r = 0; r < 5; r++)
#pragma unroll
        for (int s = 0; s <= r; s++)
#pragma unroll
            for (int t = 0; t <= s; t++) {
                float acc = 0.f;
#pragma unroll
                for (int x = 0; x < 3; x++)
#pragma unroll
                    for (int y = 0; y < 3; y++)
#pragma unroll
                        for (int z = 0; z < 3; z++)
                            acc += M2F(r, x, y) * M2F(s, x, z) * M2F(t, y, z);
                PUT(acc);
            }

#pragma unroll
    for (int r = 0; r < 5; r++)
#pragma unroll
        for (int s = 0; s <= r; s++)
#pragma unroll
            for (int t = 0; t < 5; t++) {
                float acc = 0.f;
#pragma unroll
                for (int x = 0; x < 3; x++)
#pragma unroll
                    for (int y = 0; y < 3; y++)
                        acc += m1[r][x] * m1[s][y] * M2F(t, x, y);
                PUT(acc);
            }

#pragma unroll
    for (int r = 0; r < 5; r++)
#pragma unroll
        for (int s = 0; s <= r; s++) {
            float A[3][3];
#pragma unroll
            for (int k = 0; k < 3; k++)
#pragma unroll
                for (int l = 0; l < 3; l++) {
                    float acc = 0.f;
#pragma unroll
                    for (int x = 0; x < 3; x++)
#pragma unroll
                        for (int y = 0; y < 3; y++)
                            acc += M3F(r, x, y, k) * M3F(s, x, y, l);
                    A[k][l] = acc;
                }
#pragma unroll
            for (int t = 0; t < 5; t++) {
                float acc = 0.f;
#pragma unroll
                for (int k = 0; k < 3; k++)
#pragma unroll
                    for (int l = 0; l < 3; l++)
                        acc += A[k][l] * M2F(t, k, l);
                PUT(acc);
            }
        }

#pragma unroll
    for (int r = 0; r < 5; r++)
#pragma unroll
        for (int s = 0; s < 5; s++) {
            float B[3];
#pragma unroll
            for (int k = 0; k < 3; k++) {
                float acc = 0.f;
#pragma unroll
                for (int x = 0; x < 3; x++)
#pragma unroll
                    for (int y = 0; y < 3; y++)
                        acc += M3F(r, x, y, k) * M2F(s, x, y);
                B[k] = acc;
            }
#pragma unroll
            for (int t = 0; t < 5; t++)
                PUT(B[0] * m1[t][0] + B[1] * m1[t][1] + B[2] * m1[t][2]);
        }
#undef PUT
}

// ---------------------------------------------------------------------------
// weight prep: W[K][512] fp32 -> B[n][Kp] fp16 (hi,hi) replicated
// ---------------------------------------------------------------------------
__global__ void wprep_kernel(const float* __restrict__ W, __half* __restrict__ B,
                             int K, int Kp) {
    int idx = blockIdx.x * blockDim.x + threadIdx.x;
    if (idx >= K * 512) return;
    int k = idx >> 9, n = idx & 511;
    float w = W[(size_t)k * 512 + n];
    uint32_t h = (uint32_t)__half_as_ushort(__float2half(w));
    *(uint32_t*)((char*)B + (size_t)n * (Kp * 2) + 4 * k) = h | (h << 16);
}

// ---------------------------------------------------------------------------
// mma.sync fp16 GEMM, 3-stage cp.async pipeline.
// mode 1: swish -> fp16 (hi,lo) rows scaled 2^-8 (next layer A)
// mode 2: swish -> fused GEMV vs W3, REDG partials into g_outacc
// ---------------------------------------------------------------------------
#define STAGE 20480
#define BOFF  10240
#define GSMEM (3 * STAGE)

__device__ __forceinline__ void load_stage(uint32_t sb, const char* Ab, const char* Bb,
                                           int m0, int bn, int ldab, int kt, int tid) {
    uint32_t st = (uint32_t)(kt % 3) * STAGE;
    int k0B = kt * 64;
#pragma unroll
    for (int i = 0; i < 2; i++) {
        int t = tid + i * 256;
        int row = t >> 2, ch = (t & 3) * 16;
        CP16(sb + st + (uint32_t)(row * 80 + ch),
             Ab + (size_t)(m0 + row) * ldab + k0B + ch);
    }
#pragma unroll
    for (int i = 0; i < 2; i++) {
        int t = tid + i * 256;
        int row = t >> 2, ch = (t & 3) * 16;
        CP16(sb + st + BOFF + (uint32_t)(row * 80 + ch),
             Bb + (size_t)(bn * 128 + row) * ldab + k0B + ch);
    }
    CP_COMMIT();
}

__global__ void __launch_bounds__(256, 2) gemm_mma(
    const __half* __restrict__ A, const __half* __restrict__ B,
    const float* __restrict__ bias, const float* __restrict__ W3,
    char* __restrict__ Cout, int Kp, float scale, int mode) {
    extern __shared__ __align__(16) char smem[];
    uint32_t sb = smem_u32(smem);

    const int tid = threadIdx.x, wid = tid >> 5, lane = tid & 31;
    const int wm = wid & 3, wn = wid >> 2;          // warp grid 4(m) x 2(n)
    const int bn = blockIdx.x, m0 = blockIdx.y * 128;
    const int ldab = Kp * 2;
    const int nk = Kp >> 5;

    const char* Ab = (const char*)A;
    const char* Bb = (const char*)B;

    float d[2][8][4];
#pragma unroll
    for (int i = 0; i < 2; i++)
#pragma unroll
        for (int j = 0; j < 8; j++)
#pragma unroll
            for (int q = 0; q < 4; q++) d[i][j][q] = 0.f;

    load_stage(sb, Ab, Bb, m0, bn, ldab, 0, tid);
    load_stage(sb, Ab, Bb, m0, bn, ldab, 1, tid);
    load_stage(sb, Ab, Bb, m0, bn, ldab, 2, tid);

    const int lr = lane & 15, lc = lane >> 4;

    for (int kt = 0; kt < nk; kt++) {
        CP_WAIT(2);
        __syncthreads();
        uint32_t sA = sb + (uint32_t)(kt % 3) * STAGE;
        uint32_t sBt = sA + BOFF;
#pragma unroll
        for (int h = 0; h < 2; h++) {
            uint32_t a[2][4];
#pragma unroll
            for (int mi = 0; mi < 2; mi++)
                ldm_x4(a[mi][0], a[mi][1], a[mi][2], a[mi][3],
                       sA + (uint32_t)((wm * 32 + mi * 16 + lr) * 80 + lc * 16 + h * 32));
            uint32_t b[8][2];
#pragma unroll
            for (int pi = 0; pi < 4; pi++) {
                uint32_t t0, t1, t2, t3;
                ldm_x4(t0, t1, t2, t3,
                       sBt + (uint32_t)((wn * 64 + pi * 16 + lr) * 80 + lc * 16 + h * 32));
                b[2 * pi][0] = t0; b[2 * pi][1] = t2;
                b[2 * pi + 1][0] = t1; b[2 * pi + 1][1] = t3;
            }
#pragma unroll
            for (int mi = 0; mi < 2; mi++)
#pragma unroll
                for (int ni = 0; ni < 8; ni++)
                    mma16816(d[mi][ni], a[mi], b[ni]);
        }
        __syncthreads();
        if (kt + 3 < nk) load_stage(sb, Ab, Bb, m0, bn, ldab, kt + 3, tid);
        else CP_COMMIT();
    }

    // epilogue
    const int g = lane >> 2, tg = lane & 3;
    float oacc[2][2] = {{0.f, 0.f}, {0.f, 0.f}};
#pragma unroll
    for (int mi = 0; mi < 2; mi++) {
#pragma unroll
        for (int ni = 0; ni < 8; ni++) {
            int n = bn * 128 + wn * 64 + ni * 8 + 2 * tg;
            float bz0 = 0.1f * bias[n], bz1 = 0.1f * bias[n + 1];
            float w30 = 0.f, w31 = 0.f;
            if (mode == 2) { w30 = W3[n]; w31 = W3[n + 1]; }
#pragma unroll
            for (int half = 0; half < 2; half++) {
                int m = m0 + wm * 32 + mi * 16 + g + half * 8;
                float v0 = d[mi][ni][2 * half + 0] * scale + bz0;
                float v1 = d[mi][ni][2 * half + 1] * scale + bz1;
                v0 = v0 / (1.0f + __expf(-v0));
                v1 = v1 / (1.0f + __expf(-v1));
                if (mode == 1) {
                    if (m < NA) {
                        uint32_t H0, L0, H1, L1;
                        hsplit(v0 * IN_SCALE, H0, L0);
                        hsplit(v1 * IN_SCALE, H1, L1);
                        *(uint2*)(Cout + (size_t)m * (KP2 * 2) + (size_t)n * 4) =
                            make_uint2(H0 | (L0 << 16), H1 | (L1 << 16));
                    }
                } else {
                    oacc[mi][half] += v0 * w30 + v1 * w31;
                }
            }
        }
    }
    if (mode == 2) {
#pragma unroll
        for (int mi = 0; mi < 2; mi++)
#pragma unroll
            for (int half = 0; half < 2; half++) {
                float s = oacc[mi][half];
                s += __shfl_xor_sync(0xffffffffu, s, 1);
                s += __shfl_xor_sync(0xffffffffu, s, 2);
                if (tg == 0) {
                    int m = m0 + wm * 32 + mi * 16 + g + half * 8;
                    if (m < NA) redf(&g_outacc[m], s);
                }
            }
    }
}

// ---------------------------------------------------------------------------
// finalize: out = mask * (acc / sqrt(512) + 0.1*b3)
// ---------------------------------------------------------------------------
__global__ void fin_kernel(const float* __restrict__ b3, const int* __restrict__ Z,
                           float* __restrict__ out) {
    int i = blockIdx.x * blockDim.x + threadIdx.x;
    if (i >= NA) return;
    float v = g_outacc[i] * 0.04419417382415922f + 0.1f * b3[0];
    out[i] = (Z[i] > 0) ? v : 0.0f;
}

// ---------------------------------------------------------------------------
extern "C" void kernel_launch(void* const* d_in, const int* in_sizes, int n_in,
                              void* d_out, int out_size) {
    const float* R   = (const float*)d_in[0];
    const int*   Z   = (const int*)d_in[1];
    const int*   nbr = (const int*)d_in[2];
    const float* off = (const float*)d_in[4];
    const float* emb = (const float*)d_in[5];
    const float* W1  = (const float*)d_in[6];
    const float* b1  = (const float*)d_in[7];
    const float* W2  = (const float*)d_in[8];
    const float* b2  = (const float*)d_in[9];
    const float* W3  = (const float*)d_in[10];
    const float* b3  = (const float*)d_in[11];
    float* out = (float*)d_out;

    cudaFuncSetAttribute(gemm_mma, cudaFuncAttributeMaxDynamicSharedMemorySize, GSMEM);

    __half *pA1, *pB1, *pA2, *pB2;
    cudaGetSymbolAddress((void**)&pA1, g_A1);
    cudaGetSymbolAddress((void**)&pB1, g_B1);
    cudaGetSymbolAddress((void**)&pA2, g_A2);
    cudaGetSymbolAddress((void**)&pB2, g_B2);

    zc_kernel<<<(NA + 255) / 256, 256>>>();
    hist_kernel<<<(NP + 255) / 256, 256>>>(R, nbr, off);
    scan_kernel<<<1, 1024>>>();
    p1_kernel<<<(NP + 255) / 256, 256>>>(R, Z, nbr, off, emb);
    p2_kernel<<<(NA * 32 + 255) / 256, 256>>>();
    feat_kernel<<<(NA + 127) / 128, 128>>>();
    wprep_kernel<<<(360 * 512 + 255) / 256, 256>>>(W1, pB1, 360, KP1);
    wprep_kernel<<<(512 * 512 + 255) / 256, 256>>>(W2, pB2, 512, KP2);

    const float s1 = 256.0f * 0.05270462766947299f;  // 2^8 / sqrt(360)
    const float s2 = 256.0f * 0.04419417382415922f;  // 2^8 / sqrt(512)

    dim3 g(4, NAP / 128);
    gemm_mma<<<g, 256, GSMEM>>>(pA1, pB1, b1, nullptr, (char*)pA2, KP1, s1, 1);
    gemm_mma<<<g, 256, GSMEM>>>(pA2, pB2, b2, W3, nullptr, KP2, s2, 2);

    fin_kernel<<<(NA + 255) / 256, 256>>>(b3, Z, out);
}

// round 6
// speedup vs baseline: 2.5305x; 1.1887x over previous
#include <cuda_runtime.h>
#include <cuda_fp16.h>
#include <math.h>
#include <stdint.h>

#define NA 20000
#define NAP 20096           // padded rows (157*128)
#define NP 800000
#define NSP 119
#define NB 7
#define RMAXV 6.0f
#define PI_F 3.14159265358979323846f
#define CAP 64              // per-atom neighbor capacity (lambda~15, P(>=64)~1e-20)

#define KP1 736             // 2*360 padded to 32-element k-tiles
#define KP2 1024            // 2*512
#define U 512
#define IN_SCALE 0.00390625f   // 2^-8 applied to GEMM A inputs

// ---------------------------------------------------------------------------
// device scratch (static; zero at module load)
// ---------------------------------------------------------------------------
__device__ int   g_cur[NA];
__device__ float g_outacc[NA];
__device__ float g_prod[(size_t)NA * CAP * 8];   // per active pair: rad[5]+dn[3]
__device__ float g_M[(size_t)NA * 100];          // [atom][100] moments
__device__ __half g_A1[(size_t)NAP * KP1];       // feats (scaled), fp16 hi/lo
__device__ __half g_B1[(size_t)U * KP1];         // W1^T fp16 (hi,hi)
__device__ __half g_A2[(size_t)NAP * KP2];       // h1 (scaled), fp16 hi/lo
__device__ __half g_B2[(size_t)U * KP2];         // W2^T fp16 (hi,hi)

// ---------------------------------------------------------------------------
// helpers
// ---------------------------------------------------------------------------
__device__ __forceinline__ uint32_t smem_u32(const void* p) {
    uint32_t a;
    asm("{ .reg .u64 t; cvta.to.shared.u64 t, %1; cvt.u32.u64 %0, t; }" : "=r"(a) : "l"(p));
    return a;
}
#define CP16(dst, src)   asm volatile("cp.async.cg.shared.global [%0], [%1], 16;" :: "r"(dst), "l"(src))
#define CP_COMMIT()      asm volatile("cp.async.commit_group;" ::: "memory")
#define CP_WAIT(n)       asm volatile("cp.async.wait_group %0;" :: "n"(n) : "memory")

__device__ __forceinline__ void ldm_x4(uint32_t& r0, uint32_t& r1, uint32_t& r2, uint32_t& r3,
                                       uint32_t addr) {
    asm volatile("ldmatrix.sync.aligned.m8n8.x4.shared.b16 {%0,%1,%2,%3}, [%4];"
                 : "=r"(r0), "=r"(r1), "=r"(r2), "=r"(r3) : "r"(addr));
}
__device__ __forceinline__ void mma16816(float* d, const uint32_t* a, const uint32_t* b) {
    asm volatile("mma.sync.aligned.m16n8k16.row.col.f32.f16.f16.f32 "
                 "{%0,%1,%2,%3}, {%4,%5,%6,%7}, {%8,%9}, {%0,%1,%2,%3};"
                 : "+f"(d[0]), "+f"(d[1]), "+f"(d[2]), "+f"(d[3])
                 : "r"(a[0]), "r"(a[1]), "r"(a[2]), "r"(a[3]), "r"(b[0]), "r"(b[1]));
}
__device__ __forceinline__ void redf(float* p, float v) {
    asm volatile("red.global.add.f32 [%0], %1;" :: "l"(p), "f"(v) : "memory");
}

// fp16 hi/lo split (input assumed pre-scaled into fp16 range)
__device__ __forceinline__ void hsplit(float v, uint32_t& h, uint32_t& l) {
    __half hb = __float2half(v);
    float r = v - __half2float(hb);
    __half lb = __float2half(r);
    h = (uint32_t)__half_as_ushort(hb);
    l = (uint32_t)__half_as_ushort(lb);
}

// symmetric index maps (compile-time folded)
__device__ __forceinline__ int imap2(int a, int b) {
    int i = a < b ? a : b, j = a < b ? b : a;
    return (i == 0) ? j : ((i == 1) ? (2 + j) : 5);
}
__device__ __forceinline__ int imap3(int a, int b, int c) {
    int i = a, j = b, k = c, t;
    if (i > j) { t = i; i = j; j = t; }
    if (j > k) { t = j; j = k; k = t; }
    if (i > j) { t = i; i = j; j = t; }
    if (i == 0) return imap2(j, k);
    if (i == 1) return (j == 1) ? (5 + k) : 8;
    return 9;
}

// ---------------------------------------------------------------------------
__global__ void zc_kernel() {
    int i = blockIdx.x * blockDim.x + threadIdx.x;
    if (i < NA) {
        g_cur[i] = 0;
        g_outacc[i] = 0.f;
    }
}

// ---------------------------------------------------------------------------
// p1: per active pair compute rad[5]+dn[3], place into atom bucket (32B record)
// ---------------------------------------------------------------------------
__global__ void p1_kernel(const float* __restrict__ R, const int* __restrict__ Z,
                          const int* __restrict__ nbr, const float* __restrict__ off,
                          const float* __restrict__ emb) {
    int p = blockIdx.x * blockDim.x + threadIdx.x;
    if (p >= NP) return;
    int ia = nbr[p], ja = nbr[NP + p];

    float dx = R[ja * 3 + 0] - R[ia * 3 + 0] + off[p * 3 + 0];
    float dy = R[ja * 3 + 1] - R[ia * 3 + 1] + off[p * 3 + 1];
    float dz = R[ja * 3 + 2] - R[ia * 3 + 2] + off[p * 3 + 2];
    float dr = sqrtf(dx * dx + dy * dy + dz * dz);
    if (!(dr < RMAXV)) return;

    float inv = 1.0f / (dr + 1e-5f);
    float dn0 = dx * inv, dn1 = dy * inv, dn2 = dz * inv;

    const float betta = 49.0f / 36.0f;
    const float rad_norm = 0.898112f;   // (2*betta/pi)^0.75
    float cut = 0.5f * (cosf(PI_F * dr * (1.0f / RMAXV)) + 1.0f);

    float basis[NB];
#pragma unroll
    for (int b = 0; b < NB; b++) {
        float t = dr - (0.5f + 0.91666666666666667f * (float)b);
        basis[b] = rad_norm * expf(-betta * t * t);
    }

    int zi = Z[ia], zj = Z[ja];
    const float* e = emb + (size_t)(zj * NSP + zi) * 35;
    float pref = 0.37796447300922720f * cut;
    float rad[5];
#pragma unroll
    for (int r = 0; r < 5; r++) {
        float s = 0.f;
#pragma unroll
        for (int b = 0; b < NB; b++) s += e[r * NB + b] * basis[b];
        rad[r] = pref * s;
    }

    int slot = atomicAdd(&g_cur[ia], 1);
    if (slot >= CAP) return;   // statistically impossible (P ~ 1e-20)
    float* pb = g_prod + ((size_t)ia * CAP + slot) * 8;
    ((float4*)pb)[0] = make_float4(rad[0], rad[1], rad[2], rad[3]);
    ((float4*)pb)[1] = make_float4(rad[4], dn0, dn1, dn2);
}

// ---------------------------------------------------------------------------
// p2: 5 threads per atom (one radial channel each); expand monomials on the fly
// ---------------------------------------------------------------------------
__global__ void __launch_bounds__(128) p2_kernel() {
    int t = blockIdx.x * blockDim.x + threadIdx.x;
    if (t >= NA * 5) return;
    int a = t / 5, r = t - a * 5;
    int n = g_cur[a];
    if (n > CAP) n = CAP;
    const float* base = g_prod + (size_t)a * CAP * 8;

    float acc[20];
#pragma unroll
    for (int j = 0; j < 20; j++) acc[j] = 0.f;

    for (int s = 0; s < n; s++) {
        float rv = __ldg(base + s * 8 + r);
        float4 v = __ldg((const float4*)(base + s * 8 + 4));
        float dn0 = v.y, dn1 = v.z, dn2 = v.w;
        float q00 = dn0 * dn0, q01 = dn0 * dn1, q02 = dn0 * dn2;
        float q11 = dn1 * dn1, q12 = dn1 * dn2, q22 = dn2 * dn2;
        acc[0] += rv;
        acc[1] += rv * dn0;  acc[2] += rv * dn1;  acc[3] += rv * dn2;
        acc[4] += rv * q00;  acc[5] += rv * q01;  acc[6] += rv * q02;
        acc[7] += rv * q11;  acc[8] += rv * q12;  acc[9] += rv * q22;
        acc[10] += rv * q00 * dn0;  acc[11] += rv * q00 * dn1;  acc[12] += rv * q00 * dn2;
        acc[13] += rv * q11 * dn0;  acc[14] += rv * q01 * dn2;  acc[15] += rv * q22 * dn0;
        acc[16] += rv * q11 * dn1;  acc[17] += rv * q11 * dn2;  acc[18] += rv * q22 * dn1;
        acc[19] += rv * q22 * dn2;
    }

    float* dst = g_M + (size_t)a * 100 + r * 20;
#pragma unroll
    for (int j = 0; j < 5; j++)
        *(float4*)(dst + 4 * j) = make_float4(acc[4 * j], acc[4 * j + 1],
                                              acc[4 * j + 2], acc[4 * j + 3]);
}

// ---------------------------------------------------------------------------
// per-atom contractions -> 360 feats -> fp16 (hi,lo) rows of g_A1, pre-scaled
// ---------------------------------------------------------------------------
__device__ __forceinline__ void flush8(const float* fb, uint4* dst) {
    uint32_t pw[8];
#pragma unroll
    for (int e = 0; e < 8; e++) {
        uint32_t H, L;
        hsplit(fb[e] * IN_SCALE, H, L);
        pw[e] = H | (L << 16);
    }
    dst[0] = make_uint4(pw[0], pw[1], pw[2], pw[3]);
    dst[1] = make_uint4(pw[4], pw[5], pw[6], pw[7]);
}

#define M2F(r, x, y) m2[r][imap2((x), (y))]
#define M3F(r, x, y, z) m3[r][imap3((x), (y), (z))]

__global__ void __launch_bounds__(128) feat_kernel() {
    int a = blockIdx.x * blockDim.x + threadIdx.x;
    if (a >= NA) return;

    const float* v = g_M + (size_t)a * 100;
    float m0[5], m1[5][3], m2[5][6], m3[5][10];
#pragma unroll
    for (int r = 0; r < 5; r++) {
        m0[r] = v[r * 20];
#pragma unroll
        for (int i = 0; i < 3; i++) m1[r][i] = v[r * 20 + 1 + i];
#pragma unroll
        for (int q = 0; q < 6; q++) m2[r][q] = v[r * 20 + 4 + q];
#pragma unroll
        for (int q = 0; q < 10; q++) m3[r][q] = v[r * 20 + 10 + q];
    }

    const float w2[6] = {1.f, 2.f, 2.f, 1.f, 2.f, 1.f};
    const float w3[10] = {1.f, 3.f, 3.f, 3.f, 6.f, 3.f, 1.f, 3.f, 3.f, 1.f};

    char* rowb = (char*)g_A1 + (size_t)a * (KP1 * 2);
    float fb[8];
    int cnt = 0, pos = 0;
#define PUT(x) do { fb[cnt] = (x); \
    if (cnt == 7) { flush8(fb, (uint4*)(rowb + (size_t)(pos - 7) * 4)); cnt = 0; } else cnt++; \
    pos++; } while (0)

#pragma unroll
    for (int r = 0; r < 5; r++) PUT(m0[r]);

#pragma unroll
    for (int r = 0; r < 5; r++)
#pragma unroll
        for (int s = 0; s <= r; s++) {
            float acc = 0.f;
#pragma unroll
            for (int i = 0; i < 3; i++) acc += m1[r][i] * m1[s][i];
            PUT(acc);
        }

#pragma unroll
    for (int r = 0; r < 5; r++)
#pragma unroll
        for (int s = 0; s <= r; s++) {
            float acc = 0.f;
#pragma unroll
            for (int q = 0; q < 6; q++) acc += w2[q] * m2[r][q] * m2[s][q];
            PUT(acc);
        }

#pragma unroll
    for (int r = 0; r < 5; r++)
#pragma unroll
        for (int s = 0; s <= r; s++) {
            float acc = 0.f;
#pragma unroll
            for (int q = 0; q < 10; q++) acc += w3[q] * m3[r][q] * m3[s][q];
            PUT(acc);
        }

#pragma unroll
    for (int r = 0; r < 5; r++)
#pragma unroll
        for (int s = 0; s <= r; s++)
#pragma unroll
            for (int t = 0; t <= s; t++) {
                float acc = 0.f;
#pragma unroll
                for (int x = 0; x < 3; x++)
#pragma unroll
                    for (int y = 0; y < 3; y++)
#pragma unroll
                        for (int z = 0; z < 3; z++)
                            acc += M2F(r, x, y) * M2F(s, x, z) * M2F(t, y, z);
                PUT(acc);
            }

#pragma unroll
    for (int r = 0; r < 5; r++)
#pragma unroll
        for (int s = 0; s <= r; s++)
#pragma unroll
            for (int t = 0; t < 5; t++) {
                float acc = 0.f;
#pragma unroll
                for (int x = 0; x < 3; x++)
#pragma unroll
                    for (int y = 0; y < 3; y++)
                        acc += m1[r][x] * m1[s][y] * M2F(t, x, y);
                PUT(acc);
            }

#pragma unroll
    for (int r = 0; r < 5; r++)
#pragma unroll
        for (int s = 0; s <= r; s++) {
            float A[3][3];
#pragma unroll
            for (int k = 0; k < 3; k++)
#pragma unroll
                for (int l = 0; l < 3; l++) {
                    float acc = 0.f;
#pragma unroll
                    for (int x = 0; x < 3; x++)
#pragma unroll
                        for (int y = 0; y < 3; y++)
                            acc += M3F(r, x, y, k) * M3F(s, x, y, l);
                    A[k][l] = acc;
                }
#pragma unroll
            for (int t = 0; t < 5; t++) {
                float acc = 0.f;
#pragma unroll
                for (int k = 0; k < 3; k++)
#pragma unroll
                    for (int l = 0; l < 3; l++)
                        acc += A[k][l] * M2F(t, k, l);
                PUT(acc);
            }
        }

#pragma unroll
    for (int r = 0; r < 5; r++)
#pragma unroll
        for (int s = 0; s < 5; s++) {
            float B[3];
#pragma unroll
            for (int k = 0; k < 3; k++) {
                float acc = 0.f;
#pragma unroll
                for (int x = 0; x < 3; x++)
#pragma unroll
                    for (int y = 0; y < 3; y++)
                        acc += M3F(r, x, y, k) * M2F(s, x, y);
                B[k] = acc;
            }
#pragma unroll
            for (int t = 0; t < 5; t++)
                PUT(B[0] * m1[t][0] + B[1] * m1[t][1] + B[2] * m1[t][2]);
        }
#undef PUT
}

// ---------------------------------------------------------------------------
// weight prep: W[K][512] fp32 -> B[n][Kp] fp16 (hi,hi); coalesced writes
// ---------------------------------------------------------------------------
__global__ void wprep_kernel(const float* __restrict__ W, __half* __restrict__ B,
                             int K, int Kp) {
    int idx = blockIdx.x * blockDim.x + threadIdx.x;
    if (idx >= K * 512) return;
    int n = idx / K, k = idx - n * K;     // consecutive threads -> consecutive k
    float w = __ldg(W + (size_t)k * 512 + n);
    uint32_t h = (uint32_t)__half_as_ushort(__float2half(w));
    *(uint32_t*)((char*)B + (size_t)n * (Kp * 2) + 4 * k) = h | (h << 16);
}

// ---------------------------------------------------------------------------
// mma.sync fp16 GEMM, 3-stage cp.async pipeline.
// mode 1: swish -> fp16 (hi,lo) rows scaled 2^-8 (next layer A)
// mode 2: swish -> fused GEMV vs W3, REDG partials into g_outacc
// ---------------------------------------------------------------------------
#define STAGE 20480
#define BOFF  10240
#define GSMEM (3 * STAGE)

__device__ __forceinline__ void load_stage(uint32_t sb, const char* Ab, const char* Bb,
                                           int m0, int bn, int ldab, int kt, int tid) {
    uint32_t st = (uint32_t)(kt % 3) * STAGE;
    int k0B = kt * 64;
#pragma unroll
    for (int i = 0; i < 2; i++) {
        int t = tid + i * 256;
        int row = t >> 2, ch = (t & 3) * 16;
        CP16(sb + st + (uint32_t)(row * 80 + ch),
             Ab + (size_t)(m0 + row) * ldab + k0B + ch);
    }
#pragma unroll
    for (int i = 0; i < 2; i++) {
        int t = tid + i * 256;
        int row = t >> 2, ch = (t & 3) * 16;
        CP16(sb + st + BOFF + (uint32_t)(row * 80 + ch),
             Bb + (size_t)(bn * 128 + row) * ldab + k0B + ch);
    }
    CP_COMMIT();
}

__global__ void __launch_bounds__(256, 2) gemm_mma(
    const __half* __restrict__ A, const __half* __restrict__ B,
    const float* __restrict__ bias, const float* __restrict__ W3,
    char* __restrict__ Cout, int Kp, float scale, int mode) {
    extern __shared__ __align__(16) char smem[];
    uint32_t sb = smem_u32(smem);

    const int tid = threadIdx.x, wid = tid >> 5, lane = tid & 31;
    const int wm = wid & 3, wn = wid >> 2;          // warp grid 4(m) x 2(n)
    const int bn = blockIdx.x, m0 = blockIdx.y * 128;
    const int ldab = Kp * 2;
    const int nk = Kp >> 5;

    const char* Ab = (const char*)A;
    const char* Bb = (const char*)B;

    float d[2][8][4];
#pragma unroll
    for (int i = 0; i < 2; i++)
#pragma unroll
        for (int j = 0; j < 8; j++)
#pragma unroll
            for (int q = 0; q < 4; q++) d[i][j][q] = 0.f;

    load_stage(sb, Ab, Bb, m0, bn, ldab, 0, tid);
    load_stage(sb, Ab, Bb, m0, bn, ldab, 1, tid);
    load_stage(sb, Ab, Bb, m0, bn, ldab, 2, tid);

    const int lr = lane & 15, lc = lane >> 4;

    for (int kt = 0; kt < nk; kt++) {
        CP_WAIT(2);
        __syncthreads();
        uint32_t sA = sb + (uint32_t)(kt % 3) * STAGE;
        uint32_t sBt = sA + BOFF;
#pragma unroll
        for (int h = 0; h < 2; h++) {
            uint32_t a[2][4];
#pragma unroll
            for (int mi = 0; mi < 2; mi++)
                ldm_x4(a[mi][0], a[mi][1], a[mi][2], a[mi][3],
                       sA + (uint32_t)((wm * 32 + mi * 16 + lr) * 80 + lc * 16 + h * 32));
            uint32_t b[8][2];
#pragma unroll
            for (int pi = 0; pi < 4; pi++) {
                uint32_t t0, t1, t2, t3;
                ldm_x4(t0, t1, t2, t3,
                       sBt + (uint32_t)((wn * 64 + pi * 16 + lr) * 80 + lc * 16 + h * 32));
                b[2 * pi][0] = t0; b[2 * pi][1] = t2;
                b[2 * pi + 1][0] = t1; b[2 * pi + 1][1] = t3;
            }
#pragma unroll
            for (int mi = 0; mi < 2; mi++)
#pragma unroll
                for (int ni = 0; ni < 8; ni++)
                    mma16816(d[mi][ni], a[mi], b[ni]);
        }
        __syncthreads();
        if (kt + 3 < nk) load_stage(sb, Ab, Bb, m0, bn, ldab, kt + 3, tid);
        else CP_COMMIT();
    }

    // epilogue
    const int g = lane >> 2, tg = lane & 3;
    float oacc[2][2] = {{0.f, 0.f}, {0.f, 0.f}};
#pragma unroll
    for (int mi = 0; mi < 2; mi++) {
#pragma unroll
        for (int ni = 0; ni < 8; ni++) {
            int n = bn * 128 + wn * 64 + ni * 8 + 2 * tg;
            float bz0 = 0.1f * bias[n], bz1 = 0.1f * bias[n + 1];
            float w30 = 0.f, w31 = 0.f;
            if (mode == 2) { w30 = W3[n]; w31 = W3[n + 1]; }
#pragma unroll
            for (int half = 0; half < 2; half++) {
                int m = m0 + wm * 32 + mi * 16 + g + half * 8;
                float v0 = d[mi][ni][2 * half + 0] * scale + bz0;
                float v1 = d[mi][ni][2 * half + 1] * scale + bz1;
                v0 = v0 / (1.0f + __expf(-v0));
                v1 = v1 / (1.0f + __expf(-v1));
                if (mode == 1) {
                    if (m < NA) {
                        uint32_t H0, L0, H1, L1;
                        hsplit(v0 * IN_SCALE, H0, L0);
                        hsplit(v1 * IN_SCALE, H1, L1);
                        *(uint2*)(Cout + (size_t)m * (KP2 * 2) + (size_t)n * 4) =
                            make_uint2(H0 | (L0 << 16), H1 | (L1 << 16));
                    }
                } else {
                    oacc[mi][half] += v0 * w30 + v1 * w31;
                }
            }
        }
    }
    if (mode == 2) {
#pragma unroll
        for (int mi = 0; mi < 2; mi++)
#pragma unroll
            for (int half = 0; half < 2; half++) {
                float s = oacc[mi][half];
                s += __shfl_xor_sync(0xffffffffu, s, 1);
                s += __shfl_xor_sync(0xffffffffu, s, 2);
                if (tg == 0) {
                    int m = m0 + wm * 32 + mi * 16 + g + half * 8;
                    if (m < NA) redf(&g_outacc[m], s);
                }
            }
    }
}

// ---------------------------------------------------------------------------
// finalize: out = mask * (acc / sqrt(512) + 0.1*b3)
// ---------------------------------------------------------------------------
__global__ void fin_kernel(const float* __restrict__ b3, const int* __restrict__ Z,
                           float* __restrict__ out) {
    int i = blockIdx.x * blockDim.x + threadIdx.x;
    if (i >= NA) return;
    float v = g_outacc[i] * 0.04419417382415922f + 0.1f * b3[0];
    out[i] = (Z[i] > 0) ? v : 0.0f;
}

// ---------------------------------------------------------------------------
extern "C" void kernel_launch(void* const* d_in, const int* in_sizes, int n_in,
                              void* d_out, int out_size) {
    const float* R   = (const float*)d_in[0];
    const int*   Z   = (const int*)d_in[1];
    const int*   nbr = (const int*)d_in[2];
    const float* off = (const float*)d_in[4];
    const float* emb = (const float*)d_in[5];
    const float* W1  = (const float*)d_in[6];
    const float* b1  = (const float*)d_in[7];
    const float* W2  = (const float*)d_in[8];
    const float* b2  = (const float*)d_in[9];
    const float* W3  = (const float*)d_in[10];
    const float* b3  = (const float*)d_in[11];
    float* out = (float*)d_out;

    cudaFuncSetAttribute(gemm_mma, cudaFuncAttributeMaxDynamicSharedMemorySize, GSMEM);

    __half *pA1, *pB1, *pA2, *pB2;
    cudaGetSymbolAddress((void**)&pA1, g_A1);
    cudaGetSymbolAddress((void**)&pB1, g_B1);
    cudaGetSymbolAddress((void**)&pA2, g_A2);
    cudaGetSymbolAddress((void**)&pB2, g_B2);

    zc_kernel<<<(NA + 255) / 256, 256>>>();
    p1_kernel<<<(NP + 255) / 256, 256>>>(R, Z, nbr, off, emb);
    p2_kernel<<<(NA * 5 + 127) / 128, 128>>>();
    feat_kernel<<<(NA + 127) / 128, 128>>>();
    wprep_kernel<<<(360 * 512 + 255) / 256, 256>>>(W1, pB1, 360, KP1);
    wprep_kernel<<<(512 * 512 + 255) / 256, 256>>>(W2, pB2, 512, KP2);

    const float s1 = 256.0f * 0.05270462766947299f;  // 2^8 / sqrt(360)
    const float s2 = 256.0f * 0.04419417382415922f;  // 2^8 / sqrt(512)

    dim3 g(4, NAP / 128);
    gemm_mma<<<g, 256, GSMEM>>>(pA1, pB1, b1, nullptr, (char*)pA2, KP1, s1, 1);
    gemm_mma<<<g, 256, GSMEM>>>(pA2, pB2, b2, W3, nullptr, KP2, s2, 2);

    fin_kernel<<<(NA + 255) / 256, 256>>>(b3, Z, out);
}

// round 7
// speedup vs baseline: 2.5737x; 1.0171x over previous
#include <cuda_runtime.h>
#include <cuda_fp16.h>
#include <math.h>
#include <stdint.h>

#define NA 20000
#define NAP 20096           // padded rows (157*128)
#define NP 800000
#define NSP 119
#define NB 7
#define RMAXV 6.0f
#define PI_F 3.14159265358979323846f
#define CAP 64              // per-atom neighbor capacity (lambda~15, P(>=64)~1e-20)

#define KP1 736             // 2*360 padded to 32-element k-tiles
#define KP2 1024            // 2*512
#define U 512
#define IN_SCALE 0.00390625f   // 2^-8 applied to GEMM A inputs

// ---------------------------------------------------------------------------
// device scratch (static; zero at module load)
// ---------------------------------------------------------------------------
__device__ int    g_cur[NA];
__device__ float  g_outacc[NA];
__device__ float4 g_Rz[NA];                       // packed R.xyz + Z bits
__device__ float  g_embp[NSP * NSP * 36];         // emb rows padded 35->36
__device__ float  g_prod[(size_t)NA * CAP * 8];   // per active pair: rad[5]+dn[3]
__device__ float  g_M[(size_t)NA * 100];          // [atom][100] moments
__device__ __half g_A1[(size_t)NAP * KP1];        // feats (scaled), fp16 hi/lo
__device__ __half g_B1[(size_t)U * KP1];          // W1^T fp16 (hi,hi)
__device__ __half g_A2[(size_t)NAP * KP2];        // h1 (scaled), fp16 hi/lo
__device__ __half g_B2[(size_t)U * KP2];          // W2^T fp16 (hi,hi)

// ---------------------------------------------------------------------------
// helpers
// ---------------------------------------------------------------------------
__device__ __forceinline__ uint32_t smem_u32(const void* p) {
    uint32_t a;
    asm("{ .reg .u64 t; cvta.to.shared.u64 t, %1; cvt.u32.u64 %0, t; }" : "=r"(a) : "l"(p));
    return a;
}
#define CP16(dst, src)   asm volatile("cp.async.cg.shared.global [%0], [%1], 16;" :: "r"(dst), "l"(src))
#define CP_COMMIT()      asm volatile("cp.async.commit_group;" ::: "memory")
#define CP_WAIT(n)       asm volatile("cp.async.wait_group %0;" :: "n"(n) : "memory")

__device__ __forceinline__ void ldm_x4(uint32_t& r0, uint32_t& r1, uint32_t& r2, uint32_t& r3,
                                       uint32_t addr) {
    asm volatile("ldmatrix.sync.aligned.m8n8.x4.shared.b16 {%0,%1,%2,%3}, [%4];"
                 : "=r"(r0), "=r"(r1), "=r"(r2), "=r"(r3) : "r"(addr));
}
__device__ __forceinline__ void mma16816(float* d, const uint32_t* a, const uint32_t* b) {
    asm volatile("mma.sync.aligned.m16n8k16.row.col.f32.f16.f16.f32 "
                 "{%0,%1,%2,%3}, {%4,%5,%6,%7}, {%8,%9}, {%0,%1,%2,%3};"
                 : "+f"(d[0]), "+f"(d[1]), "+f"(d[2]), "+f"(d[3])
                 : "r"(a[0]), "r"(a[1]), "r"(a[2]), "r"(a[3]), "r"(b[0]), "r"(b[1]));
}
__device__ __forceinline__ void redf(float* p, float v) {
    asm volatile("red.global.add.f32 [%0], %1;" :: "l"(p), "f"(v) : "memory");
}

// fp16 hi/lo split (input assumed pre-scaled into fp16 range)
__device__ __forceinline__ void hsplit(float v, uint32_t& h, uint32_t& l) {
    __half hb = __float2half(v);
    float r = v - __half2float(hb);
    __half lb = __float2half(r);
    h = (uint32_t)__half_as_ushort(hb);
    l = (uint32_t)__half_as_ushort(lb);
}

// symmetric index maps (compile-time folded)
__device__ __forceinline__ int imap2(int a, int b) {
    int i = a < b ? a : b, j = a < b ? b : a;
    return (i == 0) ? j : ((i == 1) ? (2 + j) : 5);
}
__device__ __forceinline__ int imap3(int a, int b, int c) {
    int i = a, j = b, k = c, t;
    if (i > j) { t = i; i = j; j = t; }
    if (j > k) { t = j; j = k; k = t; }
    if (i > j) { t = i; i = j; j = t; }
    if (i == 0) return imap2(j, k);
    if (i == 1) return (j == 1) ? (5 + k) : 8;
    return 9;
}

// ---------------------------------------------------------------------------
__global__ void zc_kernel(const float* __restrict__ R, const int* __restrict__ Z) {
    int i = blockIdx.x * blockDim.x + threadIdx.x;
    if (i < NA) {
        g_cur[i] = 0;
        g_outacc[i] = 0.f;
        g_Rz[i] = make_float4(R[3 * i], R[3 * i + 1], R[3 * i + 2], __int_as_float(Z[i]));
    }
}

__global__ void embp_kernel(const float* __restrict__ emb) {
    int i = blockIdx.x * blockDim.x + threadIdx.x;
    if (i >= NSP * NSP * 36) return;
    int pair = i / 36, c = i - pair * 36;
    g_embp[i] = (c < 35) ? emb[(size_t)pair * 35 + c] : 0.f;
}

// ---------------------------------------------------------------------------
// p1: per active pair compute rad[5]+dn[3], place into atom bucket (32B record)
// ---------------------------------------------------------------------------
__global__ void p1_kernel(const int* __restrict__ nbr, const float* __restrict__ off) {
    int p = blockIdx.x * blockDim.x + threadIdx.x;
    if (p >= NP) return;
    int ia = nbr[p], ja = nbr[NP + p];

    float4 ri = __ldg(&g_Rz[ia]);
    float4 rj = __ldg(&g_Rz[ja]);
    float dx = rj.x - ri.x + off[p * 3 + 0];
    float dy = rj.y - ri.y + off[p * 3 + 1];
    float dz = rj.z - ri.z + off[p * 3 + 2];
    float dr = sqrtf(dx * dx + dy * dy + dz * dz);
    if (!(dr < RMAXV)) return;

    float inv = 1.0f / (dr + 1e-5f);
    float dn0 = dx * inv, dn1 = dy * inv, dn2 = dz * inv;

    const float betta = 49.0f / 36.0f;
    const float rad_norm = 0.898112f;   // (2*betta/pi)^0.75
    float cut = 0.5f * (cosf(PI_F * dr * (1.0f / RMAXV)) + 1.0f);

    float basis[NB];
#pragma unroll
    for (int b = 0; b < NB; b++) {
        float t = dr - (0.5f + 0.91666666666666667f * (float)b);
        basis[b] = rad_norm * expf(-betta * t * t);
    }

    int zi = __float_as_int(ri.w), zj = __float_as_int(rj.w);
    // padded emb row: 36 floats, 16B-aligned -> 9 x LDG.128
    const float4* e4 = (const float4*)(g_embp + (size_t)(zj * NSP + zi) * 36);
    float ev[36];
#pragma unroll
    for (int q = 0; q < 9; q++) {
        float4 t = __ldg(e4 + q);
        ev[4 * q] = t.x; ev[4 * q + 1] = t.y; ev[4 * q + 2] = t.z; ev[4 * q + 3] = t.w;
    }

    float pref = 0.37796447300922720f * cut;
    float rad[5];
#pragma unroll
    for (int r = 0; r < 5; r++) {
        float s = 0.f;
#pragma unroll
        for (int b = 0; b < NB; b++) s += ev[r * NB + b] * basis[b];
        rad[r] = pref * s;
    }

    int slot = atomicAdd(&g_cur[ia], 1);
    if (slot >= CAP) return;   // statistically impossible (P ~ 1e-20)
    float* pb = g_prod + ((size_t)ia * CAP + slot) * 8;
    ((float4*)pb)[0] = make_float4(rad[0], rad[1], rad[2], rad[3]);
    ((float4*)pb)[1] = make_float4(rad[4], dn0, dn1, dn2);
}

// ---------------------------------------------------------------------------
// p2: 5 threads per atom (one radial channel each); expand monomials on the fly
// ---------------------------------------------------------------------------
__global__ void __launch_bounds__(128) p2_kernel() {
    int t = blockIdx.x * blockDim.x + threadIdx.x;
    if (t >= NA * 5) return;
    int a = t / 5, r = t - a * 5;
    int n = g_cur[a];
    if (n > CAP) n = CAP;
    const float* base = g_prod + (size_t)a * CAP * 8;

    float acc[20];
#pragma unroll
    for (int j = 0; j < 20; j++) acc[j] = 0.f;

    for (int s = 0; s < n; s++) {
        float rv = __ldg(base + s * 8 + r);
        float4 v = __ldg((const float4*)(base + s * 8 + 4));
        float dn0 = v.y, dn1 = v.z, dn2 = v.w;
        float q00 = dn0 * dn0, q01 = dn0 * dn1, q02 = dn0 * dn2;
        float q11 = dn1 * dn1, q12 = dn1 * dn2, q22 = dn2 * dn2;
        acc[0] += rv;
        acc[1] += rv * dn0;  acc[2] += rv * dn1;  acc[3] += rv * dn2;
        acc[4] += rv * q00;  acc[5] += rv * q01;  acc[6] += rv * q02;
        acc[7] += rv * q11;  acc[8] += rv * q12;  acc[9] += rv * q22;
        acc[10] += rv * q00 * dn0;  acc[11] += rv * q00 * dn1;  acc[12] += rv * q00 * dn2;
        acc[13] += rv * q11 * dn0;  acc[14] += rv * q01 * dn2;  acc[15] += rv * q22 * dn0;
        acc[16] += rv * q11 * dn1;  acc[17] += rv * q11 * dn2;  acc[18] += rv * q22 * dn1;
        acc[19] += rv * q22 * dn2;
    }

    float* dst = g_M + (size_t)a * 100 + r * 20;
#pragma unroll
    for (int j = 0; j < 5; j++)
        *(float4*)(dst + 4 * j) = make_float4(acc[4 * j], acc[4 * j + 1],
                                              acc[4 * j + 2], acc[4 * j + 3]);
}

// ---------------------------------------------------------------------------
// feat: 32 atoms per 128-thread block, warp w = feature-group role w.
// role0: M0,c1,c2,c3,c4 (pos 0..84); role1: c5 (85..159);
// role2: c6 (160..234); role3: c7 (235..359).
// Features staged fp32 in smem, then coalesced fp16-split writeout.
// ---------------------------------------------------------------------------
#define M2F(r, x, y) m2[r][imap2((x), (y))]
#define M3F(r, x, y, z) m3[r][imap3((x), (y), (z))]
#define SFLD 361   // stride 361: gcd(361%32=9,32)=1 -> conflict-free staging

__global__ void __launch_bounds__(128) feat_kernel() {
    __shared__ float sf[32 * SFLD];
    const int role = threadIdx.x >> 5;      // warp-uniform
    const int aL = threadIdx.x & 31;
    const int a = blockIdx.x * 32 + aL;
    float* F = sf + aL * SFLD;

    if (a < NA) {
        const float* v = g_M + (size_t)a * 100;
        if (role == 0) {
            int pos = 0;
            float m0[5];
#pragma unroll
            for (int r = 0; r < 5; r++) m0[r] = v[r * 20];
#pragma unroll
            for (int r = 0; r < 5; r++) F[pos++] = m0[r];
            float m1[5][3];
#pragma unroll
            for (int r = 0; r < 5; r++)
#pragma unroll
                for (int i = 0; i < 3; i++) m1[r][i] = v[r * 20 + 1 + i];
#pragma unroll
            for (int r = 0; r < 5; r++)
#pragma unroll
                for (int s = 0; s <= r; s++) {
                    float acc = 0.f;
#pragma unroll
                    for (int i = 0; i < 3; i++) acc += m1[r][i] * m1[s][i];
                    F[pos++] = acc;
                }
            float m2[5][6];
#pragma unroll
            for (int r = 0; r < 5; r++)
#pragma unroll
                for (int q = 0; q < 6; q++) m2[r][q] = v[r * 20 + 4 + q];
            const float w2[6] = {1.f, 2.f, 2.f, 1.f, 2.f, 1.f};
#pragma unroll
            for (int r = 0; r < 5; r++)
#pragma unroll
                for (int s = 0; s <= r; s++) {
                    float acc = 0.f;
#pragma unroll
                    for (int q = 0; q < 6; q++) acc += w2[q] * m2[r][q] * m2[s][q];
                    F[pos++] = acc;
                }
            {
                float m3[5][10];
#pragma unroll
                for (int r = 0; r < 5; r++)
#pragma unroll
                    for (int q = 0; q < 10; q++) m3[r][q] = v[r * 20 + 10 + q];
                const float w3[10] = {1.f, 3.f, 3.f, 3.f, 6.f, 3.f, 1.f, 3.f, 3.f, 1.f};
#pragma unroll
                for (int r = 0; r < 5; r++)
#pragma unroll
                    for (int s = 0; s <= r; s++) {
                        float acc = 0.f;
#pragma unroll
                        for (int q = 0; q < 10; q++) acc += w3[q] * m3[r][q] * m3[s][q];
                        F[pos++] = acc;
                    }
            }
            // c4
#pragma unroll
            for (int r = 0; r < 5; r++)
#pragma unroll
                for (int s = 0; s <= r; s++)
#pragma unroll
                    for (int t = 0; t <= s; t++) {
                        float acc = 0.f;
#pragma unroll
                        for (int x = 0; x < 3; x++)
#pragma unroll
                            for (int y = 0; y < 3; y++)
#pragma unroll
                                for (int z = 0; z < 3; z++)
                                    acc += M2F(r, x, y) * M2F(s, x, z) * M2F(t, y, z);
                        F[pos++] = acc;
                    }
        } else if (role == 1) {
            int pos = 85;
            float m1[5][3], m2[5][6];
#pragma unroll
            for (int r = 0; r < 5; r++) {
#pragma unroll
                for (int i = 0; i < 3; i++) m1[r][i] = v[r * 20 + 1 + i];
#pragma unroll
                for (int q = 0; q < 6; q++) m2[r][q] = v[r * 20 + 4 + q];
            }
#pragma unroll
            for (int r = 0; r < 5; r++)
#pragma unroll
                for (int s = 0; s <= r; s++)
#pragma unroll
                    for (int t = 0; t < 5; t++) {
                        float acc = 0.f;
#pragma unroll
                        for (int x = 0; x < 3; x++)
#pragma unroll
                            for (int y = 0; y < 3; y++)
                                acc += m1[r][x] * m1[s][y] * M2F(t, x, y);
                        F[pos++] = acc;
                    }
        } else if (role == 2) {
            int pos = 160;
            float m2[5][6], m3[5][10];
#pragma unroll
            for (int r = 0; r < 5; r++) {
#pragma unroll
                for (int q = 0; q < 6; q++) m2[r][q] = v[r * 20 + 4 + q];
#pragma unroll
                for (int q = 0; q < 10; q++) m3[r][q] = v[r * 20 + 10 + q];
            }
#pragma unroll
            for (int r = 0; r < 5; r++)
#pragma unroll
                for (int s = 0; s <= r; s++) {
                    float A[3][3];
#pragma unroll
                    for (int k = 0; k < 3; k++)
#pragma unroll
                        for (int l = 0; l < 3; l++) {
                            float acc = 0.f;
#pragma unroll
                            for (int x = 0; x < 3; x++)
#pragma unroll
                                for (int y = 0; y < 3; y++)
                                    acc += M3F(r, x, y, k) * M3F(s, x, y, l);
                            A[k][l] = acc;
                        }
#pragma unroll
                    for (int t = 0; t < 5; t++) {
                        float acc = 0.f;
#pragma unroll
                        for (int k = 0; k < 3; k++)
#pragma unroll
                            for (int l = 0; l < 3; l++)
                                acc += A[k][l] * M2F(t, k, l);
                        F[pos++] = acc;
                    }
                }
        } else {
            int pos = 235;
            float m1[5][3], m2[5][6], m3[5][10];
#pragma unroll
            for (int r = 0; r < 5; r++) {
#pragma unroll
                for (int i = 0; i < 3; i++) m1[r][i] = v[r * 20 + 1 + i];
#pragma unroll
                for (int q = 0; q < 6; q++) m2[r][q] = v[r * 20 + 4 + q];
#pragma unroll
                for (int q = 0; q < 10; q++) m3[r][q] = v[r * 20 + 10 + q];
            }
#pragma unroll
            for (int r = 0; r < 5; r++)
#pragma unroll
                for (int s = 0; s < 5; s++) {
                    float B[3];
#pragma unroll
                    for (int k = 0; k < 3; k++) {
                        float acc = 0.f;
#pragma unroll
                        for (int x = 0; x < 3; x++)
#pragma unroll
                            for (int y = 0; y < 3; y++)
                                acc += M3F(r, x, y, k) * M2F(s, x, y);
                        B[k] = acc;
                    }
#pragma unroll
                    for (int t = 0; t < 5; t++)
                        F[pos++] = B[0] * m1[t][0] + B[1] * m1[t][1] + B[2] * m1[t][2];
                }
        }
    }
    __syncthreads();

    // coalesced writeout: warp w handles atoms w*8..w*8+7
    const int wid = threadIdx.x >> 5, lane = threadIdx.x & 31;
#pragma unroll
    for (int i = 0; i < 8; i++) {
        int al = wid * 8 + i;
        int ga = blockIdx.x * 32 + al;
        if (ga >= NA) break;
        char* rowb = (char*)g_A1 + (size_t)ga * (KP1 * 2);
        const float* src = sf + al * SFLD;
        for (int k = lane; k < 360; k += 32) {
            uint32_t H, L;
            hsplit(src[k] * IN_SCALE, H, L);
            *(uint32_t*)(rowb + (size_t)k * 4) = H | (L << 16);
        }
    }
}

// ---------------------------------------------------------------------------
// weight prep: W[K][512] fp32 -> B[n][Kp] fp16 (hi,hi); coalesced writes
// ---------------------------------------------------------------------------
__global__ void wprep_kernel(const float* __restrict__ W, __half* __restrict__ B,
                             int K, int Kp) {
    int idx = blockIdx.x * blockDim.x + threadIdx.x;
    if (idx >= K * 512) return;
    int n = idx / K, k = idx - n * K;     // consecutive threads -> consecutive k
    float w = __ldg(W + (size_t)k * 512 + n);
    uint32_t h = (uint32_t)__half_as_ushort(__float2half(w));
    *(uint32_t*)((char*)B + (size_t)n * (Kp * 2) + 4 * k) = h | (h << 16);
}

// ---------------------------------------------------------------------------
// mma.sync fp16 GEMM, 3-stage cp.async pipeline.
// mode 1: swish -> fp16 (hi,lo) rows scaled 2^-8 (next layer A)
// mode 2: swish -> fused GEMV vs W3, REDG partials into g_outacc
// ---------------------------------------------------------------------------
#define STAGE 20480
#define BOFF  10240
#define GSMEM (3 * STAGE)

__device__ __forceinline__ void load_stage(uint32_t sb, const char* Ab, const char* Bb,
                                           int m0, int bn, int ldab, int kt, int tid) {
    uint32_t st = (uint32_t)(kt % 3) * STAGE;
    int k0B = kt * 64;
#pragma unroll
    for (int i = 0; i < 2; i++) {
        int t = tid + i * 256;
        int row = t >> 2, ch = (t & 3) * 16;
        CP16(sb + st + (uint32_t)(row * 80 + ch),
             Ab + (size_t)(m0 + row) * ldab + k0B + ch);
    }
#pragma unroll
    for (int i = 0; i < 2; i++) {
        int t = tid + i * 256;
        int row = t >> 2, ch = (t & 3) * 16;
        CP16(sb + st + BOFF + (uint32_t)(row * 80 + ch),
             Bb + (size_t)(bn * 128 + row) * ldab + k0B + ch);
    }
    CP_COMMIT();
}

__global__ void __launch_bounds__(256, 2) gemm_mma(
    const __half* __restrict__ A, const __half* __restrict__ B,
    const float* __restrict__ bias, const float* __restrict__ W3,
    char* __restrict__ Cout, int Kp, float scale, int mode) {
    extern __shared__ __align__(16) char smem[];
    uint32_t sb = smem_u32(smem);

    const int tid = threadIdx.x, wid = tid >> 5, lane = tid & 31;
    const int wm = wid & 3, wn = wid >> 2;          // warp grid 4(m) x 2(n)
    const int bn = blockIdx.x, m0 = blockIdx.y * 128;
    const int ldab = Kp * 2;
    const int nk = Kp >> 5;

    const char* Ab = (const char*)A;
    const char* Bb = (const char*)B;

    float d[2][8][4];
#pragma unroll
    for (int i = 0; i < 2; i++)
#pragma unroll
        for (int j = 0; j < 8; j++)
#pragma unroll
            for (int q = 0; q < 4; q++) d[i][j][q] = 0.f;

    load_stage(sb, Ab, Bb, m0, bn, ldab, 0, tid);
    load_stage(sb, Ab, Bb, m0, bn, ldab, 1, tid);
    load_stage(sb, Ab, Bb, m0, bn, ldab, 2, tid);

    const int lr = lane & 15, lc = lane >> 4;

    for (int kt = 0; kt < nk; kt++) {
        CP_WAIT(2);
        __syncthreads();
        uint32_t sA = sb + (uint32_t)(kt % 3) * STAGE;
        uint32_t sBt = sA + BOFF;
#pragma unroll
        for (int h = 0; h < 2; h++) {
            uint32_t a[2][4];
#pragma unroll
            for (int mi = 0; mi < 2; mi++)
                ldm_x4(a[mi][0], a[mi][1], a[mi][2], a[mi][3],
                       sA + (uint32_t)((wm * 32 + mi * 16 + lr) * 80 + lc * 16 + h * 32));
            uint32_t b[8][2];
#pragma unroll
            for (int pi = 0; pi < 4; pi++) {
                uint32_t t0, t1, t2, t3;
                ldm_x4(t0, t1, t2, t3,
                       sBt + (uint32_t)((wn * 64 + pi * 16 + lr) * 80 + lc * 16 + h * 32));
                b[2 * pi][0] = t0; b[2 * pi][1] = t2;
                b[2 * pi + 1][0] = t1; b[2 * pi + 1][1] = t3;
            }
#pragma unroll
            for (int mi = 0; mi < 2; mi++)
#pragma unroll
                for (int ni = 0; ni < 8; ni++)
                    mma16816(d[mi][ni], a[mi], b[ni]);
        }
        __syncthreads();
        if (kt + 3 < nk) load_stage(sb, Ab, Bb, m0, bn, ldab, kt + 3, tid);
        else CP_COMMIT();
    }

    // epilogue
    const int g = lane >> 2, tg = lane & 3;
    float oacc[2][2] = {{0.f, 0.f}, {0.f, 0.f}};
#pragma unroll
    for (int mi = 0; mi < 2; mi++) {
#pragma unroll
        for (int ni = 0; ni < 8; ni++) {
            int n = bn * 128 + wn * 64 + ni * 8 + 2 * tg;
            float bz0 = 0.1f * bias[n], bz1 = 0.1f * bias[n + 1];
            float w30 = 0.f, w31 = 0.f;
            if (mode == 2) { w30 = W3[n]; w31 = W3[n + 1]; }
#pragma unroll
            for (int half = 0; half < 2; half++) {
                int m = m0 + wm * 32 + mi * 16 + g + half * 8;
                float v0 = d[mi][ni][2 * half + 0] * scale + bz0;
                float v1 = d[mi][ni][2 * half + 1] * scale + bz1;
                v0 = v0 / (1.0f + __expf(-v0));
                v1 = v1 / (1.0f + __expf(-v1));
                if (mode == 1) {
                    if (m < NA) {
                        uint32_t H0, L0, H1, L1;
                        hsplit(v0 * IN_SCALE, H0, L0);
                        hsplit(v1 * IN_SCALE, H1, L1);
                        *(uint2*)(Cout + (size_t)m * (KP2 * 2) + (size_t)n * 4) =
                            make_uint2(H0 | (L0 << 16), H1 | (L1 << 16));
                    }
                } else {
                    oacc[mi][half] += v0 * w30 + v1 * w31;
                }
            }
        }
    }
    if (mode == 2) {
#pragma unroll
        for (int mi = 0; mi < 2; mi++)
#pragma unroll
            for (int half = 0; half < 2; half++) {
                float s = oacc[mi][half];
                s += __shfl_xor_sync(0xffffffffu, s, 1);
                s += __shfl_xor_sync(0xffffffffu, s, 2);
                if (tg == 0) {
                    int m = m0 + wm * 32 + mi * 16 + g + half * 8;
                    if (m < NA) redf(&g_outacc[m], s);
                }
            }
    }
}

// ---------------------------------------------------------------------------
// finalize: out = mask * (acc / sqrt(512) + 0.1*b3)
// ---------------------------------------------------------------------------
__global__ void fin_kernel(const float* __restrict__ b3, const int* __restrict__ Z,
                           float* __restrict__ out) {
    int i = blockIdx.x * blockDim.x + threadIdx.x;
    if (i >= NA) return;
    float v = g_outacc[i] * 0.04419417382415922f + 0.1f * b3[0];
    out[i] = (Z[i] > 0) ? v : 0.0f;
}

// ---------------------------------------------------------------------------
extern "C" void kernel_launch(void* const* d_in, const int* in_sizes, int n_in,
                              void* d_out, int out_size) {
    const float* R   = (const float*)d_in[0];
    const int*   Z   = (const int*)d_in[1];
    const int*   nbr = (const int*)d_in[2];
    const float* off = (const float*)d_in[4];
    const float* emb = (const float*)d_in[5];
    const float* W1  = (const float*)d_in[6];
    const float* b1  = (const float*)d_in[7];
    const float* W2  = (const float*)d_in[8];
    const float* b2  = (const float*)d_in[9];
    const float* W3  = (const float*)d_in[10];
    const float* b3  = (const float*)d_in[11];
    float* out = (float*)d_out;

    cudaFuncSetAttribute(gemm_mma, cudaFuncAttributeMaxDynamicSharedMemorySize, GSMEM);

    __half *pA1, *pB1, *pA2, *pB2;
    cudaGetSymbolAddress((void**)&pA1, g_A1);
    cudaGetSymbolAddress((void**)&pB1, g_B1);
    cudaGetSymbolAddress((void**)&pA2, g_A2);
    cudaGetSymbolAddress((void**)&pB2, g_B2);

    zc_kernel<<<(NA + 255) / 256, 256>>>(R, Z);
    embp_kernel<<<(NSP * NSP * 36 + 255) / 256, 256>>>(emb);
    p1_kernel<<<(NP + 255) / 256, 256>>>(nbr, off);
    p2_kernel<<<(NA * 5 + 127) / 128, 128>>>();
    feat_kernel<<<(NA + 31) / 32, 128>>>();
    wprep_kernel<<<(360 * 512 + 255) / 256, 256>>>(W1, pB1, 360, KP1);
    wprep_kernel<<<(512 * 512 + 255) / 256, 256>>>(W2, pB2, 512, KP2);

    const float s1 = 256.0f * 0.05270462766947299f;  // 2^8 / sqrt(360)
    const float s2 = 256.0f * 0.04419417382415922f;  // 2^8 / sqrt(512)

    dim3 g(4, NAP / 128);
    gemm_mma<<<g, 256, GSMEM>>>(pA1, pB1, b1, nullptr, (char*)pA2, KP1, s1, 1);
    gemm_mma<<<g, 256, GSMEM>>>(pA2, pB2, b2, W3, nullptr, KP2, s2, 2);

    fin_kernel<<<(NA + 255) / 256, 256>>>(b3, Z, out);
}

// round 8
// speedup vs baseline: 2.5885x; 1.0058x over previous
#include <cuda_runtime.h>
#include <cuda_fp16.h>
#include <math.h>
#include <stdint.h>

#define NA 20000
#define NAP 20096           // padded rows (157*128)
#define NP 800000
#define NSP 119
#define NB 7
#define RMAXV 6.0f
#define PI_F 3.14159265358979323846f
#define CAP 64              // per-atom neighbor capacity (lambda~15, P(>=64)~1e-20)

#define KP1 736             // 2*360 padded to 32-element k-tiles
#define KP2 1024            // 2*512
#define U 512
#define IN_SCALE 0.00390625f   // 2^-8 applied to GEMM A inputs

#define P1_BLOCKS 3125
#define W1_ELEMS (360 * 512)
#define W2_ELEMS (512 * 512)
#define W_BLOCKS ((W1_ELEMS + W2_ELEMS + 255) / 256)   // 1744

// ---------------------------------------------------------------------------
// device scratch (static; zero at module load)
// ---------------------------------------------------------------------------
__device__ int    g_cur[NA];
__device__ float  g_outacc[NA];
__device__ float4 g_Rz[NA];                       // packed R.xyz + Z bits
__device__ float  g_embp[NSP * NSP * 36];         // emb rows padded 35->36
__device__ float  g_prod[(size_t)NA * CAP * 8];   // per active pair: rad[5]+dn[3]
__device__ __half g_A1[(size_t)NAP * KP1];        // feats (scaled), fp16 hi/lo
__device__ __half g_B1[(size_t)U * KP1];          // W1^T fp16 (hi,hi)
__device__ __half g_A2[(size_t)NAP * KP2];        // h1 (scaled), fp16 hi/lo
__device__ __half g_B2[(size_t)U * KP2];          // W2^T fp16 (hi,hi)

// ---------------------------------------------------------------------------
// helpers
// ---------------------------------------------------------------------------
__device__ __forceinline__ uint32_t smem_u32(const void* p) {
    uint32_t a;
    asm("{ .reg .u64 t; cvta.to.shared.u64 t, %1; cvt.u32.u64 %0, t; }" : "=r"(a) : "l"(p));
    return a;
}
#define CP16(dst, src)   asm volatile("cp.async.cg.shared.global [%0], [%1], 16;" :: "r"(dst), "l"(src))
#define CP_COMMIT()      asm volatile("cp.async.commit_group;" ::: "memory")
#define CP_WAIT(n)       asm volatile("cp.async.wait_group %0;" :: "n"(n) : "memory")

__device__ __forceinline__ void ldm_x4(uint32_t& r0, uint32_t& r1, uint32_t& r2, uint32_t& r3,
                                       uint32_t addr) {
    asm volatile("ldmatrix.sync.aligned.m8n8.x4.shared.b16 {%0,%1,%2,%3}, [%4];"
                 : "=r"(r0), "=r"(r1), "=r"(r2), "=r"(r3) : "r"(addr));
}
__device__ __forceinline__ void mma16816(float* d, const uint32_t* a, const uint32_t* b) {
    asm volatile("mma.sync.aligned.m16n8k16.row.col.f32.f16.f16.f32 "
                 "{%0,%1,%2,%3}, {%4,%5,%6,%7}, {%8,%9}, {%0,%1,%2,%3};"
                 : "+f"(d[0]), "+f"(d[1]), "+f"(d[2]), "+f"(d[3])
                 : "r"(a[0]), "r"(a[1]), "r"(a[2]), "r"(a[3]), "r"(b[0]), "r"(b[1]));
}
__device__ __forceinline__ void redf(float* p, float v) {
    asm volatile("red.global.add.f32 [%0], %1;" :: "l"(p), "f"(v) : "memory");
}

// fp16 hi/lo split (input assumed pre-scaled into fp16 range)
__device__ __forceinline__ void hsplit(float v, uint32_t& h, uint32_t& l) {
    __half hb = __float2half(v);
    float r = v - __half2float(hb);
    __half lb = __float2half(r);
    h = (uint32_t)__half_as_ushort(hb);
    l = (uint32_t)__half_as_ushort(lb);
}

// symmetric index maps (compile-time folded)
__device__ __forceinline__ int imap2(int a, int b) {
    int i = a < b ? a : b, j = a < b ? b : a;
    return (i == 0) ? j : ((i == 1) ? (2 + j) : 5);
}
__device__ __forceinline__ int imap3(int a, int b, int c) {
    int i = a, j = b, k = c, t;
    if (i > j) { t = i; i = j; j = t; }
    if (j > k) { t = j; j = k; k = t; }
    if (i > j) { t = i; i = j; j = t; }
    if (i == 0) return imap2(j, k);
    if (i == 1) return (j == 1) ? (5 + k) : 8;
    return 9;
}

// ---------------------------------------------------------------------------
// prep: zero counters/outacc, pack R+Z, pad emb rows 35->36 (one kernel)
// ---------------------------------------------------------------------------
#define EMBP_N (NSP * NSP * 36)
__global__ void prep_kernel(const float* __restrict__ R, const int* __restrict__ Z,
                            const float* __restrict__ emb) {
    int i = blockIdx.x * blockDim.x + threadIdx.x;
    if (i < EMBP_N) {
        int pair = i / 36, c = i - pair * 36;
        g_embp[i] = (c < 35) ? emb[(size_t)pair * 35 + c] : 0.f;
    }
    if (i < NA) {
        g_cur[i] = 0;
        g_outacc[i] = 0.f;
        g_Rz[i] = make_float4(R[3 * i], R[3 * i + 1], R[3 * i + 2], __int_as_float(Z[i]));
    }
}

// ---------------------------------------------------------------------------
// p1 + wprep fused by block range:
//   blocks [0, P1_BLOCKS): pair phase (rad[5]+dn[3] -> atom bucket)
//   blocks [P1_BLOCKS, P1_BLOCKS+W_BLOCKS): W1/W2 fp32 -> fp16 (hi,hi)
// ---------------------------------------------------------------------------
__global__ void p1w_kernel(const int* __restrict__ nbr, const float* __restrict__ off,
                           const float* __restrict__ W1, const float* __restrict__ W2) {
    if (blockIdx.x >= P1_BLOCKS) {
        int idx = (blockIdx.x - P1_BLOCKS) * 256 + threadIdx.x;
        if (idx < W1_ELEMS) {
            int n = idx / 360, k = idx - n * 360;
            float w = __ldg(W1 + (size_t)k * 512 + n);
            uint32_t h = (uint32_t)__half_as_ushort(__float2half(w));
            *(uint32_t*)((char*)g_B1 + (size_t)n * (KP1 * 2) + 4 * k) = h | (h << 16);
        } else {
            idx -= W1_ELEMS;
            if (idx < W2_ELEMS) {
                int n = idx >> 9, k = idx & 511;
                float w = __ldg(W2 + (size_t)k * 512 + n);
                uint32_t h = (uint32_t)__half_as_ushort(__float2half(w));
                *(uint32_t*)((char*)g_B2 + (size_t)n * (KP2 * 2) + 4 * k) = h | (h << 16);
            }
        }
        return;
    }

    int p = blockIdx.x * blockDim.x + threadIdx.x;
    if (p >= NP) return;
    int ia = nbr[p], ja = nbr[NP + p];

    float4 ri = __ldg(&g_Rz[ia]);
    float4 rj = __ldg(&g_Rz[ja]);
    float dx = rj.x - ri.x + off[p * 3 + 0];
    float dy = rj.y - ri.y + off[p * 3 + 1];
    float dz = rj.z - ri.z + off[p * 3 + 2];
    float dr = sqrtf(dx * dx + dy * dy + dz * dz);
    if (!(dr < RMAXV)) return;

    float inv = 1.0f / (dr + 1e-5f);
    float dn0 = dx * inv, dn1 = dy * inv, dn2 = dz * inv;

    const float betta = 49.0f / 36.0f;
    const float rad_norm = 0.898112f;   // (2*betta/pi)^0.75
    float cut = 0.5f * (cosf(PI_F * dr * (1.0f / RMAXV)) + 1.0f);

    float basis[NB];
#pragma unroll
    for (int b = 0; b < NB; b++) {
        float t = dr - (0.5f + 0.91666666666666667f * (float)b);
        basis[b] = rad_norm * expf(-betta * t * t);
    }

    int zi = __float_as_int(ri.w), zj = __float_as_int(rj.w);
    const float4* e4 = (const float4*)(g_embp + (size_t)(zj * NSP + zi) * 36);
    float ev[36];
#pragma unroll
    for (int q = 0; q < 9; q++) {
        float4 t = __ldg(e4 + q);
        ev[4 * q] = t.x; ev[4 * q + 1] = t.y; ev[4 * q + 2] = t.z; ev[4 * q + 3] = t.w;
    }

    float pref = 0.37796447300922720f * cut;
    float rad[5];
#pragma unroll
    for (int r = 0; r < 5; r++) {
        float s = 0.f;
#pragma unroll
        for (int b = 0; b < NB; b++) s += ev[r * NB + b] * basis[b];
        rad[r] = pref * s;
    }

    int slot = atomicAdd(&g_cur[ia], 1);
    if (slot >= CAP) return;   // statistically impossible (P ~ 1e-20)
    float* pb = g_prod + ((size_t)ia * CAP + slot) * 8;
    ((float4*)pb)[0] = make_float4(rad[0], rad[1], rad[2], rad[3]);
    ((float4*)pb)[1] = make_float4(rad[4], dn0, dn1, dn2);
}

// ---------------------------------------------------------------------------
// fused p2+feat: 192 threads / 32 atoms per block.
//   phase A (160 thr): 5 radial channels/atom accumulate moments -> smem[32][101]
//   phase B (4 role warps): features from smem moments -> sf[32][361]
//   phase C (6 warps): coalesced fp16-split writeout to g_A1
// ---------------------------------------------------------------------------
#define M2F(r, x, y) m2[r][imap2((x), (y))]
#define M3F(r, x, y, z) m3[r][imap3((x), (y), (z))]
#define MLD 101    // 101 mod 32 = 5, gcd(5,32)=1 -> conflict-free
#define SFLD 361   // 361 mod 32 = 9, gcd(9,32)=1 -> conflict-free
#define PFSMEM ((32 * MLD + 32 * SFLD) * 4)

__global__ void __launch_bounds__(192) p2feat_kernel() {
    extern __shared__ float sm[];
    float* smM = sm;                 // [32][MLD]
    float* sf = sm + 32 * MLD;       // [32][SFLD]
    const int tid = threadIdx.x;

    // ---- phase A: moments ----
    if (tid < 160) {
        int aL = tid / 5, r = tid - aL * 5;
        int a = blockIdx.x * 32 + aL;
        if (a < NA) {
            int n = g_cur[a];
            if (n > CAP) n = CAP;
            const float* base = g_prod + (size_t)a * CAP * 8;
            float acc[20];
#pragma unroll
            for (int j = 0; j < 20; j++) acc[j] = 0.f;
            for (int s = 0; s < n; s++) {
                float rv = __ldg(base + s * 8 + r);
                float4 v = __ldg((const float4*)(base + s * 8 + 4));
                float dn0 = v.y, dn1 = v.z, dn2 = v.w;
                float q00 = dn0 * dn0, q01 = dn0 * dn1, q02 = dn0 * dn2;
                float q11 = dn1 * dn1, q12 = dn1 * dn2, q22 = dn2 * dn2;
                acc[0] += rv;
                acc[1] += rv * dn0;  acc[2] += rv * dn1;  acc[3] += rv * dn2;
                acc[4] += rv * q00;  acc[5] += rv * q01;  acc[6] += rv * q02;
                acc[7] += rv * q11;  acc[8] += rv * q12;  acc[9] += rv * q22;
                acc[10] += rv * q00 * dn0;  acc[11] += rv * q00 * dn1;  acc[12] += rv * q00 * dn2;
                acc[13] += rv * q11 * dn0;  acc[14] += rv * q01 * dn2;  acc[15] += rv * q22 * dn0;
                acc[16] += rv * q11 * dn1;  acc[17] += rv * q11 * dn2;  acc[18] += rv * q22 * dn1;
                acc[19] += rv * q22 * dn2;
            }
            float* dst = smM + aL * MLD + r * 20;
#pragma unroll
            for (int j = 0; j < 20; j++) dst[j] = acc[j];
        }
    }
    __syncthreads();

    // ---- phase B: features ----
    const int role = tid >> 5;
    const int aL = tid & 31;
    const int a = blockIdx.x * 32 + aL;
    if (role < 4 && a < NA) {
        const float* v = smM + aL * MLD;
        float* F = sf + aL * SFLD;
        if (role == 0) {
            int pos = 0;
            float m0[5];
#pragma unroll
            for (int r = 0; r < 5; r++) m0[r] = v[r * 20];
#pragma unroll
            for (int r = 0; r < 5; r++) F[pos++] = m0[r];
            float m1[5][3];
#pragma unroll
            for (int r = 0; r < 5; r++)
#pragma unroll
                for (int i = 0; i < 3; i++) m1[r][i] = v[r * 20 + 1 + i];
#pragma unroll
            for (int r = 0; r < 5; r++)
#pragma unroll
                for (int s = 0; s <= r; s++) {
                    float acc = 0.f;
#pragma unroll
                    for (int i = 0; i < 3; i++) acc += m1[r][i] * m1[s][i];
                    F[pos++] = acc;
                }
            float m2[5][6];
#pragma unroll
            for (int r = 0; r < 5; r++)
#pragma unroll
                for (int q = 0; q < 6; q++) m2[r][q] = v[r * 20 + 4 + q];
            const float w2[6] = {1.f, 2.f, 2.f, 1.f, 2.f, 1.f};
#pragma unroll
            for (int r = 0; r < 5; r++)
#pragma unroll
                for (int s = 0; s <= r; s++) {
                    float acc = 0.f;
#pragma unroll
                    for (int q = 0; q < 6; q++) acc += w2[q] * m2[r][q] * m2[s][q];
                    F[pos++] = acc;
                }
            {
                float m3[5][10];
#pragma unroll
                for (int r = 0; r < 5; r++)
#pragma unroll
                    for (int q = 0; q < 10; q++) m3[r][q] = v[r * 20 + 10 + q];
                const float w3[10] = {1.f, 3.f, 3.f, 3.f, 6.f, 3.f, 1.f, 3.f, 3.f, 1.f};
#pragma unroll
                for (int r = 0; r < 5; r++)
#pragma unroll
                    for (int s = 0; s <= r; s++) {
                        float acc = 0.f;
#pragma unroll
                        for (int q = 0; q < 10; q++) acc += w3[q] * m3[r][q] * m3[s][q];
                        F[pos++] = acc;
                    }
            }
#pragma unroll
            for (int r = 0; r < 5; r++)
#pragma unroll
                for (int s = 0; s <= r; s++)
#pragma unroll
                    for (int t = 0; t <= s; t++) {
                        float acc = 0.f;
#pragma unroll
                        for (int x = 0; x < 3; x++)
#pragma unroll
                            for (int y = 0; y < 3; y++)
#pragma unroll
                                for (int z = 0; z < 3; z++)
                                    acc += M2F(r, x, y) * M2F(s, x, z) * M2F(t, y, z);
                        F[pos++] = acc;
                    }
        } else if (role == 1) {
            int pos = 85;
            float m1[5][3], m2[5][6];
#pragma unroll
            for (int r = 0; r < 5; r++) {
#pragma unroll
                for (int i = 0; i < 3; i++) m1[r][i] = v[r * 20 + 1 + i];
#pragma unroll
                for (int q = 0; q < 6; q++) m2[r][q] = v[r * 20 + 4 + q];
            }
#pragma unroll
            for (int r = 0; r < 5; r++)
#pragma unroll
                for (int s = 0; s <= r; s++)
#pragma unroll
                    for (int t = 0; t < 5; t++) {
                        float acc = 0.f;
#pragma unroll
                        for (int x = 0; x < 3; x++)
#pragma unroll
                            for (int y = 0; y < 3; y++)
                                acc += m1[r][x] * m1[s][y] * M2F(t, x, y);
                        F[pos++] = acc;
                    }
        } else if (role == 2) {
            int pos = 160;
            float m2[5][6], m3[5][10];
#pragma unroll
            for (int r = 0; r < 5; r++) {
#pragma unroll
                for (int q = 0; q < 6; q++) m2[r][q] = v[r * 20 + 4 + q];
#pragma unroll
                for (int q = 0; q < 10; q++) m3[r][q] = v[r * 20 + 10 + q];
            }
#pragma unroll
            for (int r = 0; r < 5; r++)
#pragma unroll
                for (int s = 0; s <= r; s++) {
                    float A[3][3];
#pragma unroll
                    for (int k = 0; k < 3; k++)
#pragma unroll
                        for (int l = 0; l < 3; l++) {
                            float acc = 0.f;
#pragma unroll
                            for (int x = 0; x < 3; x++)
#pragma unroll
                                for (int y = 0; y < 3; y++)
                                    acc += M3F(r, x, y, k) * M3F(s, x, y, l);
                            A[k][l] = acc;
                        }
#pragma unroll
                    for (int t = 0; t < 5; t++) {
                        float acc = 0.f;
#pragma unroll
                        for (int k = 0; k < 3; k++)
#pragma unroll
                            for (int l = 0; l < 3; l++)
                                acc += A[k][l] * M2F(t, k, l);
                        F[pos++] = acc;
                    }
                }
        } else {
            int pos = 235;
            float m1[5][3], m2[5][6], m3[5][10];
#pragma unroll
            for (int r = 0; r < 5; r++) {
#pragma unroll
                for (int i = 0; i < 3; i++) m1[r][i] = v[r * 20 + 1 + i];
#pragma unroll
                for (int q = 0; q < 6; q++) m2[r][q] = v[r * 20 + 4 + q];
#pragma unroll
                for (int q = 0; q < 10; q++) m3[r][q] = v[r * 20 + 10 + q];
            }
#pragma unroll
            for (int r = 0; r < 5; r++)
#pragma unroll
                for (int s = 0; s < 5; s++) {
                    float B[3];
#pragma unroll
                    for (int k = 0; k < 3; k++) {
                        float acc = 0.f;
#pragma unroll
                        for (int x = 0; x < 3; x++)
#pragma unroll
                            for (int y = 0; y < 3; y++)
                                acc += M3F(r, x, y, k) * M2F(s, x, y);
                        B[k] = acc;
                    }
#pragma unroll
                    for (int t = 0; t < 5; t++)
                        F[pos++] = B[0] * m1[t][0] + B[1] * m1[t][1] + B[2] * m1[t][2];
                }
        }
    }
    __syncthreads();

    // ---- phase C: coalesced writeout (6 warps cover 32 atoms) ----
    const int wid = tid >> 5, lane = tid & 31;
    for (int al = wid; al < 32; al += 6) {
        int ga = blockIdx.x * 32 + al;
        if (ga >= NA) continue;
        char* rowb = (char*)g_A1 + (size_t)ga * (KP1 * 2);
        const float* src = sf + al * SFLD;
        for (int k = lane; k < 360; k += 32) {
            uint32_t H, L;
            hsplit(src[k] * IN_SCALE, H, L);
            *(uint32_t*)(rowb + (size_t)k * 4) = H | (L << 16);
        }
    }
}

// ---------------------------------------------------------------------------
// mma.sync fp16 GEMM, 3-stage cp.async pipeline.
// mode 1: swish -> fp16 (hi,lo) rows scaled 2^-8 (next layer A)
// mode 2: swish -> fused GEMV vs W3, REDG partials into g_outacc
// ---------------------------------------------------------------------------
#define STAGE 20480
#define BOFF  10240
#define GSMEM (3 * STAGE)

__device__ __forceinline__ void load_stage(uint32_t sb, const char* Ab, const char* Bb,
                                           int m0, int bn, int ldab, int kt, int tid) {
    uint32_t st = (uint32_t)(kt % 3) * STAGE;
    int k0B = kt * 64;
#pragma unroll
    for (int i = 0; i < 2; i++) {
        int t = tid + i * 256;
        int row = t >> 2, ch = (t & 3) * 16;
        CP16(sb + st + (uint32_t)(row * 80 + ch),
             Ab + (size_t)(m0 + row) * ldab + k0B + ch);
    }
#pragma unroll
    for (int i = 0; i < 2; i++) {
        int t = tid + i * 256;
        int row = t >> 2, ch = (t & 3) * 16;
        CP16(sb + st + BOFF + (uint32_t)(row * 80 + ch),
             Bb + (size_t)(bn * 128 + row) * ldab + k0B + ch);
    }
    CP_COMMIT();
}

__global__ void __launch_bounds__(256, 2) gemm_mma(
    const __half* __restrict__ A, const __half* __restrict__ B,
    const float* __restrict__ bias, const float* __restrict__ W3,
    char* __restrict__ Cout, int Kp, float scale, int mode) {
    extern __shared__ __align__(16) char smem[];
    uint32_t sb = smem_u32(smem);

    const int tid = threadIdx.x, wid = tid >> 5, lane = tid & 31;
    const int wm = wid & 3, wn = wid >> 2;          // warp grid 4(m) x 2(n)
    const int bn = blockIdx.x, m0 = blockIdx.y * 128;
    const int ldab = Kp * 2;
    const int nk = Kp >> 5;

    const char* Ab = (const char*)A;
    const char* Bb = (const char*)B;

    float d[2][8][4];
#pragma unroll
    for (int i = 0; i < 2; i++)
#pragma unroll
        for (int j = 0; j < 8; j++)
#pragma unroll
            for (int q = 0; q < 4; q++) d[i][j][q] = 0.f;

    load_stage(sb, Ab, Bb, m0, bn, ldab, 0, tid);
    load_stage(sb, Ab, Bb, m0, bn, ldab, 1, tid);
    load_stage(sb, Ab, Bb, m0, bn, ldab, 2, tid);

    const int lr = lane & 15, lc = lane >> 4;

    for (int kt = 0; kt < nk; kt++) {
        CP_WAIT(2);
        __syncthreads();
        uint32_t sA = sb + (uint32_t)(kt % 3) * STAGE;
        uint32_t sBt = sA + BOFF;
#pragma unroll
        for (int h = 0; h < 2; h++) {
            uint32_t a[2][4];
#pragma unroll
            for (int mi = 0; mi < 2; mi++)
                ldm_x4(a[mi][0], a[mi][1], a[mi][2], a[mi][3],
                       sA + (uint32_t)((wm * 32 + mi * 16 + lr) * 80 + lc * 16 + h * 32));
            uint32_t b[8][2];
#pragma unroll
            for (int pi = 0; pi < 4; pi++) {
                uint32_t t0, t1, t2, t3;
                ldm_x4(t0, t1, t2, t3,
                       sBt + (uint32_t)((wn * 64 + pi * 16 + lr) * 80 + lc * 16 + h * 32));
                b[2 * pi][0] = t0; b[2 * pi][1] = t2;
                b[2 * pi + 1][0] = t1; b[2 * pi + 1][1] = t3;
            }
#pragma unroll
            for (int mi = 0; mi < 2; mi++)
#pragma unroll
                for (int ni = 0; ni < 8; ni++)
                    mma16816(d[mi][ni], a[mi], b[ni]);
        }
        __syncthreads();
        if (kt + 3 < nk) load_stage(sb, Ab, Bb, m0, bn, ldab, kt + 3, tid);
        else CP_COMMIT();
    }

    // epilogue
    const int g = lane >> 2, tg = lane & 3;
    float oacc[2][2] = {{0.f, 0.f}, {0.f, 0.f}};
#pragma unroll
    for (int mi = 0; mi < 2; mi++) {
#pragma unroll
        for (int ni = 0; ni < 8; ni++) {
            int n = bn * 128 + wn * 64 + ni * 8 + 2 * tg;
            float bz0 = 0.1f * bias[n], bz1 = 0.1f * bias[n + 1];
            float w30 = 0.f, w31 = 0.f;
            if (mode == 2) { w30 = W3[n]; w31 = W3[n + 1]; }
#pragma unroll
            for (int half = 0; half < 2; half++) {
                int m = m0 + wm * 32 + mi * 16 + g + half * 8;
                float v0 = d[mi][ni][2 * half + 0] * scale + bz0;
                float v1 = d[mi][ni][2 * half + 1] * scale + bz1;
                v0 = v0 / (1.0f + __expf(-v0));
                v1 = v1 / (1.0f + __expf(-v1));
                if (mode == 1) {
                    if (m < NA) {
                        uint32_t H0, L0, H1, L1;
                        hsplit(v0 * IN_SCALE, H0, L0);
                        hsplit(v1 * IN_SCALE, H1, L1);
                        *(uint2*)(Cout + (size_t)m * (KP2 * 2) + (size_t)n * 4) =
                            make_uint2(H0 | (L0 << 16), H1 | (L1 << 16));
                    }
                } else {
                    oacc[mi][half] += v0 * w30 + v1 * w31;
                }
            }
        }
    }
    if (mode == 2) {
#pragma unroll
        for (int mi = 0; mi < 2; mi++)
#pragma unroll
            for (int half = 0; half < 2; half++) {
                float s = oacc[mi][half];
                s += __shfl_xor_sync(0xffffffffu, s, 1);
                s += __shfl_xor_sync(0xffffffffu, s, 2);
                if (tg == 0) {
                    int m = m0 + wm * 32 + mi * 16 + g + half * 8;
                    if (m < NA) redf(&g_outacc[m], s);
                }
            }
    }
}

// ---------------------------------------------------------------------------
// finalize: out = mask * (acc / sqrt(512) + 0.1*b3)
// ---------------------------------------------------------------------------
__global__ void fin_kernel(const float* __restrict__ b3, const int* __restrict__ Z,
                           float* __restrict__ out) {
    int i = blockIdx.x * blockDim.x + threadIdx.x;
    if (i >= NA) return;
    float v = g_outacc[i] * 0.04419417382415922f + 0.1f * b3[0];
    out[i] = (Z[i] > 0) ? v : 0.0f;
}

// ---------------------------------------------------------------------------
extern "C" void kernel_launch(void* const* d_in, const int* in_sizes, int n_in,
                              void* d_out, int out_size) {
    const float* R   = (const float*)d_in[0];
    const int*   Z   = (const int*)d_in[1];
    const int*   nbr = (const int*)d_in[2];
    const float* off = (const float*)d_in[4];
    const float* emb = (const float*)d_in[5];
    const float* W1  = (const float*)d_in[6];
    const float* b1  = (const float*)d_in[7];
    const float* W2  = (const float*)d_in[8];
    const float* b2  = (const float*)d_in[9];
    const float* W3  = (const float*)d_in[10];
    const float* b3  = (const float*)d_in[11];
    float* out = (float*)d_out;

    cudaFuncSetAttribute(gemm_mma, cudaFuncAttributeMaxDynamicSharedMemorySize, GSMEM);
    cudaFuncSetAttribute(p2feat_kernel, cudaFuncAttributeMaxDynamicSharedMemorySize, PFSMEM);

    __half *pA1, *pB1, *pA2, *pB2;
    cudaGetSymbolAddress((void**)&pA1, g_A1);
    cudaGetSymbolAddress((void**)&pB1, g_B1);
    cudaGetSymbolAddress((void**)&pA2, g_A2);
    cudaGetSymbolAddress((void**)&pB2, g_B2);

    prep_kernel<<<(EMBP_N + 255) / 256, 256>>>(R, Z, emb);
    p1w_kernel<<<P1_BLOCKS + W_BLOCKS, 256>>>(nbr, off, W1, W2);
    p2feat_kernel<<<(NA + 31) / 32, 192, PFSMEM>>>();

    const float s1 = 256.0f * 0.05270462766947299f;  // 2^8 / sqrt(360)
    const float s2 = 256.0f * 0.04419417382415922f;  // 2^8 / sqrt(512)

    dim3 g(4, NAP / 128);
    gemm_mma<<<g, 256, GSMEM>>>(pA1, pB1, b1, nullptr, (char*)pA2, KP1, s1, 1);
    gemm_mma<<<g, 256, GSMEM>>>(pA2, pB2, b2, W3, nullptr, KP2, s2, 2);

    fin_kernel<<<(NA + 255) / 256, 256>>>(b3, Z, out);
}

// round 9
// speedup vs baseline: 2.6835x; 1.0367x over previous
#include <cuda_runtime.h>
#include <cuda_fp16.h>
#include <math.h>
#include <stdint.h>

#define NA 20000
#define NAP 20096           // padded rows (157*128)
#define NP 800000
#define NSP 119
#define NB 7
#define RMAXV 6.0f
#define PI_F 3.14159265358979323846f
#define CAP 64              // per-atom neighbor capacity (lambda~15, P(>=64)~1e-20)

#define KP1 736             // 2*360 padded to 32-element k-tiles
#define KP2 1024            // 2*512
#define U 512
#define IN_SCALE 0.00390625f   // 2^-8 applied to GEMM A inputs

#define P1_BLOCKS 3125
#define W1_ELEMS (360 * 512)
#define W2_ELEMS (512 * 512)
#define W_BLOCKS ((W1_ELEMS + W2_ELEMS + 255) / 256)   // 1744

// ---------------------------------------------------------------------------
// device scratch (static; zero at module load)
// ---------------------------------------------------------------------------
__device__ int    g_cur[NA];
__device__ float  g_outacc[NA];
__device__ float4 g_Rz[NA];                       // packed R.xyz + Z bits
__device__ float  g_embp[NSP * NSP * 36];         // emb rows padded 35->36
__device__ float  g_prod[(size_t)NA * CAP * 8];   // per active pair: rad[5]+dn[3]
__device__ __half g_A1[(size_t)NAP * KP1];        // feats (scaled), fp16 hi/lo
__device__ __half g_B1[(size_t)U * KP1];          // W1^T fp16 (hi,hi)
__device__ __half g_A2[(size_t)NAP * KP2];        // h1 (scaled), fp16 hi/lo
__device__ __half g_B2[(size_t)U * KP2];          // W2^T fp16 (hi,hi)

// ---------------------------------------------------------------------------
// helpers
// ---------------------------------------------------------------------------
__device__ __forceinline__ uint32_t smem_u32(const void* p) {
    uint32_t a;
    asm("{ .reg .u64 t; cvta.to.shared.u64 t, %1; cvt.u32.u64 %0, t; }" : "=r"(a) : "l"(p));
    return a;
}
#define CP16(dst, src)   asm volatile("cp.async.cg.shared.global [%0], [%1], 16;" :: "r"(dst), "l"(src))
#define CP_COMMIT()      asm volatile("cp.async.commit_group;" ::: "memory")
#define CP_WAIT(n)       asm volatile("cp.async.wait_group %0;" :: "n"(n) : "memory")

__device__ __forceinline__ void ldm_x4(uint32_t& r0, uint32_t& r1, uint32_t& r2, uint32_t& r3,
                                       uint32_t addr) {
    asm volatile("ldmatrix.sync.aligned.m8n8.x4.shared.b16 {%0,%1,%2,%3}, [%4];"
                 : "=r"(r0), "=r"(r1), "=r"(r2), "=r"(r3) : "r"(addr));
}
__device__ __forceinline__ void mma16816(float* d, const uint32_t* a, const uint32_t* b) {
    asm volatile("mma.sync.aligned.m16n8k16.row.col.f32.f16.f16.f32 "
                 "{%0,%1,%2,%3}, {%4,%5,%6,%7}, {%8,%9}, {%0,%1,%2,%3};"
                 : "+f"(d[0]), "+f"(d[1]), "+f"(d[2]), "+f"(d[3])
                 : "r"(a[0]), "r"(a[1]), "r"(a[2]), "r"(a[3]), "r"(b[0]), "r"(b[1]));
}
__device__ __forceinline__ void redf(float* p, float v) {
    asm volatile("red.global.add.f32 [%0], %1;" :: "l"(p), "f"(v) : "memory");
}

// fp16 hi/lo split (input assumed pre-scaled into fp16 range)
__device__ __forceinline__ void hsplit(float v, uint32_t& h, uint32_t& l) {
    __half hb = __float2half(v);
    float r = v - __half2float(hb);
    __half lb = __float2half(r);
    h = (uint32_t)__half_as_ushort(hb);
    l = (uint32_t)__half_as_ushort(lb);
}

// symmetric index maps (compile-time folded)
__device__ __forceinline__ int imap2(int a, int b) {
    int i = a < b ? a : b, j = a < b ? b : a;
    return (i == 0) ? j : ((i == 1) ? (2 + j) : 5);
}
__device__ __forceinline__ int imap3(int a, int b, int c) {
    int i = a, j = b, k = c, t;
    if (i > j) { t = i; i = j; j = t; }
    if (j > k) { t = j; j = k; k = t; }
    if (i > j) { t = i; i = j; j = t; }
    if (i == 0) return imap2(j, k);
    if (i == 1) return (j == 1) ? (5 + k) : 8;
    return 9;
}

// ---------------------------------------------------------------------------
// prep: zero counters/outacc, pack R+Z, pad emb rows 35->36 (one kernel)
// ---------------------------------------------------------------------------
#define EMBP_N (NSP * NSP * 36)
__global__ void prep_kernel(const float* __restrict__ R, const int* __restrict__ Z,
                            const float* __restrict__ emb) {
    int i = blockIdx.x * blockDim.x + threadIdx.x;
    if (i < EMBP_N) {
        int pair = i / 36, c = i - pair * 36;
        g_embp[i] = (c < 35) ? emb[(size_t)pair * 35 + c] : 0.f;
    }
    if (i < NA) {
        g_cur[i] = 0;
        g_outacc[i] = 0.f;
        g_Rz[i] = make_float4(R[3 * i], R[3 * i + 1], R[3 * i + 2], __int_as_float(Z[i]));
    }
}

// ---------------------------------------------------------------------------
// p1 + wprep fused by block range
// ---------------------------------------------------------------------------
__global__ void p1w_kernel(const int* __restrict__ nbr, const float* __restrict__ off,
                           const float* __restrict__ W1, const float* __restrict__ W2) {
    if (blockIdx.x >= P1_BLOCKS) {
        int idx = (blockIdx.x - P1_BLOCKS) * 256 + threadIdx.x;
        if (idx < W1_ELEMS) {
            int n = idx / 360, k = idx - n * 360;
            float w = __ldg(W1 + (size_t)k * 512 + n);
            uint32_t h = (uint32_t)__half_as_ushort(__float2half(w));
            *(uint32_t*)((char*)g_B1 + (size_t)n * (KP1 * 2) + 4 * k) = h | (h << 16);
        } else {
            idx -= W1_ELEMS;
            if (idx < W2_ELEMS) {
                int n = idx >> 9, k = idx & 511;
                float w = __ldg(W2 + (size_t)k * 512 + n);
                uint32_t h = (uint32_t)__half_as_ushort(__float2half(w));
                *(uint32_t*)((char*)g_B2 + (size_t)n * (KP2 * 2) + 4 * k) = h | (h << 16);
            }
        }
        return;
    }

    int p = blockIdx.x * blockDim.x + threadIdx.x;
    if (p >= NP) return;
    int ia = nbr[p], ja = nbr[NP + p];

    float4 ri = __ldg(&g_Rz[ia]);
    float4 rj = __ldg(&g_Rz[ja]);
    float dx = rj.x - ri.x + off[p * 3 + 0];
    float dy = rj.y - ri.y + off[p * 3 + 1];
    float dz = rj.z - ri.z + off[p * 3 + 2];
    float dr = sqrtf(dx * dx + dy * dy + dz * dz);
    if (!(dr < RMAXV)) return;

    float inv = 1.0f / (dr + 1e-5f);
    float dn0 = dx * inv, dn1 = dy * inv, dn2 = dz * inv;

    const float betta = 49.0f / 36.0f;
    const float rad_norm = 0.898112f;   // (2*betta/pi)^0.75
    float cut = 0.5f * (cosf(PI_F * dr * (1.0f / RMAXV)) + 1.0f);

    float basis[NB];
#pragma unroll
    for (int b = 0; b < NB; b++) {
        float t = dr - (0.5f + 0.91666666666666667f * (float)b);
        basis[b] = rad_norm * expf(-betta * t * t);
    }

    int zi = __float_as_int(ri.w), zj = __float_as_int(rj.w);
    const float4* e4 = (const float4*)(g_embp + (size_t)(zj * NSP + zi) * 36);
    float ev[36];
#pragma unroll
    for (int q = 0; q < 9; q++) {
        float4 t = __ldg(e4 + q);
        ev[4 * q] = t.x; ev[4 * q + 1] = t.y; ev[4 * q + 2] = t.z; ev[4 * q + 3] = t.w;
    }

    float pref = 0.37796447300922720f * cut;
    float rad[5];
#pragma unroll
    for (int r = 0; r < 5; r++) {
        float s = 0.f;
#pragma unroll
        for (int b = 0; b < NB; b++) s += ev[r * NB + b] * basis[b];
        rad[r] = pref * s;
    }

    int slot = atomicAdd(&g_cur[ia], 1);
    if (slot >= CAP) return;   // statistically impossible (P ~ 1e-20)
    float* pb = g_prod + ((size_t)ia * CAP + slot) * 8;
    ((float4*)pb)[0] = make_float4(rad[0], rad[1], rad[2], rad[3]);
    ((float4*)pb)[1] = make_float4(rad[4], dn0, dn1, dn2);
}

// ---------------------------------------------------------------------------
// fused p2+feat: 192 threads / 32 atoms per block (unchanged from R8)
// ---------------------------------------------------------------------------
#define M2F(r, x, y) m2[r][imap2((x), (y))]
#define M3F(r, x, y, z) m3[r][imap3((x), (y), (z))]
#define MLD 101
#define SFLD 361
#define PFSMEM ((32 * MLD + 32 * SFLD) * 4)

__global__ void __launch_bounds__(192) p2feat_kernel() {
    extern __shared__ float sm[];
    float* smM = sm;                 // [32][MLD]
    float* sf = sm + 32 * MLD;       // [32][SFLD]
    const int tid = threadIdx.x;

    if (tid < 160) {
        int aL = tid / 5, r = tid - aL * 5;
        int a = blockIdx.x * 32 + aL;
        if (a < NA) {
            int n = g_cur[a];
            if (n > CAP) n = CAP;
            const float* base = g_prod + (size_t)a * CAP * 8;
            float acc[20];
#pragma unroll
            for (int j = 0; j < 20; j++) acc[j] = 0.f;
            for (int s = 0; s < n; s++) {
                float rv = __ldg(base + s * 8 + r);
                float4 v = __ldg((const float4*)(base + s * 8 + 4));
                float dn0 = v.y, dn1 = v.z, dn2 = v.w;
                float q00 = dn0 * dn0, q01 = dn0 * dn1, q02 = dn0 * dn2;
                float q11 = dn1 * dn1, q12 = dn1 * dn2, q22 = dn2 * dn2;
                acc[0] += rv;
                acc[1] += rv * dn0;  acc[2] += rv * dn1;  acc[3] += rv * dn2;
                acc[4] += rv * q00;  acc[5] += rv * q01;  acc[6] += rv * q02;
                acc[7] += rv * q11;  acc[8] += rv * q12;  acc[9] += rv * q22;
                acc[10] += rv * q00 * dn0;  acc[11] += rv * q00 * dn1;  acc[12] += rv * q00 * dn2;
                acc[13] += rv * q11 * dn0;  acc[14] += rv * q01 * dn2;  acc[15] += rv * q22 * dn0;
                acc[16] += rv * q11 * dn1;  acc[17] += rv * q11 * dn2;  acc[18] += rv * q22 * dn1;
                acc[19] += rv * q22 * dn2;
            }
            float* dst = smM + aL * MLD + r * 20;
#pragma unroll
            for (int j = 0; j < 20; j++) dst[j] = acc[j];
        }
    }
    __syncthreads();

    const int role = tid >> 5;
    const int aL = tid & 31;
    const int a = blockIdx.x * 32 + aL;
    if (role < 4 && a < NA) {
        const float* v = smM + aL * MLD;
        float* F = sf + aL * SFLD;
        if (role == 0) {
            int pos = 0;
            float m0[5];
#pragma unroll
            for (int r = 0; r < 5; r++) m0[r] = v[r * 20];
#pragma unroll
            for (int r = 0; r < 5; r++) F[pos++] = m0[r];
            float m1[5][3];
#pragma unroll
            for (int r = 0; r < 5; r++)
#pragma unroll
                for (int i = 0; i < 3; i++) m1[r][i] = v[r * 20 + 1 + i];
#pragma unroll
            for (int r = 0; r < 5; r++)
#pragma unroll
                for (int s = 0; s <= r; s++) {
                    float acc = 0.f;
#pragma unroll
                    for (int i = 0; i < 3; i++) acc += m1[r][i] * m1[s][i];
                    F[pos++] = acc;
                }
            float m2[5][6];
#pragma unroll
            for (int r = 0; r < 5; r++)
#pragma unroll
                for (int q = 0; q < 6; q++) m2[r][q] = v[r * 20 + 4 + q];
            const float w2[6] = {1.f, 2.f, 2.f, 1.f, 2.f, 1.f};
#pragma unroll
            for (int r = 0; r < 5; r++)
#pragma unroll
                for (int s = 0; s <= r; s++) {
                    float acc = 0.f;
#pragma unroll
                    for (int q = 0; q < 6; q++) acc += w2[q] * m2[r][q] * m2[s][q];
                    F[pos++] = acc;
                }
            {
                float m3[5][10];
#pragma unroll
                for (int r = 0; r < 5; r++)
#pragma unroll
                    for (int q = 0; q < 10; q++) m3[r][q] = v[r * 20 + 10 + q];
                const float w3[10] = {1.f, 3.f, 3.f, 3.f, 6.f, 3.f, 1.f, 3.f, 3.f, 1.f};
#pragma unroll
                for (int r = 0; r < 5; r++)
#pragma unroll
                    for (int s = 0; s <= r; s++) {
                        float acc = 0.f;
#pragma unroll
                        for (int q = 0; q < 10; q++) acc += w3[q] * m3[r][q] * m3[s][q];
                        F[pos++] = acc;
                    }
            }
#pragma unroll
            for (int r = 0; r < 5; r++)
#pragma unroll
                for (int s = 0; s <= r; s++)
#pragma unroll
                    for (int t = 0; t <= s; t++) {
                        float acc = 0.f;
#pragma unroll
                        for (int x = 0; x < 3; x++)
#pragma unroll
                            for (int y = 0; y < 3; y++)
#pragma unroll
                                for (int z = 0; z < 3; z++)
                                    acc += M2F(r, x, y) * M2F(s, x, z) * M2F(t, y, z);
                        F[pos++] = acc;
                    }
        } else if (role == 1) {
            int pos = 85;
            float m1[5][3], m2[5][6];
#pragma unroll
            for (int r = 0; r < 5; r++) {
#pragma unroll
                for (int i = 0; i < 3; i++) m1[r][i] = v[r * 20 + 1 + i];
#pragma unroll
                for (int q = 0; q < 6; q++) m2[r][q] = v[r * 20 + 4 + q];
            }
#pragma unroll
            for (int r = 0; r < 5; r++)
#pragma unroll
                for (int s = 0; s <= r; s++)
#pragma unroll
                    for (int t = 0; t < 5; t++) {
                        float acc = 0.f;
#pragma unroll
                        for (int x = 0; x < 3; x++)
#pragma unroll
                            for (int y = 0; y < 3; y++)
                                acc += m1[r][x] * m1[s][y] * M2F(t, x, y);
                        F[pos++] = acc;
                    }
        } else if (role == 2) {
            int pos = 160;
            float m2[5][6], m3[5][10];
#pragma unroll
            for (int r = 0; r < 5; r++) {
#pragma unroll
                for (int q = 0; q < 6; q++) m2[r][q] = v[r * 20 + 4 + q];
#pragma unroll
                for (int q = 0; q < 10; q++) m3[r][q] = v[r * 20 + 10 + q];
            }
#pragma unroll
            for (int r = 0; r < 5; r++)
#pragma unroll
                for (int s = 0; s <= r; s++) {
                    float A[3][3];
#pragma unroll
                    for (int k = 0; k < 3; k++)
#pragma unroll
                        for (int l = 0; l < 3; l++) {
                            float acc = 0.f;
#pragma unroll
                            for (int x = 0; x < 3; x++)
#pragma unroll
                                for (int y = 0; y < 3; y++)
                                    acc += M3F(r, x, y, k) * M3F(s, x, y, l);
                            A[k][l] = acc;
                        }
#pragma unroll
                    for (int t = 0; t < 5; t++) {
                        float acc = 0.f;
#pragma unroll
                        for (int k = 0; k < 3; k++)
#pragma unroll
                            for (int l = 0; l < 3; l++)
                                acc += A[k][l] * M2F(t, k, l);
                        F[pos++] = acc;
                    }
                }
        } else {
            int pos = 235;
            float m1[5][3], m2[5][6], m3[5][10];
#pragma unroll
            for (int r = 0; r < 5; r++) {
#pragma unroll
                for (int i = 0; i < 3; i++) m1[r][i] = v[r * 20 + 1 + i];
#pragma unroll
                for (int q = 0; q < 6; q++) m2[r][q] = v[r * 20 + 4 + q];
#pragma unroll
                for (int q = 0; q < 10; q++) m3[r][q] = v[r * 20 + 10 + q];
            }
#pragma unroll
            for (int r = 0; r < 5; r++)
#pragma unroll
                for (int s = 0; s < 5; s++) {
                    float B[3];
#pragma unroll
                    for (int k = 0; k < 3; k++) {
                        float acc = 0.f;
#pragma unroll
                        for (int x = 0; x < 3; x++)
#pragma unroll
                            for (int y = 0; y < 3; y++)
                                acc += M3F(r, x, y, k) * M2F(s, x, y);
                        B[k] = acc;
                    }
#pragma unroll
                    for (int t = 0; t < 5; t++)
                        F[pos++] = B[0] * m1[t][0] + B[1] * m1[t][1] + B[2] * m1[t][2];
                }
        }
    }
    __syncthreads();

    const int wid = tid >> 5, lane = tid & 31;
    for (int al = wid; al < 32; al += 6) {
        int ga = blockIdx.x * 32 + al;
        if (ga >= NA) continue;
        char* rowb = (char*)g_A1 + (size_t)ga * (KP1 * 2);
        const float* src = sf + al * SFLD;
        for (int k = lane; k < 360; k += 32) {
            uint32_t H, L;
            hsplit(src[k] * IN_SCALE, H, L);
            *(uint32_t*)(rowb + (size_t)k * 4) = H | (L << 16);
        }
    }
}

// ---------------------------------------------------------------------------
// mma.sync fp16 GEMM, 4-stage cp.async ring, ONE syncthreads per k-tile,
// hoisted ldmatrix addresses.
// mode 1: swish -> fp16 (hi,lo) rows scaled 2^-8; mode 2: fused W3 GEMV
// ---------------------------------------------------------------------------
#define STAGE 20480
#define BOFF  10240
#define GSMEM (4 * STAGE)

__device__ __forceinline__ void load_stage(uint32_t sb, const char* Ab, const char* Bb,
                                           int m0, int bn, int ldab, int kt, int tid) {
    uint32_t st = (uint32_t)(kt & 3) * STAGE;
    int k0B = kt * 64;
#pragma unroll
    for (int i = 0; i < 2; i++) {
        int t = tid + i * 256;
        int row = t >> 2, ch = (t & 3) * 16;
        CP16(sb + st + (uint32_t)(row * 80 + ch),
             Ab + (size_t)(m0 + row) * ldab + k0B + ch);
    }
#pragma unroll
    for (int i = 0; i < 2; i++) {
        int t = tid + i * 256;
        int row = t >> 2, ch = (t & 3) * 16;
        CP16(sb + st + BOFF + (uint32_t)(row * 80 + ch),
             Bb + (size_t)(bn * 128 + row) * ldab + k0B + ch);
    }
    CP_COMMIT();
}

__global__ void __launch_bounds__(256, 2) gemm_mma(
    const __half* __restrict__ A, const __half* __restrict__ B,
    const float* __restrict__ bias, const float* __restrict__ W3,
    char* __restrict__ Cout, int Kp, float scale, int mode) {
    extern __shared__ __align__(16) char smem[];
    uint32_t sb = smem_u32(smem);

    const int tid = threadIdx.x, wid = tid >> 5, lane = tid & 31;
    const int wm = wid & 3, wn = wid >> 2;          // warp grid 4(m) x 2(n)
    const int bn = blockIdx.x, m0 = blockIdx.y * 128;
    const int ldab = Kp * 2;
    const int nk = Kp >> 5;

    const char* Ab = (const char*)A;
    const char* Bb = (const char*)B;

    float d[2][8][4];
#pragma unroll
    for (int i = 0; i < 2; i++)
#pragma unroll
        for (int j = 0; j < 8; j++)
#pragma unroll
            for (int q = 0; q < 4; q++) d[i][j][q] = 0.f;

    load_stage(sb, Ab, Bb, m0, bn, ldab, 0, tid);
    load_stage(sb, Ab, Bb, m0, bn, ldab, 1, tid);
    load_stage(sb, Ab, Bb, m0, bn, ldab, 2, tid);

    // hoisted stage-relative fragment addresses
    const int lr = lane & 15, lc = lane >> 4;
    uint32_t aAdr[2], bAdr[4];
#pragma unroll
    for (int mi = 0; mi < 2; mi++)
        aAdr[mi] = sb + (uint32_t)((wm * 32 + mi * 16 + lr) * 80 + lc * 16);
#pragma unroll
    for (int pi = 0; pi < 4; pi++)
        bAdr[pi] = sb + BOFF + (uint32_t)((wn * 64 + pi * 16 + lr) * 80 + lc * 16);

    for (int kt = 0; kt < nk; kt++) {
        CP_WAIT(2);
        __syncthreads();
        const uint32_t so = (uint32_t)(kt & 3) * STAGE;
#pragma unroll
        for (int h = 0; h < 2; h++) {
            const uint32_t ho = so + h * 32;
            uint32_t a[2][4];
#pragma unroll
            for (int mi = 0; mi < 2; mi++)
                ldm_x4(a[mi][0], a[mi][1], a[mi][2], a[mi][3], aAdr[mi] + ho);
            uint32_t b[8][2];
#pragma unroll
            for (int pi = 0; pi < 4; pi++) {
                uint32_t t0, t1, t2, t3;
                ldm_x4(t0, t1, t2, t3, bAdr[pi] + ho);
                b[2 * pi][0] = t0; b[2 * pi][1] = t2;
                b[2 * pi + 1][0] = t1; b[2 * pi + 1][1] = t3;
            }
#pragma unroll
            for (int mi = 0; mi < 2; mi++)
#pragma unroll
                for (int ni = 0; ni < 8; ni++)
                    mma16816(d[mi][ni], a[mi], b[ni]);
        }
        // 4-stage ring: load for kt+3 targets stage (kt-1)&3, whose readers all
        // passed this iteration's barrier -> no second barrier needed.
        if (kt + 3 < nk) load_stage(sb, Ab, Bb, m0, bn, ldab, kt + 3, tid);
        else CP_COMMIT();
    }

    // epilogue
    const int g = lane >> 2, tg = lane & 3;
    float oacc[2][2] = {{0.f, 0.f}, {0.f, 0.f}};
#pragma unroll
    for (int mi = 0; mi < 2; mi++) {
#pragma unroll
        for (int ni = 0; ni < 8; ni++) {
            int n = bn * 128 + wn * 64 + ni * 8 + 2 * tg;
            float bz0 = 0.1f * bias[n], bz1 = 0.1f * bias[n + 1];
            float w30 = 0.f, w31 = 0.f;
            if (mode == 2) { w30 = W3[n]; w31 = W3[n + 1]; }
#pragma unroll
            for (int half = 0; half < 2; half++) {
                int m = m0 + wm * 32 + mi * 16 + g + half * 8;
                float v0 = d[mi][ni][2 * half + 0] * scale + bz0;
                float v1 = d[mi][ni][2 * half + 1] * scale + bz1;
                v0 = v0 / (1.0f + __expf(-v0));
                v1 = v1 / (1.0f + __expf(-v1));
                if (mode == 1) {
                    if (m < NA) {
                        uint32_t H0, L0, H1, L1;
                        hsplit(v0 * IN_SCALE, H0, L0);
                        hsplit(v1 * IN_SCALE, H1, L1);
                        *(uint2*)(Cout + (size_t)m * (KP2 * 2) + (size_t)n * 4) =
                            make_uint2(H0 | (L0 << 16), H1 | (H1 << 16) ^ (H1 << 16) ^ (L1 << 16));
                    }
                } else {
                    oacc[mi][half] += v0 * w30 + v1 * w31;
                }
            }
        }
    }
    if (mode == 2) {
#pragma unroll
        for (int mi = 0; mi < 2; mi++)
#pragma unroll
            for (int half = 0; half < 2; half++) {
                float s = oacc[mi][half];
                s += __shfl_xor_sync(0xffffffffu, s, 1);
                s += __shfl_xor_sync(0xffffffffu, s, 2);
                if (tg == 0) {
                    int m = m0 + wm * 32 + mi * 16 + g + half * 8;
                    if (m < NA) redf(&g_outacc[m], s);
                }
            }
    }
}

// ---------------------------------------------------------------------------
// finalize: out = mask * (acc / sqrt(512) + 0.1*b3)
// ---------------------------------------------------------------------------
__global__ void fin_kernel(const float* __restrict__ b3, const int* __restrict__ Z,
                           float* __restrict__ out) {
    int i = blockIdx.x * blockDim.x + threadIdx.x;
    if (i >= NA) return;
    float v = g_outacc[i] * 0.04419417382415922f + 0.1f * b3[0];
    out[i] = (Z[i] > 0) ? v : 0.0f;
}

// ---------------------------------------------------------------------------
extern "C" void kernel_launch(void* const* d_in, const int* in_sizes, int n_in,
                              void* d_out, int out_size) {
    const float* R   = (const float*)d_in[0];
    const int*   Z   = (const int*)d_in[1];
    const int*   nbr = (const int*)d_in[2];
    const float* off = (const float*)d_in[4];
    const float* emb = (const float*)d_in[5];
    const float* W1  = (const float*)d_in[6];
    const float* b1  = (const float*)d_in[7];
    const float* W2  = (const float*)d_in[8];
    const float* b2  = (const float*)d_in[9];
    const float* W3  = (const float*)d_in[10];
    const float* b3  = (const float*)d_in[11];
    float* out = (float*)d_out;

    cudaFuncSetAttribute(gemm_mma, cudaFuncAttributeMaxDynamicSharedMemorySize, GSMEM);
    cudaFuncSetAttribute(p2feat_kernel, cudaFuncAttributeMaxDynamicSharedMemorySize, PFSMEM);

    __half *pA1, *pB1, *pA2, *pB2;
    cudaGetSymbolAddress((void**)&pA1, g_A1);
    cudaGetSymbolAddress((void**)&pB1, g_B1);
    cudaGetSymbolAddress((void**)&pA2, g_A2);
    cudaGetSymbolAddress((void**)&pB2, g_B2);

    prep_kernel<<<(EMBP_N + 255) / 256, 256>>>(R, Z, emb);
    p1w_kernel<<<P1_BLOCKS + W_BLOCKS, 256>>>(nbr, off, W1, W2);
    p2feat_kernel<<<(NA + 31) / 32, 192, PFSMEM>>>();

    const float s1 = 256.0f * 0.05270462766947299f;  // 2^8 / sqrt(360)
    const float s2 = 256.0f * 0.04419417382415922f;  // 2^8 / sqrt(512)

    dim3 g(4, NAP / 128);
    gemm_mma<<<g, 256, GSMEM>>>(pA1, pB1, b1, nullptr, (char*)pA2, KP1, s1, 1);
    gemm_mma<<<g, 256, GSMEM>>>(pA2, pB2, b2, W3, nullptr, KP2, s2, 2);

    fin_kernel<<<(NA + 255) / 256, 256>>>(b3, Z, out);
}

// round 10
// speedup vs baseline: 3.8463x; 1.4333x over previous
#include <cuda_runtime.h>
#include <cuda_fp16.h>
#include <math.h>
#include <stdint.h>

#define NA 20000
#define NAP 20096           // padded rows (157*128)
#define NP 800000
#define NSP 119
#define NB 7
#define RMAXV 6.0f
#define PI_F 3.14159265358979323846f
#define CAP 64              // per-atom neighbor capacity (lambda~15, P(>=64)~1e-20)

#define KP1 384             // 360 padded to 32-element k-tiles (plain fp16)
#define KP2 512
#define U 512
#define IN_SCALE 0.00390625f   // 2^-8 applied to GEMM A inputs

#define P1_BLOCKS 3125
#define W1_ELEMS (360 * 512)
#define W2_ELEMS (512 * 512)
#define W_BLOCKS ((W1_ELEMS + W2_ELEMS + 255) / 256)   // 1744

// ---------------------------------------------------------------------------
// device scratch (static; zero at module load; pads never written)
// ---------------------------------------------------------------------------
__device__ int    g_cur[NA];
__device__ float  g_outacc[NA];
__device__ float4 g_Rz[NA];                       // packed R.xyz + Z bits
__device__ float  g_embp[NSP * NSP * 36];         // emb rows padded 35->36
__device__ float  g_prod[(size_t)NA * CAP * 8];   // per active pair: rad[5]+dn[3]
__device__ __half g_A1[(size_t)NAP * KP1];        // feats (scaled), plain fp16
__device__ __half g_B1[(size_t)U * KP1];          // W1^T fp16
__device__ __half g_A2[(size_t)NAP * KP2];        // h1 (scaled), plain fp16
__device__ __half g_B2[(size_t)U * KP2];          // W2^T fp16

// ---------------------------------------------------------------------------
// helpers
// ---------------------------------------------------------------------------
__device__ __forceinline__ uint32_t smem_u32(const void* p) {
    uint32_t a;
    asm("{ .reg .u64 t; cvta.to.shared.u64 t, %1; cvt.u32.u64 %0, t; }" : "=r"(a) : "l"(p));
    return a;
}
#define CP16(dst, src)   asm volatile("cp.async.cg.shared.global [%0], [%1], 16;" :: "r"(dst), "l"(src))
#define CP_COMMIT()      asm volatile("cp.async.commit_group;" ::: "memory")
#define CP_WAIT(n)       asm volatile("cp.async.wait_group %0;" :: "n"(n) : "memory")

__device__ __forceinline__ void ldm_x4(uint32_t& r0, uint32_t& r1, uint32_t& r2, uint32_t& r3,
                                       uint32_t addr) {
    asm volatile("ldmatrix.sync.aligned.m8n8.x4.shared.b16 {%0,%1,%2,%3}, [%4];"
                 : "=r"(r0), "=r"(r1), "=r"(r2), "=r"(r3) : "r"(addr));
}
__device__ __forceinline__ void mma16816(float* d, const uint32_t* a, const uint32_t* b) {
    asm volatile("mma.sync.aligned.m16n8k16.row.col.f32.f16.f16.f32 "
                 "{%0,%1,%2,%3}, {%4,%5,%6,%7}, {%8,%9}, {%0,%1,%2,%3};"
                 : "+f"(d[0]), "+f"(d[1]), "+f"(d[2]), "+f"(d[3])
                 : "r"(a[0]), "r"(a[1]), "r"(a[2]), "r"(a[3]), "r"(b[0]), "r"(b[1]));
}
__device__ __forceinline__ void redf(float* p, float v) {
    asm volatile("red.global.add.f32 [%0], %1;" :: "l"(p), "f"(v) : "memory");
}
__device__ __forceinline__ uint32_t h16(float v) {
    return (uint32_t)__half_as_ushort(__float2half(v));
}

// symmetric index maps (compile-time folded)
__device__ __forceinline__ int imap2(int a, int b) {
    int i = a < b ? a : b, j = a < b ? b : a;
    return (i == 0) ? j : ((i == 1) ? (2 + j) : 5);
}
__device__ __forceinline__ int imap3(int a, int b, int c) {
    int i = a, j = b, k = c, t;
    if (i > j) { t = i; i = j; j = t; }
    if (j > k) { t = j; j = k; k = t; }
    if (i > j) { t = i; i = j; j = t; }
    if (i == 0) return imap2(j, k);
    if (i == 1) return (j == 1) ? (5 + k) : 8;
    return 9;
}

// ---------------------------------------------------------------------------
// prep: zero counters/outacc, pack R+Z, pad emb rows 35->36 (one kernel)
// ---------------------------------------------------------------------------
#define EMBP_N (NSP * NSP * 36)
__global__ void prep_kernel(const float* __restrict__ R, const int* __restrict__ Z,
                            const float* __restrict__ emb) {
    int i = blockIdx.x * blockDim.x + threadIdx.x;
    if (i < EMBP_N) {
        int pair = i / 36, c = i - pair * 36;
        g_embp[i] = (c < 35) ? emb[(size_t)pair * 35 + c] : 0.f;
    }
    if (i < NA) {
        g_cur[i] = 0;
        g_outacc[i] = 0.f;
        g_Rz[i] = make_float4(R[3 * i], R[3 * i + 1], R[3 * i + 2], __int_as_float(Z[i]));
    }
}

// ---------------------------------------------------------------------------
// p1 + wprep fused by block range
// ---------------------------------------------------------------------------
__global__ void p1w_kernel(const int* __restrict__ nbr, const float* __restrict__ off,
                           const float* __restrict__ W1, const float* __restrict__ W2) {
    if (blockIdx.x >= P1_BLOCKS) {
        int idx = (blockIdx.x - P1_BLOCKS) * 256 + threadIdx.x;
        if (idx < W1_ELEMS) {
            int n = idx / 360, k = idx - n * 360;
            float w = __ldg(W1 + (size_t)k * 512 + n);
            *(__half*)((char*)g_B1 + (size_t)n * (KP1 * 2) + 2 * k) = __float2half(w);
        } else {
            idx -= W1_ELEMS;
            if (idx < W2_ELEMS) {
                int n = idx >> 9, k = idx & 511;
                float w = __ldg(W2 + (size_t)k * 512 + n);
                *(__half*)((char*)g_B2 + (size_t)n * (KP2 * 2) + 2 * k) = __float2half(w);
            }
        }
        return;
    }

    int p = blockIdx.x * blockDim.x + threadIdx.x;
    if (p >= NP) return;
    int ia = nbr[p], ja = nbr[NP + p];

    float4 ri = __ldg(&g_Rz[ia]);
    float4 rj = __ldg(&g_Rz[ja]);
    float dx = rj.x - ri.x + off[p * 3 + 0];
    float dy = rj.y - ri.y + off[p * 3 + 1];
    float dz = rj.z - ri.z + off[p * 3 + 2];
    float dr = sqrtf(dx * dx + dy * dy + dz * dz);
    if (!(dr < RMAXV)) return;

    float inv = 1.0f / (dr + 1e-5f);
    float dn0 = dx * inv, dn1 = dy * inv, dn2 = dz * inv;

    const float betta = 49.0f / 36.0f;
    const float rad_norm = 0.898112f;   // (2*betta/pi)^0.75
    float cut = 0.5f * (cosf(PI_F * dr * (1.0f / RMAXV)) + 1.0f);

    float basis[NB];
#pragma unroll
    for (int b = 0; b < NB; b++) {
        float t = dr - (0.5f + 0.91666666666666667f * (float)b);
        basis[b] = rad_norm * expf(-betta * t * t);
    }

    int zi = __float_as_int(ri.w), zj = __float_as_int(rj.w);
    const float4* e4 = (const float4*)(g_embp + (size_t)(zj * NSP + zi) * 36);
    float ev[36];
#pragma unroll
    for (int q = 0; q < 9; q++) {
        float4 t = __ldg(e4 + q);
        ev[4 * q] = t.x; ev[4 * q + 1] = t.y; ev[4 * q + 2] = t.z; ev[4 * q + 3] = t.w;
    }

    float pref = 0.37796447300922720f * cut;
    float rad[5];
#pragma unroll
    for (int r = 0; r < 5; r++) {
        float s = 0.f;
#pragma unroll
        for (int b = 0; b < NB; b++) s += ev[r * NB + b] * basis[b];
        rad[r] = pref * s;
    }

    int slot = atomicAdd(&g_cur[ia], 1);
    if (slot >= CAP) return;   // statistically impossible (P ~ 1e-20)
    float* pb = g_prod + ((size_t)ia * CAP + slot) * 8;
    ((float4*)pb)[0] = make_float4(rad[0], rad[1], rad[2], rad[3]);
    ((float4*)pb)[1] = make_float4(rad[4], dn0, dn1, dn2);
}

// ---------------------------------------------------------------------------
// fused p2+feat: 192 threads / 32 atoms per block
// ---------------------------------------------------------------------------
#define M2F(r, x, y) m2[r][imap2((x), (y))]
#define M3F(r, x, y, z) m3[r][imap3((x), (y), (z))]
#define MLD 101
#define SFLD 361
#define PFSMEM ((32 * MLD + 32 * SFLD) * 4)

__global__ void __launch_bounds__(192) p2feat_kernel() {
    extern __shared__ float sm[];
    float* smM = sm;                 // [32][MLD]
    float* sf = sm + 32 * MLD;       // [32][SFLD]
    const int tid = threadIdx.x;

    if (tid < 160) {
        int aL = tid / 5, r = tid - aL * 5;
        int a = blockIdx.x * 32 + aL;
        if (a < NA) {
            int n = g_cur[a];
            if (n > CAP) n = CAP;
            const float* base = g_prod + (size_t)a * CAP * 8;
            float acc[20];
#pragma unroll
            for (int j = 0; j < 20; j++) acc[j] = 0.f;
            for (int s = 0; s < n; s++) {
                float rv = __ldg(base + s * 8 + r);
                float4 v = __ldg((const float4*)(base + s * 8 + 4));
                float dn0 = v.y, dn1 = v.z, dn2 = v.w;
                float q00 = dn0 * dn0, q01 = dn0 * dn1, q02 = dn0 * dn2;
                float q11 = dn1 * dn1, q12 = dn1 * dn2, q22 = dn2 * dn2;
                acc[0] += rv;
                acc[1] += rv * dn0;  acc[2] += rv * dn1;  acc[3] += rv * dn2;
                acc[4] += rv * q00;  acc[5] += rv * q01;  acc[6] += rv * q02;
                acc[7] += rv * q11;  acc[8] += rv * q12;  acc[9] += rv * q22;
                acc[10] += rv * q00 * dn0;  acc[11] += rv * q00 * dn1;  acc[12] += rv * q00 * dn2;
                acc[13] += rv * q11 * dn0;  acc[14] += rv * q01 * dn2;  acc[15] += rv * q22 * dn0;
                acc[16] += rv * q11 * dn1;  acc[17] += rv * q11 * dn2;  acc[18] += rv * q22 * dn1;
                acc[19] += rv * q22 * dn2;
            }
            float* dst = smM + aL * MLD + r * 20;
#pragma unroll
            for (int j = 0; j < 20; j++) dst[j] = acc[j];
        }
    }
    __syncthreads();

    const int role = tid >> 5;
    const int aL = tid & 31;
    const int a = blockIdx.x * 32 + aL;
    if (role < 4 && a < NA) {
        const float* v = smM + aL * MLD;
        float* F = sf + aL * SFLD;
        if (role == 0) {
            int pos = 0;
            float m0[5];
#pragma unroll
            for (int r = 0; r < 5; r++) m0[r] = v[r * 20];
#pragma unroll
            for (int r = 0; r < 5; r++) F[pos++] = m0[r];
            float m1[5][3];
#pragma unroll
            for (int r = 0; r < 5; r++)
#pragma unroll
                for (int i = 0; i < 3; i++) m1[r][i] = v[r * 20 + 1 + i];
#pragma unroll
            for (int r = 0; r < 5; r++)
#pragma unroll
                for (int s = 0; s <= r; s++) {
                    float acc = 0.f;
#pragma unroll
                    for (int i = 0; i < 3; i++) acc += m1[r][i] * m1[s][i];
                    F[pos++] = acc;
                }
            float m2[5][6];
#pragma unroll
            for (int r = 0; r < 5; r++)
#pragma unroll
                for (int q = 0; q < 6; q++) m2[r][q] = v[r * 20 + 4 + q];
            const float w2[6] = {1.f, 2.f, 2.f, 1.f, 2.f, 1.f};
#pragma unroll
            for (int r = 0; r < 5; r++)
#pragma unroll
                for (int s = 0; s <= r; s++) {
                    float acc = 0.f;
#pragma unroll
                    for (int q = 0; q < 6; q++) acc += w2[q] * m2[r][q] * m2[s][q];
                    F[pos++] = acc;
                }
            {
                float m3[5][10];
#pragma unroll
                for (int r = 0; r < 5; r++)
#pragma unroll
                    for (int q = 0; q < 10; q++) m3[r][q] = v[r * 20 + 10 + q];
                const float w3[10] = {1.f, 3.f, 3.f, 3.f, 6.f, 3.f, 1.f, 3.f, 3.f, 1.f};
#pragma unroll
                for (int r = 0; r < 5; r++)
#pragma unroll
                    for (int s = 0; s <= r; s++) {
                        float acc = 0.f;
#pragma unroll
                        for (int q = 0; q < 10; q++) acc += w3[q] * m3[r][q] * m3[s][q];
                        F[pos++] = acc;
                    }
            }
#pragma unroll
            for (int r = 0; r < 5; r++)
#pragma unroll
                for (int s = 0; s <= r; s++)
#pragma unroll
                    for (int t = 0; t <= s; t++) {
                        float acc = 0.f;
#pragma unroll
                        for (int x = 0; x < 3; x++)
#pragma unroll
                            for (int y = 0; y < 3; y++)
#pragma unroll
                                for (int z = 0; z < 3; z++)
                                    acc += M2F(r, x, y) * M2F(s, x, z) * M2F(t, y, z);
                        F[pos++] = acc;
                    }
        } else if (role == 1) {
            int pos = 85;
            float m1[5][3], m2[5][6];
#pragma unroll
            for (int r = 0; r < 5; r++) {
#pragma unroll
                for (int i = 0; i < 3; i++) m1[r][i] = v[r * 20 + 1 + i];
#pragma unroll
                for (int q = 0; q < 6; q++) m2[r][q] = v[r * 20 + 4 + q];
            }
#pragma unroll
            for (int r = 0; r < 5; r++)
#pragma unroll
                for (int s = 0; s <= r; s++)
#pragma unroll
                    for (int t = 0; t < 5; t++) {
                        float acc = 0.f;
#pragma unroll
                        for (int x = 0; x < 3; x++)
#pragma unroll
                            for (int y = 0; y < 3; y++)
                                acc += m1[r][x] * m1[s][y] * M2F(t, x, y);
                        F[pos++] = acc;
                    }
        } else if (role == 2) {
            int pos = 160;
            float m2[5][6], m3[5][10];
#pragma unroll
            for (int r = 0; r < 5; r++) {
#pragma unroll
                for (int q = 0; q < 6; q++) m2[r][q] = v[r * 20 + 4 + q];
#pragma unroll
                for (int q = 0; q < 10; q++) m3[r][q] = v[r * 20 + 10 + q];
            }
#pragma unroll
            for (int r = 0; r < 5; r++)
#pragma unroll
                for (int s = 0; s <= r; s++) {
                    float A[3][3];
#pragma unroll
                    for (int k = 0; k < 3; k++)
#pragma unroll
                        for (int l = 0; l < 3; l++) {
                            float acc = 0.f;
#pragma unroll
                            for (int x = 0; x < 3; x++)
#pragma unroll
                                for (int y = 0; y < 3; y++)
                                    acc += M3F(r, x, y, k) * M3F(s, x, y, l);
                            A[k][l] = acc;
                        }
#pragma unroll
                    for (int t = 0; t < 5; t++) {
                        float acc = 0.f;
#pragma unroll
                        for (int k = 0; k < 3; k++)
#pragma unroll
                            for (int l = 0; l < 3; l++)
                                acc += A[k][l] * M2F(t, k, l);
                        F[pos++] = acc;
                    }
                }
        } else {
            int pos = 235;
            float m1[5][3], m2[5][6], m3[5][10];
#pragma unroll
            for (int r = 0; r < 5; r++) {
#pragma unroll
                for (int i = 0; i < 3; i++) m1[r][i] = v[r * 20 + 1 + i];
#pragma unroll
                for (int q = 0; q < 6; q++) m2[r][q] = v[r * 20 + 4 + q];
#pragma unroll
                for (int q = 0; q < 10; q++) m3[r][q] = v[r * 20 + 10 + q];
            }
#pragma unroll
            for (int r = 0; r < 5; r++)
#pragma unroll
                for (int s = 0; s < 5; s++) {
                    float B[3];
#pragma unroll
                    for (int k = 0; k < 3; k++) {
                        float acc = 0.f;
#pragma unroll
                        for (int x = 0; x < 3; x++)
#pragma unroll
                            for (int y = 0; y < 3; y++)
                                acc += M3F(r, x, y, k) * M2F(s, x, y);
                        B[k] = acc;
                    }
#pragma unroll
                    for (int t = 0; t < 5; t++)
                        F[pos++] = B[0] * m1[t][0] + B[1] * m1[t][1] + B[2] * m1[t][2];
                }
        }
    }
    __syncthreads();

    // coalesced writeout: plain fp16, two features per lane-word
    const int wid = tid >> 5, lane = tid & 31;
    for (int al = wid; al < 32; al += 6) {
        int ga = blockIdx.x * 32 + al;
        if (ga >= NA) continue;
        char* rowb = (char*)g_A1 + (size_t)ga * (KP1 * 2);
        const float* src = sf + al * SFLD;
        for (int k2 = lane; k2 < 180; k2 += 32) {
            uint32_t h0 = h16(src[2 * k2] * IN_SCALE);
            uint32_t h1 = h16(src[2 * k2 + 1] * IN_SCALE);
            *(uint32_t*)(rowb + (size_t)k2 * 4) = h0 | (h1 << 16);
        }
    }
}

// ---------------------------------------------------------------------------
// mma.sync fp16 GEMM, 4-stage cp.async ring, one syncthreads per k-tile.
// mode 1: swish -> fp16 rows scaled 2^-8; mode 2: fused W3 GEMV
// ---------------------------------------------------------------------------
#define STAGE 20480
#define BOFF  10240
#define GSMEM (4 * STAGE)

__device__ __forceinline__ void load_stage(uint32_t sb, const char* Ab, const char* Bb,
                                           int m0, int bn, int ldab, int kt, int tid) {
    uint32_t st = (uint32_t)(kt & 3) * STAGE;
    int k0B = kt * 64;
#pragma unroll
    for (int i = 0; i < 2; i++) {
        int t = tid + i * 256;
        int row = t >> 2, ch = (t & 3) * 16;
        CP16(sb + st + (uint32_t)(row * 80 + ch),
             Ab + (size_t)(m0 + row) * ldab + k0B + ch);
    }
#pragma unroll
    for (int i = 0; i < 2; i++) {
        int t = tid + i * 256;
        int row = t >> 2, ch = (t & 3) * 16;
        CP16(sb + st + BOFF + (uint32_t)(row * 80 + ch),
             Bb + (size_t)(bn * 128 + row) * ldab + k0B + ch);
    }
    CP_COMMIT();
}

__global__ void __launch_bounds__(256, 2) gemm_mma(
    const __half* __restrict__ A, const __half* __restrict__ B,
    const float* __restrict__ bias, const float* __restrict__ W3,
    char* __restrict__ Cout, int Kp, float scale, int mode) {
    extern __shared__ __align__(16) char smem[];
    uint32_t sb = smem_u32(smem);

    const int tid = threadIdx.x, wid = tid >> 5, lane = tid & 31;
    const int wm = wid & 3, wn = wid >> 2;          // warp grid 4(m) x 2(n)
    const int bn = blockIdx.x, m0 = blockIdx.y * 128;
    const int ldab = Kp * 2;
    const int nk = Kp >> 5;

    const char* Ab = (const char*)A;
    const char* Bb = (const char*)B;

    float d[2][8][4];
#pragma unroll
    for (int i = 0; i < 2; i++)
#pragma unroll
        for (int j = 0; j < 8; j++)
#pragma unroll
            for (int q = 0; q < 4; q++) d[i][j][q] = 0.f;

    load_stage(sb, Ab, Bb, m0, bn, ldab, 0, tid);
    load_stage(sb, Ab, Bb, m0, bn, ldab, 1, tid);
    load_stage(sb, Ab, Bb, m0, bn, ldab, 2, tid);

    const int lr = lane & 15, lc = lane >> 4;
    uint32_t aAdr[2], bAdr[4];
#pragma unroll
    for (int mi = 0; mi < 2; mi++)
        aAdr[mi] = sb + (uint32_t)((wm * 32 + mi * 16 + lr) * 80 + lc * 16);
#pragma unroll
    for (int pi = 0; pi < 4; pi++)
        bAdr[pi] = sb + BOFF + (uint32_t)((wn * 64 + pi * 16 + lr) * 80 + lc * 16);

    for (int kt = 0; kt < nk; kt++) {
        CP_WAIT(2);
        __syncthreads();
        const uint32_t so = (uint32_t)(kt & 3) * STAGE;
#pragma unroll
        for (int h = 0; h < 2; h++) {
            const uint32_t ho = so + h * 32;
            uint32_t a[2][4];
#pragma unroll
            for (int mi = 0; mi < 2; mi++)
                ldm_x4(a[mi][0], a[mi][1], a[mi][2], a[mi][3], aAdr[mi] + ho);
            uint32_t b[8][2];
#pragma unroll
            for (int pi = 0; pi < 4; pi++) {
                uint32_t t0, t1, t2, t3;
                ldm_x4(t0, t1, t2, t3, bAdr[pi] + ho);
                b[2 * pi][0] = t0; b[2 * pi][1] = t2;
                b[2 * pi + 1][0] = t1; b[2 * pi + 1][1] = t3;
            }
#pragma unroll
            for (int mi = 0; mi < 2; mi++)
#pragma unroll
                for (int ni = 0; ni < 8; ni++)
                    mma16816(d[mi][ni], a[mi], b[ni]);
        }
        if (kt + 3 < nk) load_stage(sb, Ab, Bb, m0, bn, ldab, kt + 3, tid);
        else CP_COMMIT();
    }

    // epilogue
    const int g = lane >> 2, tg = lane & 3;
    float oacc[2][2] = {{0.f, 0.f}, {0.f, 0.f}};
#pragma unroll
    for (int mi = 0; mi < 2; mi++) {
#pragma unroll
        for (int ni = 0; ni < 8; ni++) {
            int n = bn * 128 + wn * 64 + ni * 8 + 2 * tg;
            float bz0 = 0.1f * bias[n], bz1 = 0.1f * bias[n + 1];
            float w30 = 0.f, w31 = 0.f;
            if (mode == 2) { w30 = W3[n]; w31 = W3[n + 1]; }
#pragma unroll
            for (int half = 0; half < 2; half++) {
                int m = m0 + wm * 32 + mi * 16 + g + half * 8;
                float v0 = d[mi][ni][2 * half + 0] * scale + bz0;
                float v1 = d[mi][ni][2 * half + 1] * scale + bz1;
                v0 = v0 / (1.0f + __expf(-v0));
                v1 = v1 / (1.0f + __expf(-v1));
                if (mode == 1) {
                    if (m < NA) {
                        uint32_t H0 = h16(v0 * IN_SCALE);
                        uint32_t H1 = h16(v1 * IN_SCALE);
                        *(uint32_t*)(Cout + (size_t)m * (KP2 * 2) + (size_t)n * 2) =
                            H0 | (H1 << 16);
                    }
                } else {
                    oacc[mi][half] += v0 * w30 + v1 * w31;
                }
            }
        }
    }
    if (mode == 2) {
#pragma unroll
        for (int mi = 0; mi < 2; mi++)
#pragma unroll
            for (int half = 0; half < 2; half++) {
                float s = oacc[mi][half];
                s += __shfl_xor_sync(0xffffffffu, s, 1);
                s += __shfl_xor_sync(0xffffffffu, s, 2);
                if (tg == 0) {
                    int m = m0 + wm * 32 + mi * 16 + g + half * 8;
                    if (m < NA) redf(&g_outacc[m], s);
                }
            }
    }
}

// ---------------------------------------------------------------------------
// finalize: out = mask * (acc / sqrt(512) + 0.1*b3)
// ---------------------------------------------------------------------------
__global__ void fin_kernel(const float* __restrict__ b3, const int* __restrict__ Z,
                           float* __restrict__ out) {
    int i = blockIdx.x * blockDim.x + threadIdx.x;
    if (i >= NA) return;
    float v = g_outacc[i] * 0.04419417382415922f + 0.1f * b3[0];
    out[i] = (Z[i] > 0) ? v : 0.0f;
}

// ---------------------------------------------------------------------------
extern "C" void kernel_launch(void* const* d_in, const int* in_sizes, int n_in,
                              void* d_out, int out_size) {
    const float* R   = (const float*)d_in[0];
    const int*   Z   = (const int*)d_in[1];
    const int*   nbr = (const int*)d_in[2];
    const float* off = (const float*)d_in[4];
    const float* emb = (const float*)d_in[5];
    const float* W1  = (const float*)d_in[6];
    const float* b1  = (const float*)d_in[7];
    const float* W2  = (const float*)d_in[8];
    const float* b2  = (const float*)d_in[9];
    const float* W3  = (const float*)d_in[10];
    const float* b3  = (const float*)d_in[11];
    float* out = (float*)d_out;

    cudaFuncSetAttribute(gemm_mma, cudaFuncAttributeMaxDynamicSharedMemorySize, GSMEM);
    cudaFuncSetAttribute(p2feat_kernel, cudaFuncAttributeMaxDynamicSharedMemorySize, PFSMEM);

    __half *pA1, *pB1, *pA2, *pB2;
    cudaGetSymbolAddress((void**)&pA1, g_A1);
    cudaGetSymbolAddress((void**)&pB1, g_B1);
    cudaGetSymbolAddress((void**)&pA2, g_A2);
    cudaGetSymbolAddress((void**)&pB2, g_B2);

    prep_kernel<<<(EMBP_N + 255) / 256, 256>>>(R, Z, emb);
    p1w_kernel<<<P1_BLOCKS + W_BLOCKS, 256>>>(nbr, off, W1, W2);
    p2feat_kernel<<<(NA + 31) / 32, 192, PFSMEM>>>();

    const float s1 = 256.0f * 0.05270462766947299f;  // 2^8 / sqrt(360)
    const float s2 = 256.0f * 0.04419417382415922f;  // 2^8 / sqrt(512)

    dim3 g(4, NAP / 128);
    gemm_mma<<<g, 256, GSMEM>>>(pA1, pB1, b1, nullptr, (char*)pA2, KP1, s1, 1);
    gemm_mma<<<g, 256, GSMEM>>>(pA2, pB2, b2, W3, nullptr, KP2, s2, 2);

    fin_kernel<<<(NA + 255) / 256, 256>>>(b3, Z, out);
}

// round 11
// speedup vs baseline: 4.0999x; 1.0659x over previous
#include <cuda_runtime.h>
#include <cuda_fp16.h>
#include <math.h>
#include <stdint.h>

#define NA 20000
#define NAP 20096           // padded rows (157*128)
#define NP 800000
#define NSP 119
#define NB 7
#define RMAXV 6.0f
#define PI_F 3.14159265358979323846f
#define CAP 64              // per-atom neighbor capacity (lambda~15, P(>=64)~1e-20)

#define KP1 384             // 360 padded to 64-element k-tiles (plain fp16)
#define KP2 512
#define U 512
#define IN_SCALE 0.00390625f   // 2^-8 applied to GEMM A inputs

#define P1_BLOCKS 3125
#define W1_ELEMS (360 * 512)
#define W2_ELEMS (512 * 512)
#define W_BLOCKS ((W1_ELEMS + W2_ELEMS + 255) / 256)   // 1744

// ---------------------------------------------------------------------------
// device scratch (static; zero at module load; pads never written)
// ---------------------------------------------------------------------------
__device__ int    g_cur[NA];
__device__ float  g_outacc[NA];
__device__ float4 g_Rz[NA];                       // packed R.xyz + Z bits
__device__ float  g_embp[NSP * NSP * 36];         // emb rows padded 35->36
__device__ float  g_prod[(size_t)NA * CAP * 8];   // per active pair: rad[5]+dn[3]
__device__ __half g_A1[(size_t)NAP * KP1];        // feats (scaled), plain fp16
__device__ __half g_B1[(size_t)U * KP1];          // W1^T fp16
__device__ __half g_A2[(size_t)NAP * KP2];        // h1 (scaled), plain fp16
__device__ __half g_B2[(size_t)U * KP2];          // W2^T fp16

// ---------------------------------------------------------------------------
// helpers
// ---------------------------------------------------------------------------
__device__ __forceinline__ uint32_t smem_u32(const void* p) {
    uint32_t a;
    asm("{ .reg .u64 t; cvta.to.shared.u64 t, %1; cvt.u32.u64 %0, t; }" : "=r"(a) : "l"(p));
    return a;
}
#define CP16(dst, src)   asm volatile("cp.async.cg.shared.global [%0], [%1], 16;" :: "r"(dst), "l"(src))
#define CP_COMMIT()      asm volatile("cp.async.commit_group;" ::: "memory")
#define CP_WAIT(n)       asm volatile("cp.async.wait_group %0;" :: "n"(n) : "memory")

__device__ __forceinline__ void ldm_x4(uint32_t& r0, uint32_t& r1, uint32_t& r2, uint32_t& r3,
                                       uint32_t addr) {
    asm volatile("ldmatrix.sync.aligned.m8n8.x4.shared.b16 {%0,%1,%2,%3}, [%4];"
                 : "=r"(r0), "=r"(r1), "=r"(r2), "=r"(r3) : "r"(addr));
}
__device__ __forceinline__ void mma16816(float* d, const uint32_t* a, const uint32_t* b) {
    asm volatile("mma.sync.aligned.m16n8k16.row.col.f32.f16.f16.f32 "
                 "{%0,%1,%2,%3}, {%4,%5,%6,%7}, {%8,%9}, {%0,%1,%2,%3};"
                 : "+f"(d[0]), "+f"(d[1]), "+f"(d[2]), "+f"(d[3])
                 : "r"(a[0]), "r"(a[1]), "r"(a[2]), "r"(a[3]), "r"(b[0]), "r"(b[1]));
}
__device__ __forceinline__ void redf(float* p, float v) {
    asm volatile("red.global.add.f32 [%0], %1;" :: "l"(p), "f"(v) : "memory");
}
__device__ __forceinline__ uint32_t h16(float v) {
    return (uint32_t)__half_as_ushort(__float2half(v));
}

// symmetric index maps (compile-time folded)
__device__ __forceinline__ int imap2(int a, int b) {
    int i = a < b ? a : b, j = a < b ? b : a;
    return (i == 0) ? j : ((i == 1) ? (2 + j) : 5);
}
__device__ __forceinline__ int imap3(int a, int b, int c) {
    int i = a, j = b, k = c, t;
    if (i > j) { t = i; i = j; j = t; }
    if (j > k) { t = j; j = k; k = t; }
    if (i > j) { t = i; i = j; j = t; }
    if (i == 0) return imap2(j, k);
    if (i == 1) return (j == 1) ? (5 + k) : 8;
    return 9;
}

// ---------------------------------------------------------------------------
// prep: zero counters/outacc, pack R+Z, pad emb rows 35->36 (one kernel)
// ---------------------------------------------------------------------------
#define EMBP_N (NSP * NSP * 36)
__global__ void prep_kernel(const float* __restrict__ R, const int* __restrict__ Z,
                            const float* __restrict__ emb) {
    int i = blockIdx.x * blockDim.x + threadIdx.x;
    if (i < EMBP_N) {
        int pair = i / 36, c = i - pair * 36;
        g_embp[i] = (c < 35) ? emb[(size_t)pair * 35 + c] : 0.f;
    }
    if (i < NA) {
        g_cur[i] = 0;
        g_outacc[i] = 0.f;
        g_Rz[i] = make_float4(R[3 * i], R[3 * i + 1], R[3 * i + 2], __int_as_float(Z[i]));
    }
}

// ---------------------------------------------------------------------------
// p1 + wprep fused by block range
// ---------------------------------------------------------------------------
__global__ void p1w_kernel(const int* __restrict__ nbr, const float* __restrict__ off,
                           const float* __restrict__ W1, const float* __restrict__ W2) {
    if (blockIdx.x >= P1_BLOCKS) {
        int idx = (blockIdx.x - P1_BLOCKS) * 256 + threadIdx.x;
        if (idx < W1_ELEMS) {
            int n = idx / 360, k = idx - n * 360;
            float w = __ldg(W1 + (size_t)k * 512 + n);
            *(__half*)((char*)g_B1 + (size_t)n * (KP1 * 2) + 2 * k) = __float2half(w);
        } else {
            idx -= W1_ELEMS;
            if (idx < W2_ELEMS) {
                int n = idx >> 9, k = idx & 511;
                float w = __ldg(W2 + (size_t)k * 512 + n);
                *(__half*)((char*)g_B2 + (size_t)n * (KP2 * 2) + 2 * k) = __float2half(w);
            }
        }
        return;
    }

    int p = blockIdx.x * blockDim.x + threadIdx.x;
    if (p >= NP) return;
    int ia = nbr[p], ja = nbr[NP + p];

    float4 ri = __ldg(&g_Rz[ia]);
    float4 rj = __ldg(&g_Rz[ja]);
    float dx = rj.x - ri.x + off[p * 3 + 0];
    float dy = rj.y - ri.y + off[p * 3 + 1];
    float dz = rj.z - ri.z + off[p * 3 + 2];
    float dr = sqrtf(dx * dx + dy * dy + dz * dz);
    if (!(dr < RMAXV)) return;

    float inv = 1.0f / (dr + 1e-5f);
    float dn0 = dx * inv, dn1 = dy * inv, dn2 = dz * inv;

    const float betta = 49.0f / 36.0f;
    const float rad_norm = 0.898112f;   // (2*betta/pi)^0.75
    float cut = 0.5f * (cosf(PI_F * dr * (1.0f / RMAXV)) + 1.0f);

    float basis[NB];
#pragma unroll
    for (int b = 0; b < NB; b++) {
        float t = dr - (0.5f + 0.91666666666666667f * (float)b);
        basis[b] = rad_norm * expf(-betta * t * t);
    }

    int zi = __float_as_int(ri.w), zj = __float_as_int(rj.w);
    const float4* e4 = (const float4*)(g_embp + (size_t)(zj * NSP + zi) * 36);
    float ev[36];
#pragma unroll
    for (int q = 0; q < 9; q++) {
        float4 t = __ldg(e4 + q);
        ev[4 * q] = t.x; ev[4 * q + 1] = t.y; ev[4 * q + 2] = t.z; ev[4 * q + 3] = t.w;
    }

    float pref = 0.37796447300922720f * cut;
    float rad[5];
#pragma unroll
    for (int r = 0; r < 5; r++) {
        float s = 0.f;
#pragma unroll
        for (int b = 0; b < NB; b++) s += ev[r * NB + b] * basis[b];
        rad[r] = pref * s;
    }

    int slot = atomicAdd(&g_cur[ia], 1);
    if (slot >= CAP) return;   // statistically impossible (P ~ 1e-20)
    float* pb = g_prod + ((size_t)ia * CAP + slot) * 8;
    ((float4*)pb)[0] = make_float4(rad[0], rad[1], rad[2], rad[3]);
    ((float4*)pb)[1] = make_float4(rad[4], dn0, dn1, dn2);
}

// ---------------------------------------------------------------------------
// fused p2+feat: 192 threads / 32 atoms per block
// ---------------------------------------------------------------------------
#define M2F(r, x, y) m2[r][imap2((x), (y))]
#define M3F(r, x, y, z) m3[r][imap3((x), (y), (z))]
#define MLD 101
#define SFLD 361
#define PFSMEM ((32 * MLD + 32 * SFLD) * 4)

__global__ void __launch_bounds__(192) p2feat_kernel() {
    extern __shared__ float sm[];
    float* smM = sm;                 // [32][MLD]
    float* sf = sm + 32 * MLD;       // [32][SFLD]
    const int tid = threadIdx.x;

    if (tid < 160) {
        int aL = tid / 5, r = tid - aL * 5;
        int a = blockIdx.x * 32 + aL;
        if (a < NA) {
            int n = g_cur[a];
            if (n > CAP) n = CAP;
            const float* base = g_prod + (size_t)a * CAP * 8;
            float acc[20];
#pragma unroll
            for (int j = 0; j < 20; j++) acc[j] = 0.f;
            for (int s = 0; s < n; s++) {
                float rv = __ldg(base + s * 8 + r);
                float4 v = __ldg((const float4*)(base + s * 8 + 4));
                float dn0 = v.y, dn1 = v.z, dn2 = v.w;
                float q00 = dn0 * dn0, q01 = dn0 * dn1, q02 = dn0 * dn2;
                float q11 = dn1 * dn1, q12 = dn1 * dn2, q22 = dn2 * dn2;
                acc[0] += rv;
                acc[1] += rv * dn0;  acc[2] += rv * dn1;  acc[3] += rv * dn2;
                acc[4] += rv * q00;  acc[5] += rv * q01;  acc[6] += rv * q02;
                acc[7] += rv * q11;  acc[8] += rv * q12;  acc[9] += rv * q22;
                acc[10] += rv * q00 * dn0;  acc[11] += rv * q00 * dn1;  acc[12] += rv * q00 * dn2;
                acc[13] += rv * q11 * dn0;  acc[14] += rv * q01 * dn2;  acc[15] += rv * q22 * dn0;
                acc[16] += rv * q11 * dn1;  acc[17] += rv * q11 * dn2;  acc[18] += rv * q22 * dn1;
                acc[19] += rv * q22 * dn2;
            }
            float* dst = smM + aL * MLD + r * 20;
#pragma unroll
            for (int j = 0; j < 20; j++) dst[j] = acc[j];
        }
    }
    __syncthreads();

    const int role = tid >> 5;
    const int aL = tid & 31;
    const int a = blockIdx.x * 32 + aL;
    if (role < 4 && a < NA) {
        const float* v = smM + aL * MLD;
        float* F = sf + aL * SFLD;
        if (role == 0) {
            int pos = 0;
            float m0[5];
#pragma unroll
            for (int r = 0; r < 5; r++) m0[r] = v[r * 20];
#pragma unroll
            for (int r = 0; r < 5; r++) F[pos++] = m0[r];
            float m1[5][3];
#pragma unroll
            for (int r = 0; r < 5; r++)
#pragma unroll
                for (int i = 0; i < 3; i++) m1[r][i] = v[r * 20 + 1 + i];
#pragma unroll
            for (int r = 0; r < 5; r++)
#pragma unroll
                for (int s = 0; s <= r; s++) {
                    float acc = 0.f;
#pragma unroll
                    for (int i = 0; i < 3; i++) acc += m1[r][i] * m1[s][i];
                    F[pos++] = acc;
                }
            float m2[5][6];
#pragma unroll
            for (int r = 0; r < 5; r++)
#pragma unroll
                for (int q = 0; q < 6; q++) m2[r][q] = v[r * 20 + 4 + q];
            const float w2[6] = {1.f, 2.f, 2.f, 1.f, 2.f, 1.f};
#pragma unroll
            for (int r = 0; r < 5; r++)
#pragma unroll
                for (int s = 0; s <= r; s++) {
                    float acc = 0.f;
#pragma unroll
                    for (int q = 0; q < 6; q++) acc += w2[q] * m2[r][q] * m2[s][q];
                    F[pos++] = acc;
                }
            {
                float m3[5][10];
#pragma unroll
                for (int r = 0; r < 5; r++)
#pragma unroll
                    for (int q = 0; q < 10; q++) m3[r][q] = v[r * 20 + 10 + q];
                const float w3[10] = {1.f, 3.f, 3.f, 3.f, 6.f, 3.f, 1.f, 3.f, 3.f, 1.f};
#pragma unroll
                for (int r = 0; r < 5; r++)
#pragma unroll
                    for (int s = 0; s <= r; s++) {
                        float acc = 0.f;
#pragma unroll
                        for (int q = 0; q < 10; q++) acc += w3[q] * m3[r][q] * m3[s][q];
                        F[pos++] = acc;
                    }
            }
#pragma unroll
            for (int r = 0; r < 5; r++)
#pragma unroll
                for (int s = 0; s <= r; s++)
#pragma unroll
                    for (int t = 0; t <= s; t++) {
                        float acc = 0.f;
#pragma unroll
                        for (int x = 0; x < 3; x++)
#pragma unroll
                            for (int y = 0; y < 3; y++)
#pragma unroll
                                for (int z = 0; z < 3; z++)
                                    acc += M2F(r, x, y) * M2F(s, x, z) * M2F(t, y, z);
                        F[pos++] = acc;
                    }
        } else if (role == 1) {
            int pos = 85;
            float m1[5][3], m2[5][6];
#pragma unroll
            for (int r = 0; r < 5; r++) {
#pragma unroll
                for (int i = 0; i < 3; i++) m1[r][i] = v[r * 20 + 1 + i];
#pragma unroll
                for (int q = 0; q < 6; q++) m2[r][q] = v[r * 20 + 4 + q];
            }
#pragma unroll
            for (int r = 0; r < 5; r++)
#pragma unroll
                for (int s = 0; s <= r; s++)
#pragma unroll
                    for (int t = 0; t < 5; t++) {
                        float acc = 0.f;
#pragma unroll
                        for (int x = 0; x < 3; x++)
#pragma unroll
                            for (int y = 0; y < 3; y++)
                                acc += m1[r][x] * m1[s][y] * M2F(t, x, y);
                        F[pos++] = acc;
                    }
        } else if (role == 2) {
            int pos = 160;
            float m2[5][6], m3[5][10];
#pragma unroll
            for (int r = 0; r < 5; r++) {
#pragma unroll
                for (int q = 0; q < 6; q++) m2[r][q] = v[r * 20 + 4 + q];
#pragma unroll
                for (int q = 0; q < 10; q++) m3[r][q] = v[r * 20 + 10 + q];
            }
#pragma unroll
            for (int r = 0; r < 5; r++)
#pragma unroll
                for (int s = 0; s <= r; s++) {
                    float A[3][3];
#pragma unroll
                    for (int k = 0; k < 3; k++)
#pragma unroll
                        for (int l = 0; l < 3; l++) {
                            float acc = 0.f;
#pragma unroll
                            for (int x = 0; x < 3; x++)
#pragma unroll
                                for (int y = 0; y < 3; y++)
                                    acc += M3F(r, x, y, k) * M3F(s, x, y, l);
                            A[k][l] = acc;
                        }
#pragma unroll
                    for (int t = 0; t < 5; t++) {
                        float acc = 0.f;
#pragma unroll
                        for (int k = 0; k < 3; k++)
#pragma unroll
                            for (int l = 0; l < 3; l++)
                                acc += A[k][l] * M2F(t, k, l);
                        F[pos++] = acc;
                    }
                }
        } else {
            int pos = 235;
            float m1[5][3], m2[5][6], m3[5][10];
#pragma unroll
            for (int r = 0; r < 5; r++) {
#pragma unroll
                for (int i = 0; i < 3; i++) m1[r][i] = v[r * 20 + 1 + i];
#pragma unroll
                for (int q = 0; q < 6; q++) m2[r][q] = v[r * 20 + 4 + q];
#pragma unroll
                for (int q = 0; q < 10; q++) m3[r][q] = v[r * 20 + 10 + q];
            }
#pragma unroll
            for (int r = 0; r < 5; r++)
#pragma unroll
                for (int s = 0; s < 5; s++) {
                    float B[3];
#pragma unroll
                    for (int k = 0; k < 3; k++) {
                        float acc = 0.f;
#pragma unroll
                        for (int x = 0; x < 3; x++)
#pragma unroll
                            for (int y = 0; y < 3; y++)
                                acc += M3F(r, x, y, k) * M2F(s, x, y);
                        B[k] = acc;
                    }
#pragma unroll
                    for (int t = 0; t < 5; t++)
                        F[pos++] = B[0] * m1[t][0] + B[1] * m1[t][1] + B[2] * m1[t][2];
                }
        }
    }
    __syncthreads();

    // coalesced writeout: plain fp16, two features per lane-word
    const int wid = tid >> 5, lane = tid & 31;
    for (int al = wid; al < 32; al += 6) {
        int ga = blockIdx.x * 32 + al;
        if (ga >= NA) continue;
        char* rowb = (char*)g_A1 + (size_t)ga * (KP1 * 2);
        const float* src = sf + al * SFLD;
        for (int k2 = lane; k2 < 180; k2 += 32) {
            uint32_t h0 = h16(src[2 * k2] * IN_SCALE);
            uint32_t h1 = h16(src[2 * k2 + 1] * IN_SCALE);
            *(uint32_t*)(rowb + (size_t)k2 * 4) = h0 | (h1 << 16);
        }
    }
}

// ---------------------------------------------------------------------------
// mma.sync fp16 GEMM, k-tile 64 (128B rows, 144B stride), 3-stage ring,
// one syncthreads per k-tile.
// mode 1: swish -> fp16 rows scaled 2^-8; mode 2: fused W3 GEMV
// ---------------------------------------------------------------------------
#define ROWB 144
#define BOFF  (128 * ROWB)           // 18432
#define STAGE (2 * 128 * ROWB)       // 36864
#define GSMEM (3 * STAGE)            // 110592

__device__ __forceinline__ void load_stage(uint32_t sb, const char* Ab, const char* Bb,
                                           int m0, int bn, int ldab, int kt, int stg,
                                           int tid) {
    uint32_t st = (uint32_t)stg * STAGE;
    int k0B = kt * 128;
#pragma unroll
    for (int i = 0; i < 4; i++) {
        int t = tid + i * 256;
        int row = t >> 3, ch = (t & 7) * 16;
        CP16(sb + st + (uint32_t)(row * ROWB + ch),
             Ab + (size_t)(m0 + row) * ldab + k0B + ch);
    }
#pragma unroll
    for (int i = 0; i < 4; i++) {
        int t = tid + i * 256;
        int row = t >> 3, ch = (t & 7) * 16;
        CP16(sb + st + BOFF + (uint32_t)(row * ROWB + ch),
             Bb + (size_t)(bn * 128 + row) * ldab + k0B + ch);
    }
    CP_COMMIT();
}

__global__ void __launch_bounds__(256, 2) gemm_mma(
    const __half* __restrict__ A, const __half* __restrict__ B,
    const float* __restrict__ bias, const float* __restrict__ W3,
    char* __restrict__ Cout, int Kp, float scale, int mode) {
    extern __shared__ __align__(16) char smem[];
    uint32_t sb = smem_u32(smem);

    const int tid = threadIdx.x, wid = tid >> 5, lane = tid & 31;
    const int wm = wid & 3, wn = wid >> 2;          // warp grid 4(m) x 2(n)
    const int bn = blockIdx.x, m0 = blockIdx.y * 128;
    const int ldab = Kp * 2;
    const int nk = Kp >> 6;                         // k-tile = 64

    const char* Ab = (const char*)A;
    const char* Bb = (const char*)B;

    float d[2][8][4];
#pragma unroll
    for (int i = 0; i < 2; i++)
#pragma unroll
        for (int j = 0; j < 8; j++)
#pragma unroll
            for (int q = 0; q < 4; q++) d[i][j][q] = 0.f;

    load_stage(sb, Ab, Bb, m0, bn, ldab, 0, 0, tid);
    load_stage(sb, Ab, Bb, m0, bn, ldab, 1, 1, tid);

    const int lr = lane & 15, lc = lane >> 4;
    uint32_t aAdr[2], bAdr[4];
#pragma unroll
    for (int mi = 0; mi < 2; mi++)
        aAdr[mi] = sb + (uint32_t)((wm * 32 + mi * 16 + lr) * ROWB + lc * 16);
#pragma unroll
    for (int pi = 0; pi < 4; pi++)
        bAdr[pi] = sb + BOFF + (uint32_t)((wn * 64 + pi * 16 + lr) * ROWB + lc * 16);

    int s_cur = 0, s_ld = 2;
    for (int kt = 0; kt < nk; kt++) {
        CP_WAIT(1);
        __syncthreads();
        const uint32_t so = (uint32_t)s_cur * STAGE;
#pragma unroll
        for (int h = 0; h < 4; h++) {
            const uint32_t ho = so + h * 32;
            uint32_t a[2][4];
#pragma unroll
            for (int mi = 0; mi < 2; mi++)
                ldm_x4(a[mi][0], a[mi][1], a[mi][2], a[mi][3], aAdr[mi] + ho);
            uint32_t b[8][2];
#pragma unroll
            for (int pi = 0; pi < 4; pi++) {
                uint32_t t0, t1, t2, t3;
                ldm_x4(t0, t1, t2, t3, bAdr[pi] + ho);
                b[2 * pi][0] = t0; b[2 * pi][1] = t2;
                b[2 * pi + 1][0] = t1; b[2 * pi + 1][1] = t3;
            }
#pragma unroll
            for (int mi = 0; mi < 2; mi++)
#pragma unroll
                for (int ni = 0; ni < 8; ni++)
                    mma16816(d[mi][ni], a[mi], b[ni]);
        }
        // 3-stage ring, single barrier: load for kt+2 targets stage (kt-1)%3,
        // whose readers all passed this iteration's barrier.
        if (kt + 2 < nk) load_stage(sb, Ab, Bb, m0, bn, ldab, kt + 2, s_ld, tid);
        else CP_COMMIT();
        if (++s_cur == 3) s_cur = 0;
        if (++s_ld == 3) s_ld = 0;
    }

    // epilogue
    const int g = lane >> 2, tg = lane & 3;
    float oacc[2][2] = {{0.f, 0.f}, {0.f, 0.f}};
#pragma unroll
    for (int mi = 0; mi < 2; mi++) {
#pragma unroll
        for (int ni = 0; ni < 8; ni++) {
            int n = bn * 128 + wn * 64 + ni * 8 + 2 * tg;
            float bz0 = 0.1f * bias[n], bz1 = 0.1f * bias[n + 1];
            float w30 = 0.f, w31 = 0.f;
            if (mode == 2) { w30 = W3[n]; w31 = W3[n + 1]; }
#pragma unroll
            for (int half = 0; half < 2; half++) {
                int m = m0 + wm * 32 + mi * 16 + g + half * 8;
                float v0 = d[mi][ni][2 * half + 0] * scale + bz0;
                float v1 = d[mi][ni][2 * half + 1] * scale + bz1;
                v0 = v0 / (1.0f + __expf(-v0));
                v1 = v1 / (1.0f + __expf(-v1));
                if (mode == 1) {
                    if (m < NA) {
                        uint32_t H0 = h16(v0 * IN_SCALE);
                        uint32_t H1 = h16(v1 * IN_SCALE);
                        *(uint32_t*)(Cout + (size_t)m * (KP2 * 2) + (size_t)n * 2) =
                            H0 | (H1 << 16);
                    }
                } else {
                    oacc[mi][half] += v0 * w30 + v1 * w31;
                }
            }
        }
    }
    if (mode == 2) {
#pragma unroll
        for (int mi = 0; mi < 2; mi++)
#pragma unroll
            for (int half = 0; half < 2; half++) {
                float s = oacc[mi][half];
                s += __shfl_xor_sync(0xffffffffu, s, 1);
                s += __shfl_xor_sync(0xffffffffu, s, 2);
                if (tg == 0) {
                    int m = m0 + wm * 32 + mi * 16 + g + half * 8;
                    if (m < NA) redf(&g_outacc[m], s);
                }
            }
    }
}

// ---------------------------------------------------------------------------
// finalize: out = mask * (acc / sqrt(512) + 0.1*b3)
// ---------------------------------------------------------------------------
__global__ void fin_kernel(const float* __restrict__ b3, const int* __restrict__ Z,
                           float* __restrict__ out) {
    int i = blockIdx.x * blockDim.x + threadIdx.x;
    if (i >= NA) return;
    float v = g_outacc[i] * 0.04419417382415922f + 0.1f * b3[0];
    out[i] = (Z[i] > 0) ? v : 0.0f;
}

// ---------------------------------------------------------------------------
extern "C" void kernel_launch(void* const* d_in, const int* in_sizes, int n_in,
                              void* d_out, int out_size) {
    const float* R   = (const float*)d_in[0];
    const int*   Z   = (const int*)d_in[1];
    const int*   nbr = (const int*)d_in[2];
    const float* off = (const float*)d_in[4];
    const float* emb = (const float*)d_in[5];
    const float* W1  = (const float*)d_in[6];
    const float* b1  = (const float*)d_in[7];
    const float* W2  = (const float*)d_in[8];
    const float* b2  = (const float*)d_in[9];
    const float* W3  = (const float*)d_in[10];
    const float* b3  = (const float*)d_in[11];
    float* out = (float*)d_out;

    cudaFuncSetAttribute(gemm_mma, cudaFuncAttributeMaxDynamicSharedMemorySize, GSMEM);
    cudaFuncSetAttribute(p2feat_kernel, cudaFuncAttributeMaxDynamicSharedMemorySize, PFSMEM);

    __half *pA1, *pB1, *pA2, *pB2;
    cudaGetSymbolAddress((void**)&pA1, g_A1);
    cudaGetSymbolAddress((void**)&pB1, g_B1);
    cudaGetSymbolAddress((void**)&pA2, g_A2);
    cudaGetSymbolAddress((void**)&pB2, g_B2);

    prep_kernel<<<(EMBP_N + 255) / 256, 256>>>(R, Z, emb);
    p1w_kernel<<<P1_BLOCKS + W_BLOCKS, 256>>>(nbr, off, W1, W2);
    p2feat_kernel<<<(NA + 31) / 32, 192, PFSMEM>>>();

    const float s1 = 256.0f * 0.05270462766947299f;  // 2^8 / sqrt(360)
    const float s2 = 256.0f * 0.04419417382415922f;  // 2^8 / sqrt(512)

    dim3 g(4, NAP / 128);
    gemm_mma<<<g, 256, GSMEM>>>(pA1, pB1, b1, nullptr, (char*)pA2, KP1, s1, 1);
    gemm_mma<<<g, 256, GSMEM>>>(pA2, pB2, b2, W3, nullptr, KP2, s2, 2);

    fin_kernel<<<(NA + 255) / 256, 256>>>(b3, Z, out);
}